// round 1
// baseline (speedup 1.0000x reference)
#include <cuda_runtime.h>
#include <math.h>

// Problem dims
#define Tn 1024
#define Sn 1024
#define Bn 4
#define En 1024
#define Hn 16
#define DHn 64
#define FFn 4096
#define ROWS (Tn*Bn)      // 4096 token rows
#define BH (Bn*Hn)        // 64 attention batches

// -------- scratch (device globals; no allocation) --------
__device__ float g_xq[ROWS*En];
__device__ float g_xk[ROWS*En];
__device__ float g_xv[ROWS*En];
__device__ float g_attn[ROWS*En];
__device__ float g_tmp[ROWS*En];
__device__ float g_state1[ROWS*En];
__device__ float g_state2[ROWS*En];
__device__ float g_ffn[ROWS*FFn];
__device__ float g_scores[(long)BH*Tn*Sn];   // 256 MB SA scores

// ======================= generic strided batched SGEMM =======================
// C[m,n] = alpha * sum_k A[m*lda_m + k*lda_k] * B[n*ldb_n + k*ldb_k]  (+bias[n]) (+relu)
// Tiles: 64x64, K-step 16, 256 threads, 4x4 per-thread microtile.
__global__ __launch_bounds__(256) void sgemm_kernel(
    const float* __restrict__ A, const float* __restrict__ B,
    const float* __restrict__ bias, float* __restrict__ C,
    int M, int N, int K,
    long lda_m, long lda_k, long a_bs,
    long ldb_n, long ldb_k, long b_bs,
    long ldc_m, long c_bs,
    float alpha, int relu)
{
    __shared__ float As[16][68];
    __shared__ float Bs[16][68];
    const int bm = blockIdx.y * 64;
    const int bn = blockIdx.x * 64;
    A += (long)blockIdx.z * a_bs + (long)bm * lda_m;
    B += (long)blockIdx.z * b_bs + (long)bn * ldb_n;
    C += (long)blockIdx.z * c_bs;
    const int tid = threadIdx.x;
    const int tx = tid & 15, ty = tid >> 4;
    float acc[4][4] = {};

    for (int k0 = 0; k0 < K; k0 += 16) {
        #pragma unroll
        for (int r = 0; r < 4; r++) {
            int i = tid + r * 256;
            int m, k;
            if (lda_k == 1) { k = i & 15; m = i >> 4; }   // contiguous along k
            else            { m = i & 63; k = i >> 6; }   // contiguous along m
            As[k][m] = A[(long)m * lda_m + (long)(k0 + k) * lda_k];
            int n, kb;
            if (ldb_k == 1) { kb = i & 15; n = i >> 4; }
            else            { n = i & 63; kb = i >> 6; }
            Bs[kb][n] = B[(long)n * ldb_n + (long)(k0 + kb) * ldb_k];
        }
        __syncthreads();
        #pragma unroll
        for (int kk = 0; kk < 16; kk++) {
            float4 a4 = *(const float4*)&As[kk][ty * 4];
            float4 b4 = *(const float4*)&Bs[kk][tx * 4];
            float a[4] = {a4.x, a4.y, a4.z, a4.w};
            float b[4] = {b4.x, b4.y, b4.z, b4.w};
            #pragma unroll
            for (int i = 0; i < 4; i++)
                #pragma unroll
                for (int j = 0; j < 4; j++)
                    acc[i][j] += a[i] * b[j];
        }
        __syncthreads();
    }

    #pragma unroll
    for (int i = 0; i < 4; i++) {
        int m = bm + ty * 4 + i;
        float4 o;
        float* po = (float*)&o;
        #pragma unroll
        for (int j = 0; j < 4; j++) {
            int n = bn + tx * 4 + j;
            float v = acc[i][j] * alpha;
            if (bias) v += bias[n];
            if (relu) v = fmaxf(v, 0.f);
            po[j] = v;
        }
        *(float4*)&C[(long)m * ldc_m + bn + tx * 4] = o;
    }
}

// ======================= softmax over last dim (S=1024), optional additive mask [T,S]
__global__ __launch_bounds__(256) void softmax_kernel(float* __restrict__ scores,
                                                      const float* __restrict__ mask)
{
    const int t = blockIdx.x;
    float* p = scores + ((long)blockIdx.y * Tn + t) * (long)Sn;
    const int tid = threadIdx.x;
    float v[4];
    float lmax = -1e30f;
    #pragma unroll
    for (int j = 0; j < 4; j++) {
        int s = tid + j * 256;
        float x = p[s];
        if (mask) x += mask[(long)t * Sn + s];
        v[j] = x;
        lmax = fmaxf(lmax, x);
    }
    __shared__ float sh[8];
    #pragma unroll
    for (int o = 16; o; o >>= 1) lmax = fmaxf(lmax, __shfl_xor_sync(0xffffffffu, lmax, o));
    if ((tid & 31) == 0) sh[tid >> 5] = lmax;
    __syncthreads();
    float gmax = fmaxf(fmaxf(fmaxf(sh[0], sh[1]), fmaxf(sh[2], sh[3])),
                       fmaxf(fmaxf(sh[4], sh[5]), fmaxf(sh[6], sh[7])));
    float lsum = 0.f;
    #pragma unroll
    for (int j = 0; j < 4; j++) { v[j] = expf(v[j] - gmax); lsum += v[j]; }
    #pragma unroll
    for (int o = 16; o; o >>= 1) lsum += __shfl_xor_sync(0xffffffffu, lsum, o);
    __syncthreads();
    if ((tid & 31) == 0) sh[tid >> 5] = lsum;
    __syncthreads();
    float gsum = sh[0] + sh[1] + sh[2] + sh[3] + sh[4] + sh[5] + sh[6] + sh[7];
    float inv = 1.f / gsum;
    #pragma unroll
    for (int j = 0; j < 4; j++) p[tid + j * 256] = v[j] * inv;
}

// ======================= out = LayerNorm(x + res) * g + b, per row of E=1024
__global__ __launch_bounds__(256) void add_ln_kernel(
    const float* __restrict__ x, const float* __restrict__ res,
    const float* __restrict__ g, const float* __restrict__ b,
    float* __restrict__ out)
{
    const long row = (long)blockIdx.x * En;
    const int tid = threadIdx.x;
    float v[4]; float s = 0.f, s2 = 0.f;
    #pragma unroll
    for (int j = 0; j < 4; j++) {
        int i = tid + j * 256;
        float val = x[row + i] + res[row + i];
        v[j] = val; s += val; s2 += val * val;
    }
    __shared__ float sh1[8], sh2[8];
    #pragma unroll
    for (int o = 16; o; o >>= 1) {
        s  += __shfl_xor_sync(0xffffffffu, s, o);
        s2 += __shfl_xor_sync(0xffffffffu, s2, o);
    }
    if ((tid & 31) == 0) { sh1[tid >> 5] = s; sh2[tid >> 5] = s2; }
    __syncthreads();
    float ts = 0.f, ts2 = 0.f;
    #pragma unroll
    for (int w = 0; w < 8; w++) { ts += sh1[w]; ts2 += sh2[w]; }
    const float mu  = ts * (1.f / En);
    const float var = ts2 * (1.f / En) - mu * mu;
    const float inv = rsqrtf(var + 1e-5f);
    #pragma unroll
    for (int j = 0; j < 4; j++) {
        int i = tid + j * 256;
        out[row + i] = (v[j] - mu) * inv * g[i] + b[i];
    }
}

// ======================= host-side helpers =======================
static inline void gemm(const float* A, const float* B, const float* bias, float* C,
                        int M, int N, int K,
                        long lda_m, long lda_k, long a_bs,
                        long ldb_n, long ldb_k, long b_bs,
                        long ldc_m, long c_bs, int batch,
                        float alpha, int relu)
{
    dim3 grid(N / 64, M / 64, batch);
    sgemm_kernel<<<grid, 256>>>(A, B, bias, C, M, N, K,
                                lda_m, lda_k, a_bs, ldb_n, ldb_k, b_bs,
                                ldc_m, c_bs, alpha, relu);
}

extern "C" void kernel_launch(void* const* d_in, const int* in_sizes, int n_in,
                              void* d_out, int out_size)
{
    const float* state = (const float*)d_in[0];
    const float* enc   = (const float*)d_in[1];
    const float* mask  = (const float*)d_in[2];
    const float* sa_wq = (const float*)d_in[3];  const float* sa_bq = (const float*)d_in[4];
    const float* sa_wk = (const float*)d_in[5];  const float* sa_bk = (const float*)d_in[6];
    const float* sa_wv = (const float*)d_in[7];  const float* sa_bv = (const float*)d_in[8];
    const float* sa_wo = (const float*)d_in[9];  const float* sa_bo = (const float*)d_in[10];
    const float* ea_wq = (const float*)d_in[11]; const float* ea_bq = (const float*)d_in[12];
    const float* ea_wk = (const float*)d_in[13]; const float* ea_bk = (const float*)d_in[14];
    const float* ea_wv = (const float*)d_in[15]; const float* ea_bv = (const float*)d_in[16];
    const float* ea_wo = (const float*)d_in[17]; const float* ea_bo = (const float*)d_in[18];
    const float* fc1_w = (const float*)d_in[19]; const float* fc1_b = (const float*)d_in[20];
    const float* fc2_w = (const float*)d_in[21]; const float* fc2_b = (const float*)d_in[22];
    const float* ln1_g = (const float*)d_in[23]; const float* ln1_b = (const float*)d_in[24];
    const float* ln2_g = (const float*)d_in[25]; const float* ln2_b = (const float*)d_in[26];
    const float* ln3_g = (const float*)d_in[27]; const float* ln3_b = (const float*)d_in[28];

    float *xq, *xk, *xv, *attn, *tmp, *st1, *st2, *ffn, *scores;
    cudaGetSymbolAddress((void**)&xq,     g_xq);
    cudaGetSymbolAddress((void**)&xk,     g_xk);
    cudaGetSymbolAddress((void**)&xv,     g_xv);
    cudaGetSymbolAddress((void**)&attn,   g_attn);
    cudaGetSymbolAddress((void**)&tmp,    g_tmp);
    cudaGetSymbolAddress((void**)&st1,    g_state1);
    cudaGetSymbolAddress((void**)&st2,    g_state2);
    cudaGetSymbolAddress((void**)&ffn,    g_ffn);
    cudaGetSymbolAddress((void**)&scores, g_scores);

    float* out_state = (float*)d_out;                            // [T,B,E]
    float* out_attn  = (float*)d_out + (long)Tn * Bn * En;       // [B,H,T,S]

    const float sc = 1.0f / 8.0f;   // 1/sqrt(DH)
    const long BE = (long)Bn * En;  // 4096

    // ---------------- self-attention ----------------
    gemm(state, sa_wq, sa_bq, xq, ROWS, En, En, En,1,0, En,1,0, En,0, 1, 1.f, 0);
    gemm(state, sa_wk, sa_bk, xk, ROWS, En, En, En,1,0, En,1,0, En,0, 1, 1.f, 0);
    gemm(state, sa_wv, sa_bv, xv, ROWS, En, En, En,1,0, En,1,0, En,0, 1, 1.f, 0);
    // scores[bh,t,s] = (Q . K)/8  ; per-bh base offset = bh*64 in xq/xk
    gemm(xq, xk, nullptr, scores, Tn, Sn, DHn,
         BE,1,DHn,  BE,1,DHn,  Sn,(long)Tn*Sn, BH, sc, 0);
    softmax_kernel<<<dim3(Tn, BH), 256>>>(scores, mask);
    // attn[t,b,h,d] = W @ V
    gemm(scores, xv, nullptr, attn, Tn, DHn, Sn,
         Sn,1,(long)Tn*Sn,  1,BE,DHn,  BE,DHn, BH, 1.f, 0);
    gemm(attn, sa_wo, sa_bo, tmp, ROWS, En, En, En,1,0, En,1,0, En,0, 1, 1.f, 0);
    add_ln_kernel<<<ROWS, 256>>>(tmp, state, ln1_g, ln1_b, st1);

    // ---------------- encoder-decoder attention ----------------
    gemm(st1, ea_wq, ea_bq, xq, ROWS, En, En, En,1,0, En,1,0, En,0, 1, 1.f, 0);
    gemm(enc, ea_wk, ea_bk, xk, ROWS, En, En, En,1,0, En,1,0, En,0, 1, 1.f, 0);
    gemm(enc, ea_wv, ea_bv, xv, ROWS, En, En, En,1,0, En,1,0, En,0, 1, 1.f, 0);
    // EA scores straight into d_out attn-weight region, softmax in place
    gemm(xq, xk, nullptr, out_attn, Tn, Sn, DHn,
         BE,1,DHn,  BE,1,DHn,  Sn,(long)Tn*Sn, BH, sc, 0);
    softmax_kernel<<<dim3(Tn, BH), 256>>>(out_attn, nullptr);
    gemm(out_attn, xv, nullptr, attn, Tn, DHn, Sn,
         Sn,1,(long)Tn*Sn,  1,BE,DHn,  BE,DHn, BH, 1.f, 0);
    gemm(attn, ea_wo, ea_bo, tmp, ROWS, En, En, En,1,0, En,1,0, En,0, 1, 1.f, 0);
    add_ln_kernel<<<ROWS, 256>>>(tmp, st1, ln2_g, ln2_b, st2);

    // ---------------- FFN ----------------
    gemm(st2, fc1_w, fc1_b, ffn, ROWS, FFn, En, En,1,0, En,1,0, FFn,0, 1, 1.f, 1);
    gemm(ffn, fc2_w, fc2_b, tmp, ROWS, En, FFn, FFn,1,0, FFn,1,0, En,0, 1, 1.f, 0);
    add_ln_kernel<<<ROWS, 256>>>(tmp, st2, ln3_g, ln3_b, out_state);
}

// round 2
// speedup vs baseline: 2.4519x; 2.4519x over previous
#include <cuda_runtime.h>
#include <math.h>
#include <stdint.h>

// Problem dims
#define Tn 1024
#define Sn 1024
#define Bn 4
#define En 1024
#define Hn 16
#define DHn 64
#define FFn 4096
#define ROWS (Tn*Bn)      // 4096 token rows
#define BH (Bn*Hn)        // 64 attention batches

// -------- scratch (device globals; no allocation) --------
__device__ float g_xq[ROWS*En];
__device__ float g_xk[ROWS*En];
__device__ float g_xv[ROWS*En];
__device__ float g_attn[ROWS*En];
__device__ float g_tmp[ROWS*En];
__device__ float g_state1[ROWS*En];
__device__ float g_state2[ROWS*En];
__device__ float g_ffn[ROWS*FFn];
__device__ float g_scores[(long)BH*Tn*Sn];   // 256 MB SA scores

__device__ __forceinline__ uint32_t f2tf32(float x) {
    uint32_t r;
    asm("cvt.rna.tf32.f32 %0, %1;" : "=r"(r) : "f"(x));
    return r;
}

__device__ __forceinline__ void mma_tf32(float* c, const uint32_t* a, const uint32_t* b) {
    asm volatile(
        "mma.sync.aligned.m16n8k8.row.col.f32.tf32.tf32.f32 "
        "{%0,%1,%2,%3}, {%4,%5,%6,%7}, {%8,%9}, {%0,%1,%2,%3};"
        : "+f"(c[0]), "+f"(c[1]), "+f"(c[2]), "+f"(c[3])
        : "r"(a[0]), "r"(a[1]), "r"(a[2]), "r"(a[3]), "r"(b[0]), "r"(b[1]));
}

// ======================= tf32 tensor-core strided batched GEMM =======================
// C[m,n] = alpha * sum_k A[m,k] * B[n,k]  (+bias[n]) (+relu)
// A is k-contiguous (lda_k==1) always. B either k-contiguous (ldb_k==1) or
// n-contiguous (ldb_n==1). Tiles: 128 x BN x 32, 256 threads.
template<int BN>
__global__ __launch_bounds__(256) void tgemm(
    const float* __restrict__ A, const float* __restrict__ B,
    const float* __restrict__ bias, float* __restrict__ C,
    int K,
    long lda_m, long a_bs,
    long ldb_n, long ldb_k, long b_bs,
    long ldc_m, long c_bs,
    float alpha, int relu)
{
    constexpr int BM = 128;
    constexpr int BK = 32;
    constexpr int WM = 256 / BN;        // warps along m (2 or 4)
    constexpr int MI = BN / 32;         // m16 tiles per warp (4 or 2)
    constexpr int NB4 = (BK * BN / 4) / 256;  // B float4 loads per thread
    constexpr int NA4 = 4;                    // A float4 loads per thread

    __shared__ uint32_t As[BM][BK + 4];       // [m][k], pad 4 -> conflict-free frags
    __shared__ uint32_t Bs[BK][BN + 4];       // [k][n]

    const int tid = threadIdx.x;
    const int lane = tid & 31;
    const int wid = tid >> 5;
    const int wm = wid % WM;
    const int wn = wid / WM;
    const int m_base = wm * (BM / WM);
    const int n_base = wn * 32;
    const int g  = lane >> 2;   // group id (0..7)
    const int tg = lane & 3;    // thread in group

    const int bm = blockIdx.y * BM;
    const int bn = blockIdx.x * BN;
    A += (long)blockIdx.z * a_bs + (long)bm * lda_m;
    B += (long)blockIdx.z * b_bs + (long)bn * ldb_n;
    C += (long)blockIdx.z * c_bs;

    const bool n_contig = (ldb_k != 1);

    float4 avr[NA4];
    float4 bvr[NB4];

    // A tile map: idx -> row = idx>>3, c4 = idx&7 (BK/4 = 8 float4 per row)
    auto loadA = [&](int k0) {
        #pragma unroll
        for (int i = 0; i < NA4; i++) {
            int idx = tid + i * 256;
            int row = idx >> 3, c4 = idx & 7;
            avr[i] = *(const float4*)(A + (long)row * lda_m + k0 + c4 * 4);
        }
    };
    auto loadB = [&](int k0) {
        if (n_contig) {
            #pragma unroll
            for (int i = 0; i < NB4; i++) {
                int idx = tid + i * 256;
                int n4 = idx % (BN / 4), k = idx / (BN / 4);
                bvr[i] = *(const float4*)(B + (long)(k0 + k) * ldb_k + n4 * 4);
            }
        } else {
            #pragma unroll
            for (int i = 0; i < NB4; i++) {
                int idx = tid + i * 256;
                int k4 = idx & 7, n = idx >> 3;
                bvr[i] = *(const float4*)(B + (long)n * ldb_n + k0 + k4 * 4);
            }
        }
    };
    auto storeTiles = [&]() {
        #pragma unroll
        for (int i = 0; i < NA4; i++) {
            int idx = tid + i * 256;
            int row = idx >> 3, c4 = idx & 7;
            As[row][c4 * 4 + 0] = f2tf32(avr[i].x);
            As[row][c4 * 4 + 1] = f2tf32(avr[i].y);
            As[row][c4 * 4 + 2] = f2tf32(avr[i].z);
            As[row][c4 * 4 + 3] = f2tf32(avr[i].w);
        }
        if (n_contig) {
            #pragma unroll
            for (int i = 0; i < NB4; i++) {
                int idx = tid + i * 256;
                int n4 = idx % (BN / 4), k = idx / (BN / 4);
                Bs[k][n4 * 4 + 0] = f2tf32(bvr[i].x);
                Bs[k][n4 * 4 + 1] = f2tf32(bvr[i].y);
                Bs[k][n4 * 4 + 2] = f2tf32(bvr[i].z);
                Bs[k][n4 * 4 + 3] = f2tf32(bvr[i].w);
            }
        } else {
            #pragma unroll
            for (int i = 0; i < NB4; i++) {
                int idx = tid + i * 256;
                int k4 = idx & 7, n = idx >> 3;
                Bs[k4 * 4 + 0][n] = f2tf32(bvr[i].x);
                Bs[k4 * 4 + 1][n] = f2tf32(bvr[i].y);
                Bs[k4 * 4 + 2][n] = f2tf32(bvr[i].z);
                Bs[k4 * 4 + 3][n] = f2tf32(bvr[i].w);
            }
        }
    };

    float acc[MI][4][4];
    #pragma unroll
    for (int mi = 0; mi < MI; mi++)
        #pragma unroll
        for (int ni = 0; ni < 4; ni++)
            #pragma unroll
            for (int r = 0; r < 4; r++) acc[mi][ni][r] = 0.f;

    loadA(0);
    loadB(0);

    for (int k0 = 0; k0 < K; k0 += BK) {
        storeTiles();
        __syncthreads();
        if (k0 + BK < K) { loadA(k0 + BK); loadB(k0 + BK); }

        #pragma unroll
        for (int kk = 0; kk < BK; kk += 8) {
            uint32_t afr[MI][4];
            uint32_t bfr[4][2];
            #pragma unroll
            for (int mi = 0; mi < MI; mi++) {
                int r = m_base + mi * 16 + g;
                afr[mi][0] = As[r][kk + tg];
                afr[mi][1] = As[r + 8][kk + tg];
                afr[mi][2] = As[r][kk + tg + 4];
                afr[mi][3] = As[r + 8][kk + tg + 4];
            }
            #pragma unroll
            for (int ni = 0; ni < 4; ni++) {
                int c = n_base + ni * 8 + g;
                bfr[ni][0] = Bs[kk + tg][c];
                bfr[ni][1] = Bs[kk + tg + 4][c];
            }
            #pragma unroll
            for (int mi = 0; mi < MI; mi++)
                #pragma unroll
                for (int ni = 0; ni < 4; ni++)
                    mma_tf32(acc[mi][ni], afr[mi], bfr[ni]);
        }
        __syncthreads();
    }

    // epilogue
    #pragma unroll
    for (int mi = 0; mi < MI; mi++) {
        int row0 = bm + m_base + mi * 16 + g;
        #pragma unroll
        for (int ni = 0; ni < 4; ni++) {
            int col = bn + n_base + ni * 8 + tg * 2;
            float b0 = bias ? bias[col] : 0.f;
            float b1 = bias ? bias[col + 1] : 0.f;
            float v0 = acc[mi][ni][0] * alpha + b0;
            float v1 = acc[mi][ni][1] * alpha + b1;
            float v2 = acc[mi][ni][2] * alpha + b0;
            float v3 = acc[mi][ni][3] * alpha + b1;
            if (relu) {
                v0 = fmaxf(v0, 0.f); v1 = fmaxf(v1, 0.f);
                v2 = fmaxf(v2, 0.f); v3 = fmaxf(v3, 0.f);
            }
            *(float2*)&C[(long)row0 * ldc_m + col]       = make_float2(v0, v1);
            *(float2*)&C[(long)(row0 + 8) * ldc_m + col] = make_float2(v2, v3);
        }
    }
}

// ======================= softmax over last dim (S=1024), optional additive mask [T,S]
__global__ __launch_bounds__(256) void softmax_kernel(float* __restrict__ scores,
                                                      const float* __restrict__ mask)
{
    const int t = blockIdx.x;
    float* p = scores + ((long)blockIdx.y * Tn + t) * (long)Sn;
    const int tid = threadIdx.x;
    float v[4];
    float lmax = -1e30f;
    #pragma unroll
    for (int j = 0; j < 4; j++) {
        int s = tid + j * 256;
        float x = p[s];
        if (mask) x += mask[(long)t * Sn + s];
        v[j] = x;
        lmax = fmaxf(lmax, x);
    }
    __shared__ float sh[8];
    #pragma unroll
    for (int o = 16; o; o >>= 1) lmax = fmaxf(lmax, __shfl_xor_sync(0xffffffffu, lmax, o));
    if ((tid & 31) == 0) sh[tid >> 5] = lmax;
    __syncthreads();
    float gmax = fmaxf(fmaxf(fmaxf(sh[0], sh[1]), fmaxf(sh[2], sh[3])),
                       fmaxf(fmaxf(sh[4], sh[5]), fmaxf(sh[6], sh[7])));
    float lsum = 0.f;
    #pragma unroll
    for (int j = 0; j < 4; j++) { v[j] = expf(v[j] - gmax); lsum += v[j]; }
    #pragma unroll
    for (int o = 16; o; o >>= 1) lsum += __shfl_xor_sync(0xffffffffu, lsum, o);
    __syncthreads();
    if ((tid & 31) == 0) sh[tid >> 5] = lsum;
    __syncthreads();
    float gsum = sh[0] + sh[1] + sh[2] + sh[3] + sh[4] + sh[5] + sh[6] + sh[7];
    float inv = 1.f / gsum;
    #pragma unroll
    for (int j = 0; j < 4; j++) p[tid + j * 256] = v[j] * inv;
}

// ======================= out = LayerNorm(x + res) * g + b, per row of E=1024
__global__ __launch_bounds__(256) void add_ln_kernel(
    const float* __restrict__ x, const float* __restrict__ res,
    const float* __restrict__ g, const float* __restrict__ b,
    float* __restrict__ out)
{
    const long row = (long)blockIdx.x * En;
    const int tid = threadIdx.x;
    float v[4]; float s = 0.f, s2 = 0.f;
    #pragma unroll
    for (int j = 0; j < 4; j++) {
        int i = tid + j * 256;
        float val = x[row + i] + res[row + i];
        v[j] = val; s += val; s2 += val * val;
    }
    __shared__ float sh1[8], sh2[8];
    #pragma unroll
    for (int o = 16; o; o >>= 1) {
        s  += __shfl_xor_sync(0xffffffffu, s, o);
        s2 += __shfl_xor_sync(0xffffffffu, s2, o);
    }
    if ((tid & 31) == 0) { sh1[tid >> 5] = s; sh2[tid >> 5] = s2; }
    __syncthreads();
    float ts = 0.f, ts2 = 0.f;
    #pragma unroll
    for (int w = 0; w < 8; w++) { ts += sh1[w]; ts2 += sh2[w]; }
    const float mu  = ts * (1.f / En);
    const float var = ts2 * (1.f / En) - mu * mu;
    const float inv = rsqrtf(var + 1e-5f);
    #pragma unroll
    for (int j = 0; j < 4; j++) {
        int i = tid + j * 256;
        out[row + i] = (v[j] - mu) * inv * g[i] + b[i];
    }
}

// ======================= host-side helper =======================
static inline void gemm128(const float* A, const float* B, const float* bias, float* C,
                           int M, int N, int K,
                           long lda_m, long a_bs,
                           long ldb_n, long ldb_k, long b_bs,
                           long ldc_m, long c_bs, int batch,
                           float alpha, int relu)
{
    dim3 grid(N / 128, M / 128, batch);
    tgemm<128><<<grid, 256>>>(A, B, bias, C, K, lda_m, a_bs,
                              ldb_n, ldb_k, b_bs, ldc_m, c_bs, alpha, relu);
}
static inline void gemm64(const float* A, const float* B, const float* bias, float* C,
                          int M, int N, int K,
                          long lda_m, long a_bs,
                          long ldb_n, long ldb_k, long b_bs,
                          long ldc_m, long c_bs, int batch,
                          float alpha, int relu)
{
    dim3 grid(N / 64, M / 128, batch);
    tgemm<64><<<grid, 256>>>(A, B, bias, C, K, lda_m, a_bs,
                             ldb_n, ldb_k, b_bs, ldc_m, c_bs, alpha, relu);
}

extern "C" void kernel_launch(void* const* d_in, const int* in_sizes, int n_in,
                              void* d_out, int out_size)
{
    const float* state = (const float*)d_in[0];
    const float* enc   = (const float*)d_in[1];
    const float* mask  = (const float*)d_in[2];
    const float* sa_wq = (const float*)d_in[3];  const float* sa_bq = (const float*)d_in[4];
    const float* sa_wk = (const float*)d_in[5];  const float* sa_bk = (const float*)d_in[6];
    const float* sa_wv = (const float*)d_in[7];  const float* sa_bv = (const float*)d_in[8];
    const float* sa_wo = (const float*)d_in[9];  const float* sa_bo = (const float*)d_in[10];
    const float* ea_wq = (const float*)d_in[11]; const float* ea_bq = (const float*)d_in[12];
    const float* ea_wk = (const float*)d_in[13]; const float* ea_bk = (const float*)d_in[14];
    const float* ea_wv = (const float*)d_in[15]; const float* ea_bv = (const float*)d_in[16];
    const float* ea_wo = (const float*)d_in[17]; const float* ea_bo = (const float*)d_in[18];
    const float* fc1_w = (const float*)d_in[19]; const float* fc1_b = (const float*)d_in[20];
    const float* fc2_w = (const float*)d_in[21]; const float* fc2_b = (const float*)d_in[22];
    const float* ln1_g = (const float*)d_in[23]; const float* ln1_b = (const float*)d_in[24];
    const float* ln2_g = (const float*)d_in[25]; const float* ln2_b = (const float*)d_in[26];
    const float* ln3_g = (const float*)d_in[27]; const float* ln3_b = (const float*)d_in[28];

    float *xq, *xk, *xv, *attn, *tmp, *st1, *st2, *ffn, *scores;
    cudaGetSymbolAddress((void**)&xq,     g_xq);
    cudaGetSymbolAddress((void**)&xk,     g_xk);
    cudaGetSymbolAddress((void**)&xv,     g_xv);
    cudaGetSymbolAddress((void**)&attn,   g_attn);
    cudaGetSymbolAddress((void**)&tmp,    g_tmp);
    cudaGetSymbolAddress((void**)&st1,    g_state1);
    cudaGetSymbolAddress((void**)&st2,    g_state2);
    cudaGetSymbolAddress((void**)&ffn,    g_ffn);
    cudaGetSymbolAddress((void**)&scores, g_scores);

    float* out_state = (float*)d_out;                            // [T,B,E]
    float* out_attn  = (float*)d_out + (long)Tn * Bn * En;       // [B,H,T,S]

    const float sc = 1.0f / 8.0f;   // 1/sqrt(DH)
    const long BE = (long)Bn * En;  // 4096
    const long TS = (long)Tn * Sn;

    // ---------------- self-attention ----------------
    gemm128(state, sa_wq, sa_bq, xq, ROWS, En, En, En,0, En,1,0, En,0, 1, 1.f, 0);
    gemm128(state, sa_wk, sa_bk, xk, ROWS, En, En, En,0, En,1,0, En,0, 1, 1.f, 0);
    gemm128(state, sa_wv, sa_bv, xv, ROWS, En, En, En,0, En,1,0, En,0, 1, 1.f, 0);
    // scores[bh,t,s] = (Q . K)/8
    gemm128(xq, xk, nullptr, scores, Tn, Sn, DHn,
            BE,DHn,  BE,1,DHn,  Sn,TS, BH, sc, 0);
    softmax_kernel<<<dim3(Tn, BH), 256>>>(scores, mask);
    // attn[t,b,h,d] = W @ V  (B is n-contiguous: ldb_n=1, ldb_k=BE)
    gemm64(scores, xv, nullptr, attn, Tn, DHn, Sn,
           Sn,TS,  1,BE,DHn,  BE,DHn, BH, 1.f, 0);
    gemm128(attn, sa_wo, sa_bo, tmp, ROWS, En, En, En,0, En,1,0, En,0, 1, 1.f, 0);
    add_ln_kernel<<<ROWS, 256>>>(tmp, state, ln1_g, ln1_b, st1);

    // ---------------- encoder-decoder attention ----------------
    gemm128(st1, ea_wq, ea_bq, xq, ROWS, En, En, En,0, En,1,0, En,0, 1, 1.f, 0);
    gemm128(enc, ea_wk, ea_bk, xk, ROWS, En, En, En,0, En,1,0, En,0, 1, 1.f, 0);
    gemm128(enc, ea_wv, ea_bv, xv, ROWS, En, En, En,0, En,1,0, En,0, 1, 1.f, 0);
    gemm128(xq, xk, nullptr, out_attn, Tn, Sn, DHn,
            BE,DHn,  BE,1,DHn,  Sn,TS, BH, sc, 0);
    softmax_kernel<<<dim3(Tn, BH), 256>>>(out_attn, nullptr);
    gemm64(out_attn, xv, nullptr, attn, Tn, DHn, Sn,
           Sn,TS,  1,BE,DHn,  BE,DHn, BH, 1.f, 0);
    gemm128(attn, ea_wo, ea_bo, tmp, ROWS, En, En, En,0, En,1,0, En,0, 1, 1.f, 0);
    add_ln_kernel<<<ROWS, 256>>>(tmp, st1, ln2_g, ln2_b, st2);

    // ---------------- FFN ----------------
    gemm128(st2, fc1_w, fc1_b, ffn, ROWS, FFn, En, En,0, En,1,0, FFn,0, 1, 1.f, 1);
    gemm128(ffn, fc2_w, fc2_b, tmp, ROWS, En, FFn, FFn,0, FFn,1,0, En,0, 1, 1.f, 0);
    add_ln_kernel<<<ROWS, 256>>>(tmp, st2, ln3_g, ln3_b, out_state);
}

// round 3
// speedup vs baseline: 3.1939x; 1.3027x over previous
#include <cuda_runtime.h>
#include <math.h>
#include <stdint.h>

// Problem dims
#define Tn 1024
#define Sn 1024
#define Bn 4
#define En 1024
#define Hn 16
#define DHn 64
#define FFn 4096
#define ROWS (Tn*Bn)
#define BH (Bn*Hn)

// -------- scratch (device globals; no allocation) --------
__device__ float g_xq[ROWS*En];
__device__ float g_xk[ROWS*En];
__device__ float g_xv[ROWS*En];
__device__ float g_attn[ROWS*En];
__device__ float g_tmp[ROWS*En];
__device__ float g_state1[ROWS*En];
__device__ float g_state2[ROWS*En];
__device__ float g_ffn[ROWS*FFn];
__device__ float g_scores[(long)BH*Tn*Sn];

__device__ __forceinline__ uint32_t f2tf32(float x) {
    uint32_t r;
    asm("cvt.rna.tf32.f32 %0, %1;" : "=r"(r) : "f"(x));
    return r;
}
__device__ __forceinline__ void mma_tf32(float* c, const uint32_t* a, const uint32_t* b) {
    asm volatile(
        "mma.sync.aligned.m16n8k8.row.col.f32.tf32.tf32.f32 "
        "{%0,%1,%2,%3}, {%4,%5,%6,%7}, {%8,%9}, {%0,%1,%2,%3};"
        : "+f"(c[0]), "+f"(c[1]), "+f"(c[2]), "+f"(c[3])
        : "r"(a[0]), "r"(a[1]), "r"(a[2]), "r"(a[3]), "r"(b[0]), "r"(b[1]));
}
__device__ __forceinline__ void cp16(uint32_t dst, const void* src) {
    asm volatile("cp.async.cg.shared.global [%0], [%1], 16;" :: "r"(dst), "l"(src));
}
__device__ __forceinline__ void cp_commit() {
    asm volatile("cp.async.commit_group;" ::: "memory");
}
__device__ __forceinline__ void cp_wait0() {
    asm volatile("cp.async.wait_group 0;" ::: "memory");
}
__device__ __forceinline__ uint32_t smaddr(const void* p) {
    return (uint32_t)__cvta_generic_to_shared(p);
}

// ======================= tf32 tensor-core GEMM, cp.async double-buffered ============
// C[m,n] = alpha * sum_k A[m,k]*B[n,k] (+bias) (+relu).  A k-contiguous.
// KN=false: B k-contiguous (weights [n][k]), smem layout [n][k].
// KN=true : B n-contiguous (ldb_n==1),       smem layout [k][n].
template<int BN, bool KN>
__global__ __launch_bounds__(256, 2) void tgemm(
    const float* __restrict__ A, const float* __restrict__ B,
    const float* __restrict__ bias, float* __restrict__ C,
    int K,
    long lda_m, long a_bs,
    long ldb_n, long ldb_k, long b_bs,
    long ldc_m, long c_bs,
    float alpha, int relu)
{
    constexpr int BM = 128, BK = 32;
    constexpr int WARPS_N = BN / 32;
    constexpr int WARPS_M = 8 / WARPS_N;
    constexpr int MI = (BM / WARPS_M) / 16;
    constexpr int NI = 4;
    constexpr int A_STRIDE = BK + 4;                     // 36: 4g+tg conflict-free
    constexpr int B_STRIDE = KN ? (BN + 8) : (BK + 4);   // KN: 8tg+g conflict-free
    constexpr int B_ROWS   = KN ? BK : BN;
    constexpr int A_TILE = BM * A_STRIDE;
    constexpr int B_TILE = B_ROWS * B_STRIDE;
    constexpr int BCPT = (BK * BN / 4) / 256;            // B 16B-chunks per thread

    extern __shared__ float sm[];
    float* As = sm;                    // [2][BM][A_STRIDE]
    float* Bs = sm + 2 * A_TILE;       // [2][B_ROWS][B_STRIDE]

    const int tid  = threadIdx.x;
    const int lane = tid & 31;
    const int wid  = tid >> 5;
    const int wm = wid % WARPS_M, wn = wid / WARPS_M;
    const int m_base = wm * (BM / WARPS_M);
    const int n_base = wn * 32;
    const int g  = lane >> 2;
    const int tg = lane & 3;

    const int bm = blockIdx.y * BM;
    const int bn = blockIdx.x * BN;
    A += (long)blockIdx.z * a_bs + (long)bm * lda_m;
    B += (long)blockIdx.z * b_bs + (long)bn * ldb_n;
    C += (long)blockIdx.z * c_bs;

    // --- per-thread cp.async source pointers / smem destinations ---
    const float* aSrc[4];
    uint32_t aDst[4];
    #pragma unroll
    for (int i = 0; i < 4; i++) {
        int idx = tid + i * 256;
        int row = idx >> 3, c4 = idx & 7;           // 8 chunks per 32-float row
        aSrc[i] = A + (long)row * lda_m + c4 * 4;
        aDst[i] = smaddr(As + row * A_STRIDE + c4 * 4);
    }
    const float* bSrc[BCPT];
    uint32_t bDst[BCPT];
    #pragma unroll
    for (int i = 0; i < BCPT; i++) {
        int idx = tid + i * 256;
        if (KN) {
            int row = idx / (BN / 4), c4 = idx % (BN / 4);
            bSrc[i] = B + (long)row * ldb_k + c4 * 4;
            bDst[i] = smaddr(Bs + row * B_STRIDE + c4 * 4);
        } else {
            int row = idx >> 3, c4 = idx & 7;
            bSrc[i] = B + (long)row * ldb_n + c4 * 4;
            bDst[i] = smaddr(Bs + row * B_STRIDE + c4 * 4);
        }
    }
    const long bAdv = KN ? (long)BK * ldb_k : (long)BK;

    auto load_slab = [&](int st) {
        uint32_t ao = st * (A_TILE * 4);
        uint32_t bo = st * (B_TILE * 4);
        #pragma unroll
        for (int i = 0; i < 4; i++) { cp16(aDst[i] + ao, aSrc[i]); aSrc[i] += BK; }
        #pragma unroll
        for (int i = 0; i < BCPT; i++) { cp16(bDst[i] + bo, bSrc[i]); bSrc[i] += bAdv; }
        cp_commit();
    };

    float acc[MI][NI][4];
    #pragma unroll
    for (int mi = 0; mi < MI; mi++)
        #pragma unroll
        for (int ni = 0; ni < NI; ni++)
            #pragma unroll
            for (int r = 0; r < 4; r++) acc[mi][ni][r] = 0.f;

    const int nslab = K / BK;
    load_slab(0);

    for (int s = 0; s < nslab; s++) {
        cp_wait0();
        __syncthreads();
        if (s + 1 < nslab) load_slab((s + 1) & 1);

        const int st = s & 1;
        const float* Ab = As + st * A_TILE;
        const float* Bb = Bs + st * B_TILE;

        #pragma unroll
        for (int kk = 0; kk < BK; kk += 8) {
            uint32_t afr[MI][4], bfr[NI][2];
            #pragma unroll
            for (int mi = 0; mi < MI; mi++) {
                const float* ap = Ab + (m_base + mi * 16 + g) * A_STRIDE + kk;
                afr[mi][0] = f2tf32(ap[tg]);
                afr[mi][1] = f2tf32(ap[8 * A_STRIDE + tg]);
                afr[mi][2] = f2tf32(ap[tg + 4]);
                afr[mi][3] = f2tf32(ap[8 * A_STRIDE + tg + 4]);
            }
            #pragma unroll
            for (int ni = 0; ni < NI; ni++) {
                if (KN) {
                    const float* bp = Bb + (kk + tg) * B_STRIDE + n_base + ni * 8 + g;
                    bfr[ni][0] = f2tf32(bp[0]);
                    bfr[ni][1] = f2tf32(bp[4 * B_STRIDE]);
                } else {
                    const float* bp = Bb + (n_base + ni * 8 + g) * B_STRIDE + kk;
                    bfr[ni][0] = f2tf32(bp[tg]);
                    bfr[ni][1] = f2tf32(bp[tg + 4]);
                }
            }
            #pragma unroll
            for (int mi = 0; mi < MI; mi++)
                #pragma unroll
                for (int ni = 0; ni < NI; ni++)
                    mma_tf32(acc[mi][ni], afr[mi], bfr[ni]);
        }
        __syncthreads();
    }

    // epilogue
    #pragma unroll
    for (int mi = 0; mi < MI; mi++) {
        int row0 = bm + m_base + mi * 16 + g;
        #pragma unroll
        for (int ni = 0; ni < NI; ni++) {
            int col = bn + n_base + ni * 8 + tg * 2;
            float b0 = bias ? bias[col] : 0.f;
            float b1 = bias ? bias[col + 1] : 0.f;
            float v0 = acc[mi][ni][0] * alpha + b0;
            float v1 = acc[mi][ni][1] * alpha + b1;
            float v2 = acc[mi][ni][2] * alpha + b0;
            float v3 = acc[mi][ni][3] * alpha + b1;
            if (relu) {
                v0 = fmaxf(v0, 0.f); v1 = fmaxf(v1, 0.f);
                v2 = fmaxf(v2, 0.f); v3 = fmaxf(v3, 0.f);
            }
            *(float2*)&C[(long)row0 * ldc_m + col]       = make_float2(v0, v1);
            *(float2*)&C[(long)(row0 + 8) * ldc_m + col] = make_float2(v2, v3);
        }
    }
}

// ======================= softmax over last dim (S=1024), optional additive mask [T,S]
__global__ __launch_bounds__(256) void softmax_kernel(float* __restrict__ scores,
                                                      const float* __restrict__ mask)
{
    const int t = blockIdx.x;
    float* p = scores + ((long)blockIdx.y * Tn + t) * (long)Sn;
    const int tid = threadIdx.x;
    float v[4];
    float lmax = -1e30f;
    #pragma unroll
    for (int j = 0; j < 4; j++) {
        int s = tid + j * 256;
        float x = p[s];
        if (mask) x += mask[(long)t * Sn + s];
        v[j] = x;
        lmax = fmaxf(lmax, x);
    }
    __shared__ float sh[8];
    #pragma unroll
    for (int o = 16; o; o >>= 1) lmax = fmaxf(lmax, __shfl_xor_sync(0xffffffffu, lmax, o));
    if ((tid & 31) == 0) sh[tid >> 5] = lmax;
    __syncthreads();
    float gmax = fmaxf(fmaxf(fmaxf(sh[0], sh[1]), fmaxf(sh[2], sh[3])),
                       fmaxf(fmaxf(sh[4], sh[5]), fmaxf(sh[6], sh[7])));
    float lsum = 0.f;
    #pragma unroll
    for (int j = 0; j < 4; j++) { v[j] = expf(v[j] - gmax); lsum += v[j]; }
    #pragma unroll
    for (int o = 16; o; o >>= 1) lsum += __shfl_xor_sync(0xffffffffu, lsum, o);
    __syncthreads();
    if ((tid & 31) == 0) sh[tid >> 5] = lsum;
    __syncthreads();
    float gsum = sh[0] + sh[1] + sh[2] + sh[3] + sh[4] + sh[5] + sh[6] + sh[7];
    float inv = 1.f / gsum;
    #pragma unroll
    for (int j = 0; j < 4; j++) p[tid + j * 256] = v[j] * inv;
}

// ======================= out = LayerNorm(x + res) * g + b
__global__ __launch_bounds__(256) void add_ln_kernel(
    const float* __restrict__ x, const float* __restrict__ res,
    const float* __restrict__ g, const float* __restrict__ b,
    float* __restrict__ out)
{
    const long row = (long)blockIdx.x * En;
    const int tid = threadIdx.x;
    float v[4]; float s = 0.f, s2 = 0.f;
    #pragma unroll
    for (int j = 0; j < 4; j++) {
        int i = tid + j * 256;
        float val = x[row + i] + res[row + i];
        v[j] = val; s += val; s2 += val * val;
    }
    __shared__ float sh1[8], sh2[8];
    #pragma unroll
    for (int o = 16; o; o >>= 1) {
        s  += __shfl_xor_sync(0xffffffffu, s, o);
        s2 += __shfl_xor_sync(0xffffffffu, s2, o);
    }
    if ((tid & 31) == 0) { sh1[tid >> 5] = s; sh2[tid >> 5] = s2; }
    __syncthreads();
    float ts = 0.f, ts2 = 0.f;
    #pragma unroll
    for (int w = 0; w < 8; w++) { ts += sh1[w]; ts2 += sh2[w]; }
    const float mu  = ts * (1.f / En);
    const float var = ts2 * (1.f / En) - mu * mu;
    const float inv = rsqrtf(var + 1e-5f);
    #pragma unroll
    for (int j = 0; j < 4; j++) {
        int i = tid + j * 256;
        out[row + i] = (v[j] - mu) * inv * g[i] + b[i];
    }
}

// ======================= host-side =======================
#define SMEM128 ((2*128*36 + 2*128*36) * 4)
#define SMEM64  ((2*128*36 + 2*32*72) * 4)

static inline void gemm128(const float* A, const float* B, const float* bias, float* C,
                           int M, int N, int K,
                           long lda_m, long a_bs,
                           long ldb_n, long ldb_k, long b_bs,
                           long ldc_m, long c_bs, int batch,
                           float alpha, int relu)
{
    dim3 grid(N / 128, M / 128, batch);
    tgemm<128, false><<<grid, 256, SMEM128>>>(A, B, bias, C, K, lda_m, a_bs,
                                              ldb_n, ldb_k, b_bs, ldc_m, c_bs, alpha, relu);
}
static inline void gemm64kn(const float* A, const float* B, const float* bias, float* C,
                            int M, int N, int K,
                            long lda_m, long a_bs,
                            long ldb_n, long ldb_k, long b_bs,
                            long ldc_m, long c_bs, int batch,
                            float alpha, int relu)
{
    dim3 grid(N / 64, M / 128, batch);
    tgemm<64, true><<<grid, 256, SMEM64>>>(A, B, bias, C, K, lda_m, a_bs,
                                           ldb_n, ldb_k, b_bs, ldc_m, c_bs, alpha, relu);
}

extern "C" void kernel_launch(void* const* d_in, const int* in_sizes, int n_in,
                              void* d_out, int out_size)
{
    static bool attr_done = false;
    if (!attr_done) {
        cudaFuncSetAttribute((const void*)tgemm<128, false>,
                             cudaFuncAttributeMaxDynamicSharedMemorySize, SMEM128);
        cudaFuncSetAttribute((const void*)tgemm<64, true>,
                             cudaFuncAttributeMaxDynamicSharedMemorySize, SMEM64);
        attr_done = true;
    }

    const float* state = (const float*)d_in[0];
    const float* enc   = (const float*)d_in[1];
    const float* mask  = (const float*)d_in[2];
    const float* sa_wq = (const float*)d_in[3];  const float* sa_bq = (const float*)d_in[4];
    const float* sa_wk = (const float*)d_in[5];  const float* sa_bk = (const float*)d_in[6];
    const float* sa_wv = (const float*)d_in[7];  const float* sa_bv = (const float*)d_in[8];
    const float* sa_wo = (const float*)d_in[9];  const float* sa_bo = (const float*)d_in[10];
    const float* ea_wq = (const float*)d_in[11]; const float* ea_bq = (const float*)d_in[12];
    const float* ea_wk = (const float*)d_in[13]; const float* ea_bk = (const float*)d_in[14];
    const float* ea_wv = (const float*)d_in[15]; const float* ea_bv = (const float*)d_in[16];
    const float* ea_wo = (const float*)d_in[17]; const float* ea_bo = (const float*)d_in[18];
    const float* fc1_w = (const float*)d_in[19]; const float* fc1_b = (const float*)d_in[20];
    const float* fc2_w = (const float*)d_in[21]; const float* fc2_b = (const float*)d_in[22];
    const float* ln1_g = (const float*)d_in[23]; const float* ln1_b = (const float*)d_in[24];
    const float* ln2_g = (const float*)d_in[25]; const float* ln2_b = (const float*)d_in[26];
    const float* ln3_g = (const float*)d_in[27]; const float* ln3_b = (const float*)d_in[28];

    float *xq, *xk, *xv, *attn, *tmp, *st1, *st2, *ffn, *scores;
    cudaGetSymbolAddress((void**)&xq,     g_xq);
    cudaGetSymbolAddress((void**)&xk,     g_xk);
    cudaGetSymbolAddress((void**)&xv,     g_xv);
    cudaGetSymbolAddress((void**)&attn,   g_attn);
    cudaGetSymbolAddress((void**)&tmp,    g_tmp);
    cudaGetSymbolAddress((void**)&st1,    g_state1);
    cudaGetSymbolAddress((void**)&st2,    g_state2);
    cudaGetSymbolAddress((void**)&ffn,    g_ffn);
    cudaGetSymbolAddress((void**)&scores, g_scores);

    float* out_state = (float*)d_out;
    float* out_attn  = (float*)d_out + (long)Tn * Bn * En;

    const float sc = 1.0f / 8.0f;
    const long BE = (long)Bn * En;
    const long TS = (long)Tn * Sn;

    // ---------------- self-attention ----------------
    gemm128(state, sa_wq, sa_bq, xq, ROWS, En, En, En,0, En,1,0, En,0, 1, 1.f, 0);
    gemm128(state, sa_wk, sa_bk, xk, ROWS, En, En, En,0, En,1,0, En,0, 1, 1.f, 0);
    gemm128(state, sa_wv, sa_bv, xv, ROWS, En, En, En,0, En,1,0, En,0, 1, 1.f, 0);
    gemm128(xq, xk, nullptr, scores, Tn, Sn, DHn,
            BE,DHn,  BE,1,DHn,  Sn,TS, BH, sc, 0);
    softmax_kernel<<<dim3(Tn, BH), 256>>>(scores, mask);
    gemm64kn(scores, xv, nullptr, attn, Tn, DHn, Sn,
             Sn,TS,  1,BE,DHn,  BE,DHn, BH, 1.f, 0);
    gemm128(attn, sa_wo, sa_bo, tmp, ROWS, En, En, En,0, En,1,0, En,0, 1, 1.f, 0);
    add_ln_kernel<<<ROWS, 256>>>(tmp, state, ln1_g, ln1_b, st1);

    // ---------------- encoder-decoder attention ----------------
    gemm128(st1, ea_wq, ea_bq, xq, ROWS, En, En, En,0, En,1,0, En,0, 1, 1.f, 0);
    gemm128(enc, ea_wk, ea_bk, xk, ROWS, En, En, En,0, En,1,0, En,0, 1, 1.f, 0);
    gemm128(enc, ea_wv, ea_bv, xv, ROWS, En, En, En,0, En,1,0, En,0, 1, 1.f, 0);
    gemm128(xq, xk, nullptr, out_attn, Tn, Sn, DHn,
            BE,DHn,  BE,1,DHn,  Sn,TS, BH, sc, 0);
    softmax_kernel<<<dim3(Tn, BH), 256>>>(out_attn, nullptr);
    gemm64kn(out_attn, xv, nullptr, attn, Tn, DHn, Sn,
             Sn,TS,  1,BE,DHn,  BE,DHn, BH, 1.f, 0);
    gemm128(attn, ea_wo, ea_bo, tmp, ROWS, En, En, En,0, En,1,0, En,0, 1, 1.f, 0);
    add_ln_kernel<<<ROWS, 256>>>(tmp, st1, ln2_g, ln2_b, st2);

    // ---------------- FFN ----------------
    gemm128(st2, fc1_w, fc1_b, ffn, ROWS, FFn, En, En,0, En,1,0, FFn,0, 1, 1.f, 1);
    gemm128(ffn, fc2_w, fc2_b, tmp, ROWS, En, FFn, FFn,0, FFn,1,0, En,0, 1, 1.f, 0);
    add_ln_kernel<<<ROWS, 256>>>(tmp, st2, ln3_g, ln3_b, out_state);
}

// round 5
// speedup vs baseline: 3.3206x; 1.0397x over previous
#include <cuda_runtime.h>
#include <math.h>
#include <stdint.h>

// Problem dims
#define Tn 1024
#define Sn 1024
#define Bn 4
#define En 1024
#define Hn 16
#define DHn 64
#define FFn 4096
#define ROWS (Tn*Bn)
#define BH (Bn*Hn)
#define MEG (1024*1024)

// -------- scratch (device globals; no allocation) --------
__device__ float g_xq[ROWS*En];
__device__ float g_xk[ROWS*En];
__device__ float g_xv[ROWS*En];
__device__ float g_attn[ROWS*En];
__device__ float g_tmp[ROWS*En];
__device__ float g_state1[ROWS*En];
__device__ float g_state2[ROWS*En];
__device__ float g_st1r[ROWS*En];
__device__ float g_st2r[ROWS*En];
__device__ float g_ffn[ROWS*FFn];
__device__ float g_scores[(long)BH*Tn*Sn];
__device__ float g_rw[24*MEG];   // tf32-rounded weights & inputs

// ======================= helpers =======================
__device__ __forceinline__ uint32_t f2tf32(float x) {
    uint32_t r;
    asm("cvt.rna.tf32.f32 %0, %1;" : "=r"(r) : "f"(x));
    return r;
}
__device__ __forceinline__ float roundtf(float x) { return __uint_as_float(f2tf32(x)); }

__device__ __forceinline__ void mma_tf32(float* c, const uint32_t* a, const uint32_t* b) {
    asm volatile(
        "mma.sync.aligned.m16n8k8.row.col.f32.tf32.tf32.f32 "
        "{%0,%1,%2,%3}, {%4,%5,%6,%7}, {%8,%9}, {%0,%1,%2,%3};"
        : "+f"(c[0]), "+f"(c[1]), "+f"(c[2]), "+f"(c[3])
        : "r"(a[0]), "r"(a[1]), "r"(a[2]), "r"(a[3]), "r"(b[0]), "r"(b[1]));
}
__device__ __forceinline__ void cp16(uint32_t dst, const void* src) {
    asm volatile("cp.async.cg.shared.global [%0], [%1], 16;" :: "r"(dst), "l"(src));
}
__device__ __forceinline__ void cp_commit() {
    asm volatile("cp.async.commit_group;" ::: "memory");
}
__device__ __forceinline__ void cp_wait0() {
    asm volatile("cp.async.wait_group 0;" ::: "memory");
}
__device__ __forceinline__ uint32_t smaddr(const void* p) {
    return (uint32_t)__cvta_generic_to_shared(p);
}

// ======================= HMMA tf32 GEMM =======================
// C[m,n] = alpha * sum_k A[m,k]*B[n,k] (+bias) ; A k-contiguous.
// KN=false: B k-contiguous (weights [n][k]); KN=true: B n-contiguous.
// CVTA: apply tf32 rounding to A fragments (A not pre-rounded).
// B is ALWAYS assumed pre-rounded to tf32 values.
// postop: 0 = bias only; 1 = bias+relu+round; 2 = bias+round.
template<int BN, bool KN, bool CVTA>
__global__ __launch_bounds__(256, 2) void tgemm(
    const float* __restrict__ A, const float* __restrict__ B,
    const float* __restrict__ bias, float* __restrict__ C,
    int K,
    long lda_m, long a_bs,
    long ldb_n, long ldb_k, long b_bs,
    long ldc_m, long c_bs,
    float alpha, int postop)
{
    constexpr int BM = 128, BK = 32;
    constexpr int WARPS_N = BN / 32;
    constexpr int WARPS_M = 8 / WARPS_N;
    constexpr int MI = (BM / WARPS_M) / 16;
    constexpr int NI = 4;
    constexpr int A_STRIDE = BK + 4;
    constexpr int B_STRIDE = KN ? (BN + 8) : (BK + 4);
    constexpr int B_ROWS   = KN ? BK : BN;
    constexpr int A_TILE = BM * A_STRIDE;
    constexpr int B_TILE = B_ROWS * B_STRIDE;
    constexpr int BCPT = (BK * BN / 4) / 256;

    extern __shared__ float smf[];
    float* As = smf;
    float* Bs = smf + 2 * A_TILE;

    const int tid  = threadIdx.x;
    const int lane = tid & 31;
    const int wid  = tid >> 5;
    const int wm = wid % WARPS_M, wn = wid / WARPS_M;
    const int m_base = wm * (BM / WARPS_M);
    const int n_base = wn * 32;
    const int g  = lane >> 2;
    const int tg = lane & 3;

    const int bm = blockIdx.y * BM;
    const int bn = blockIdx.x * BN;
    A += (long)blockIdx.z * a_bs + (long)bm * lda_m;
    B += (long)blockIdx.z * b_bs + (long)bn * ldb_n;
    C += (long)blockIdx.z * c_bs;

    const float* aSrc[4];
    uint32_t aDst[4];
    #pragma unroll
    for (int i = 0; i < 4; i++) {
        int idx = tid + i * 256;
        int row = idx >> 3, c4 = idx & 7;
        aSrc[i] = A + (long)row * lda_m + c4 * 4;
        aDst[i] = smaddr(As + row * A_STRIDE + c4 * 4);
    }
    const float* bSrc[BCPT];
    uint32_t bDst[BCPT];
    #pragma unroll
    for (int i = 0; i < BCPT; i++) {
        int idx = tid + i * 256;
        if (KN) {
            int row = idx / (BN / 4), c4 = idx % (BN / 4);
            bSrc[i] = B + (long)row * ldb_k + c4 * 4;
            bDst[i] = smaddr(Bs + row * B_STRIDE + c4 * 4);
        } else {
            int row = idx >> 3, c4 = idx & 7;
            bSrc[i] = B + (long)row * ldb_n + c4 * 4;
            bDst[i] = smaddr(Bs + row * B_STRIDE + c4 * 4);
        }
    }
    const long bAdv = KN ? (long)BK * ldb_k : (long)BK;

    auto load_slab = [&](int st) {
        uint32_t ao = st * (A_TILE * 4);
        uint32_t bo = st * (B_TILE * 4);
        #pragma unroll
        for (int i = 0; i < 4; i++) { cp16(aDst[i] + ao, aSrc[i]); aSrc[i] += BK; }
        #pragma unroll
        for (int i = 0; i < BCPT; i++) { cp16(bDst[i] + bo, bSrc[i]); bSrc[i] += bAdv; }
        cp_commit();
    };

    float acc[MI][NI][4];
    #pragma unroll
    for (int mi = 0; mi < MI; mi++)
        #pragma unroll
        for (int ni = 0; ni < NI; ni++)
            #pragma unroll
            for (int r = 0; r < 4; r++) acc[mi][ni][r] = 0.f;

    const int nslab = K / BK;
    load_slab(0);

    for (int s = 0; s < nslab; s++) {
        cp_wait0();
        __syncthreads();
        if (s + 1 < nslab) load_slab((s + 1) & 1);

        const int st = s & 1;
        const float* Ab = As + st * A_TILE;
        const float* Bb = Bs + st * B_TILE;

        #pragma unroll
        for (int kk = 0; kk < BK; kk += 8) {
            uint32_t afr[MI][4], bfr[NI][2];
            #pragma unroll
            for (int mi = 0; mi < MI; mi++) {
                const float* ap = Ab + (m_base + mi * 16 + g) * A_STRIDE + kk;
                if (CVTA) {
                    afr[mi][0] = f2tf32(ap[tg]);
                    afr[mi][1] = f2tf32(ap[8 * A_STRIDE + tg]);
                    afr[mi][2] = f2tf32(ap[tg + 4]);
                    afr[mi][3] = f2tf32(ap[8 * A_STRIDE + tg + 4]);
                } else {
                    afr[mi][0] = __float_as_uint(ap[tg]);
                    afr[mi][1] = __float_as_uint(ap[8 * A_STRIDE + tg]);
                    afr[mi][2] = __float_as_uint(ap[tg + 4]);
                    afr[mi][3] = __float_as_uint(ap[8 * A_STRIDE + tg + 4]);
                }
            }
            #pragma unroll
            for (int ni = 0; ni < NI; ni++) {
                if (KN) {
                    const float* bp = Bb + (kk + tg) * B_STRIDE + n_base + ni * 8 + g;
                    bfr[ni][0] = __float_as_uint(bp[0]);
                    bfr[ni][1] = __float_as_uint(bp[4 * B_STRIDE]);
                } else {
                    const float* bp = Bb + (n_base + ni * 8 + g) * B_STRIDE + kk;
                    bfr[ni][0] = __float_as_uint(bp[tg]);
                    bfr[ni][1] = __float_as_uint(bp[tg + 4]);
                }
            }
            #pragma unroll
            for (int mi = 0; mi < MI; mi++)
                #pragma unroll
                for (int ni = 0; ni < NI; ni++)
                    mma_tf32(acc[mi][ni], afr[mi], bfr[ni]);
        }
        __syncthreads();
    }

    #pragma unroll
    for (int mi = 0; mi < MI; mi++) {
        int row0 = bm + m_base + mi * 16 + g;
        #pragma unroll
        for (int ni = 0; ni < NI; ni++) {
            int col = bn + n_base + ni * 8 + tg * 2;
            float b0 = bias ? bias[col] : 0.f;
            float b1 = bias ? bias[col + 1] : 0.f;
            float v0 = acc[mi][ni][0] * alpha + b0;
            float v1 = acc[mi][ni][1] * alpha + b1;
            float v2 = acc[mi][ni][2] * alpha + b0;
            float v3 = acc[mi][ni][3] * alpha + b1;
            if (postop == 1) {
                v0 = roundtf(fmaxf(v0, 0.f)); v1 = roundtf(fmaxf(v1, 0.f));
                v2 = roundtf(fmaxf(v2, 0.f)); v3 = roundtf(fmaxf(v3, 0.f));
            } else if (postop == 2) {
                v0 = roundtf(v0); v1 = roundtf(v1);
                v2 = roundtf(v2); v3 = roundtf(v3);
            }
            *(float2*)&C[(long)row0 * ldc_m + col]       = make_float2(v0, v1);
            *(float2*)&C[(long)(row0 + 8) * ldc_m + col] = make_float2(v2, v3);
        }
    }
}

// ======================= softmax (S=1024) with optional mask [T,S]
__global__ __launch_bounds__(256) void softmax_kernel(float* __restrict__ scores,
                                                      const float* __restrict__ mask)
{
    const int t = blockIdx.x;
    float* p = scores + ((long)blockIdx.y * Tn + t) * (long)Sn;
    const int tid = threadIdx.x;
    float v[4];
    float lmax = -1e30f;
    #pragma unroll
    for (int j = 0; j < 4; j++) {
        int s = tid + j * 256;
        float x = p[s];
        if (mask) x += mask[(long)t * Sn + s];
        v[j] = x;
        lmax = fmaxf(lmax, x);
    }
    __shared__ float sh[8];
    #pragma unroll
    for (int o = 16; o; o >>= 1) lmax = fmaxf(lmax, __shfl_xor_sync(0xffffffffu, lmax, o));
    if ((tid & 31) == 0) sh[tid >> 5] = lmax;
    __syncthreads();
    float gmax = fmaxf(fmaxf(fmaxf(sh[0], sh[1]), fmaxf(sh[2], sh[3])),
                       fmaxf(fmaxf(sh[4], sh[5]), fmaxf(sh[6], sh[7])));
    float lsum = 0.f;
    #pragma unroll
    for (int j = 0; j < 4; j++) { v[j] = expf(v[j] - gmax); lsum += v[j]; }
    #pragma unroll
    for (int o = 16; o; o >>= 1) lsum += __shfl_xor_sync(0xffffffffu, lsum, o);
    __syncthreads();
    if ((tid & 31) == 0) sh[tid >> 5] = lsum;
    __syncthreads();
    float gsum = sh[0] + sh[1] + sh[2] + sh[3] + sh[4] + sh[5] + sh[6] + sh[7];
    float inv = 1.f / gsum;
    #pragma unroll
    for (int j = 0; j < 4; j++) p[tid + j * 256] = v[j] * inv;
}

// ======================= out = LayerNorm(x+res)*g+b ; optional tf32-rounded copy
__global__ __launch_bounds__(256) void add_ln_kernel(
    const float* __restrict__ x, const float* __restrict__ res,
    const float* __restrict__ g, const float* __restrict__ b,
    float* __restrict__ out, float* __restrict__ out_r)
{
    const long row = (long)blockIdx.x * En;
    const int tid = threadIdx.x;
    float v[4]; float s = 0.f, s2 = 0.f;
    #pragma unroll
    for (int j = 0; j < 4; j++) {
        int i = tid + j * 256;
        float val = x[row + i] + res[row + i];
        v[j] = val; s += val; s2 += val * val;
    }
    __shared__ float sh1[8], sh2[8];
    #pragma unroll
    for (int o = 16; o; o >>= 1) {
        s  += __shfl_xor_sync(0xffffffffu, s, o);
        s2 += __shfl_xor_sync(0xffffffffu, s2, o);
    }
    if ((tid & 31) == 0) { sh1[tid >> 5] = s; sh2[tid >> 5] = s2; }
    __syncthreads();
    float ts = 0.f, ts2 = 0.f;
    #pragma unroll
    for (int w = 0; w < 8; w++) { ts += sh1[w]; ts2 += sh2[w]; }
    const float mu  = ts * (1.f / En);
    const float var = ts2 * (1.f / En) - mu * mu;
    const float inv = rsqrtf(var + 1e-5f);
    #pragma unroll
    for (int j = 0; j < 4; j++) {
        int i = tid + j * 256;
        float o = (v[j] - mu) * inv * g[i] + b[i];
        out[row + i] = o;
        if (out_r) out_r[row + i] = roundtf(o);
    }
}

// ======================= tf32 rounding pre-pass =======================
__global__ __launch_bounds__(256) void cvt_kernel(const float4* __restrict__ in,
                                                  float4* __restrict__ out, int n4)
{
    for (int i = blockIdx.x * 256 + threadIdx.x; i < n4; i += gridDim.x * 256) {
        float4 v = in[i];
        v.x = roundtf(v.x); v.y = roundtf(v.y);
        v.z = roundtf(v.z); v.w = roundtf(v.w);
        out[i] = v;
    }
}

// ======================= host-side =======================
#define SMEM128 ((2*128*36 + 2*128*36) * 4)
#define SMEM64  ((2*128*36 + 2*32*72) * 4)

static inline void gemm128(const float* A, const float* B, const float* bias, float* C,
                           int M, int N, int K,
                           long lda_m, long a_bs,
                           long ldb_n, long ldb_k, long b_bs,
                           long ldc_m, long c_bs, int batch,
                           float alpha, int postop)
{
    dim3 grid(N / 128, M / 128, batch);
    tgemm<128, false, false><<<grid, 256, SMEM128>>>(A, B, bias, C, K, lda_m, a_bs,
                                                     ldb_n, ldb_k, b_bs, ldc_m, c_bs,
                                                     alpha, postop);
}
static inline void gemm64av(const float* A, const float* B, float* C,
                            int M, int N, int K,
                            long lda_m, long a_bs,
                            long ldb_n, long ldb_k, long b_bs,
                            long ldc_m, long c_bs, int batch,
                            float alpha, int postop)
{
    dim3 grid(N / 64, M / 128, batch);
    tgemm<64, true, true><<<grid, 256, SMEM64>>>(A, B, nullptr, C, K, lda_m, a_bs,
                                                 ldb_n, ldb_k, b_bs, ldc_m, c_bs,
                                                 alpha, postop);
}
static inline void cvt(const float* in, float* out, long n)
{
    cvt_kernel<<<512, 256>>>((const float4*)in, (float4*)out, (int)(n / 4));
}

extern "C" void kernel_launch(void* const* d_in, const int* in_sizes, int n_in,
                              void* d_out, int out_size)
{
    static bool attr_done = false;
    if (!attr_done) {
        cudaFuncSetAttribute((const void*)tgemm<128, false, false>,
                             cudaFuncAttributeMaxDynamicSharedMemorySize, SMEM128);
        cudaFuncSetAttribute((const void*)tgemm<64, true, true>,
                             cudaFuncAttributeMaxDynamicSharedMemorySize, SMEM64);
        attr_done = true;
    }

    const float* state = (const float*)d_in[0];
    const float* enc   = (const float*)d_in[1];
    const float* mask  = (const float*)d_in[2];
    const float* sa_wq = (const float*)d_in[3];  const float* sa_bq = (const float*)d_in[4];
    const float* sa_wk = (const float*)d_in[5];  const float* sa_bk = (const float*)d_in[6];
    const float* sa_wv = (const float*)d_in[7];  const float* sa_bv = (const float*)d_in[8];
    const float* sa_wo = (const float*)d_in[9];  const float* sa_bo = (const float*)d_in[10];
    const float* ea_wq = (const float*)d_in[11]; const float* ea_bq = (const float*)d_in[12];
    const float* ea_wk = (const float*)d_in[13]; const float* ea_bk = (const float*)d_in[14];
    const float* ea_wv = (const float*)d_in[15]; const float* ea_bv = (const float*)d_in[16];
    const float* ea_wo = (const float*)d_in[17]; const float* ea_bo = (const float*)d_in[18];
    const float* fc1_w = (const float*)d_in[19]; const float* fc1_b = (const float*)d_in[20];
    const float* fc2_w = (const float*)d_in[21]; const float* fc2_b = (const float*)d_in[22];
    const float* ln1_g = (const float*)d_in[23]; const float* ln1_b = (const float*)d_in[24];
    const float* ln2_g = (const float*)d_in[25]; const float* ln2_b = (const float*)d_in[26];
    const float* ln3_g = (const float*)d_in[27]; const float* ln3_b = (const float*)d_in[28];

    float *xq, *xk, *xv, *attn, *tmp, *st1, *st2, *st1r, *st2r, *ffn, *scores, *rw;
    cudaGetSymbolAddress((void**)&xq,     g_xq);
    cudaGetSymbolAddress((void**)&xk,     g_xk);
    cudaGetSymbolAddress((void**)&xv,     g_xv);
    cudaGetSymbolAddress((void**)&attn,   g_attn);
    cudaGetSymbolAddress((void**)&tmp,    g_tmp);
    cudaGetSymbolAddress((void**)&st1,    g_state1);
    cudaGetSymbolAddress((void**)&st2,    g_state2);
    cudaGetSymbolAddress((void**)&st1r,   g_st1r);
    cudaGetSymbolAddress((void**)&st2r,   g_st2r);
    cudaGetSymbolAddress((void**)&ffn,    g_ffn);
    cudaGetSymbolAddress((void**)&scores, g_scores);
    cudaGetSymbolAddress((void**)&rw,     g_rw);

    float* r_state = rw + 0L  * MEG;
    float* r_enc   = rw + 4L  * MEG;
    float* r_saq   = rw + 8L  * MEG;
    float* r_sak   = rw + 9L  * MEG;
    float* r_sav   = rw + 10L * MEG;
    float* r_sao   = rw + 11L * MEG;
    float* r_eaq   = rw + 12L * MEG;
    float* r_eak   = rw + 13L * MEG;
    float* r_eav   = rw + 14L * MEG;
    float* r_eao   = rw + 15L * MEG;
    float* r_fc1   = rw + 16L * MEG;
    float* r_fc2   = rw + 20L * MEG;

    float* out_state = (float*)d_out;
    float* out_attn  = (float*)d_out + (long)Tn * Bn * En;

    const float sc = 1.0f / 8.0f;
    const long BE = (long)Bn * En;
    const long TS = (long)Tn * Sn;

    // -------- tf32 pre-round pass --------
    cvt(state, r_state, (long)ROWS * En);
    cvt(enc,   r_enc,   (long)Sn * Bn * En);
    cvt(sa_wq, r_saq, (long)En * En);  cvt(sa_wk, r_sak, (long)En * En);
    cvt(sa_wv, r_sav, (long)En * En);  cvt(sa_wo, r_sao, (long)En * En);
    cvt(ea_wq, r_eaq, (long)En * En);  cvt(ea_wk, r_eak, (long)En * En);
    cvt(ea_wv, r_eav, (long)En * En);  cvt(ea_wo, r_eao, (long)En * En);
    cvt(fc1_w, r_fc1, (long)FFn * En); cvt(fc2_w, r_fc2, (long)En * FFn);

    // ---------------- self-attention ----------------
    gemm128(r_state, r_saq, sa_bq, xq, ROWS, En, En, En,0, En,1,0, En,0, 1, 1.f, 2);
    gemm128(r_state, r_sak, sa_bk, xk, ROWS, En, En, En,0, En,1,0, En,0, 1, 1.f, 2);
    gemm128(r_state, r_sav, sa_bv, xv, ROWS, En, En, En,0, En,1,0, En,0, 1, 1.f, 2);
    gemm128(xq, xk, nullptr, scores, Tn, Sn, DHn,
            BE,DHn,  BE,1,DHn,  Sn,TS, BH, sc, 0);
    softmax_kernel<<<dim3(Tn, BH), 256>>>(scores, mask);
    gemm64av(scores, xv, attn, Tn, DHn, Sn,
             Sn,TS,  1,BE,DHn,  BE,DHn, BH, 1.f, 2);
    gemm128(attn, r_sao, sa_bo, tmp, ROWS, En, En, En,0, En,1,0, En,0, 1, 1.f, 0);
    add_ln_kernel<<<ROWS, 256>>>(tmp, state, ln1_g, ln1_b, st1, st1r);

    // ---------------- encoder-decoder attention ----------------
    gemm128(st1r, r_eaq, ea_bq, xq, ROWS, En, En, En,0, En,1,0, En,0, 1, 1.f, 2);
    gemm128(r_enc, r_eak, ea_bk, xk, ROWS, En, En, En,0, En,1,0, En,0, 1, 1.f, 2);
    gemm128(r_enc, r_eav, ea_bv, xv, ROWS, En, En, En,0, En,1,0, En,0, 1, 1.f, 2);
    gemm128(xq, xk, nullptr, out_attn, Tn, Sn, DHn,
            BE,DHn,  BE,1,DHn,  Sn,TS, BH, sc, 0);
    softmax_kernel<<<dim3(Tn, BH), 256>>>(out_attn, nullptr);
    gemm64av(out_attn, xv, attn, Tn, DHn, Sn,
             Sn,TS,  1,BE,DHn,  BE,DHn, BH, 1.f, 2);
    gemm128(attn, r_eao, ea_bo, tmp, ROWS, En, En, En,0, En,1,0, En,0, 1, 1.f, 0);
    add_ln_kernel<<<ROWS, 256>>>(tmp, st1, ln2_g, ln2_b, st2, st2r);

    // ---------------- FFN ----------------
    gemm128(st2r, r_fc1, fc1_b, ffn, ROWS, FFn, En, En,0, En,1,0, FFn,0, 1, 1.f, 1);
    gemm128(ffn,  r_fc2, fc2_b, tmp, ROWS, En, FFn, FFn,0, FFn,1,0, En,0, 1, 1.f, 0);
    add_ln_kernel<<<ROWS, 256>>>(tmp, st2, ln3_g, ln3_b, out_state, nullptr);
}

// round 6
// speedup vs baseline: 3.6764x; 1.1072x over previous
#include <cuda_runtime.h>
#include <math.h>
#include <stdint.h>

// Problem dims
#define Tn 1024
#define Sn 1024
#define Bn 4
#define En 1024
#define Hn 16
#define DHn 64
#define FFn 4096
#define ROWS (Tn*Bn)
#define BH (Bn*Hn)
#define MEG (1024*1024)

// -------- scratch (device globals; no allocation) --------
__device__ float g_xq[ROWS*En];
__device__ float g_xk[ROWS*En];
__device__ float g_xv[ROWS*En];
__device__ float g_attn[ROWS*En];
__device__ float g_tmp[ROWS*En];
__device__ float g_state1[ROWS*En];
__device__ float g_state2[ROWS*En];
__device__ float g_st1r[ROWS*En];
__device__ float g_st2r[ROWS*En];
__device__ float g_ffn[ROWS*FFn];
__device__ float2 g_stats[BH*Tn];
__device__ float g_rw[24*MEG];   // tf32-rounded weights & inputs

// ======================= helpers =======================
__device__ __forceinline__ uint32_t f2tf32(float x) {
    uint32_t r;
    asm("cvt.rna.tf32.f32 %0, %1;" : "=r"(r) : "f"(x));
    return r;
}
__device__ __forceinline__ float roundtf(float x) { return __uint_as_float(f2tf32(x)); }

__device__ __forceinline__ void mma_tf32(float* c, const uint32_t* a, const uint32_t* b) {
    asm volatile(
        "mma.sync.aligned.m16n8k8.row.col.f32.tf32.tf32.f32 "
        "{%0,%1,%2,%3}, {%4,%5,%6,%7}, {%8,%9}, {%0,%1,%2,%3};"
        : "+f"(c[0]), "+f"(c[1]), "+f"(c[2]), "+f"(c[3])
        : "r"(a[0]), "r"(a[1]), "r"(a[2]), "r"(a[3]), "r"(b[0]), "r"(b[1]));
}
__device__ __forceinline__ void cp16(uint32_t dst, const void* src) {
    asm volatile("cp.async.cg.shared.global [%0], [%1], 16;" :: "r"(dst), "l"(src));
}
__device__ __forceinline__ void cp_commit() {
    asm volatile("cp.async.commit_group;" ::: "memory");
}
__device__ __forceinline__ void cp_wait0() {
    asm volatile("cp.async.wait_group 0;" ::: "memory");
}
__device__ __forceinline__ uint32_t smaddr(const void* p) {
    return (uint32_t)__cvta_generic_to_shared(p);
}

// ======================= fused flash attention =======================
// Q/K/V: [t][b][h][d] flat; per (bh) base offset bh*64, row stride 4096.
// O (attn) same layout, written tf32-rounded. DH=64, S tile = 64 rows.
// CAUSAL: analytic causal mask (matches reference -1e9 additive mask).
// !CAUSAL: also writes per-row (max, sum) stats for the weight-normalize pass.
#define FL_QS 68
#define FL_KS 68
#define FL_VS 72
#define FL_PS 68
#define FL_SMEM ((128*FL_QS + 2*64*FL_KS + 2*64*FL_VS + 128*FL_PS) * 4)

template<bool CAUSAL>
__global__ __launch_bounds__(256, 1) void flash_kernel(
    const float* __restrict__ Qp, const float* __restrict__ Kp,
    const float* __restrict__ Vp, float* __restrict__ Op,
    float2* __restrict__ stats)
{
    extern __shared__ float fsm[];
    float* Qs = fsm;                       // [128][68]
    float* Ks = Qs + 128 * FL_QS;          // [2][64][68]
    float* Vs = Ks + 2 * 64 * FL_KS;       // [2][64][72]
    float* Ps = Vs + 2 * 64 * FL_VS;       // [128][68]

    const int tid = threadIdx.x;
    const int lane = tid & 31, w = tid >> 5;
    const int g = lane >> 2, tg = lane & 3;
    const int bh = blockIdx.y;
    const int it = CAUSAL ? ((int)gridDim.x - 1 - (int)blockIdx.x) : (int)blockIdx.x;
    const int t0 = it * 128;
    const int nIter = CAUSAL ? 2 * it + 2 : 16;

    const float* Qg = Qp + (long)t0 * 4096 + bh * 64;
    const float* Kg = Kp + bh * 64;
    const float* Vg = Vp + bh * 64;

    auto loadKV = [&](int j, int buf) {
        float* kb = Ks + buf * 64 * FL_KS;
        float* vb = Vs + buf * 64 * FL_VS;
        const long s0 = (long)j * 64;
        #pragma unroll
        for (int i = 0; i < 4; i++) {
            int idx = tid + i * 256;
            int row = idx >> 4, c = idx & 15;
            cp16(smaddr(kb + row * FL_KS + c * 4), Kg + (s0 + row) * 4096 + c * 4);
            cp16(smaddr(vb + row * FL_VS + c * 4), Vg + (s0 + row) * 4096 + c * 4);
        }
    };

    // Q load + first KV tile
    #pragma unroll
    for (int i = 0; i < 8; i++) {
        int idx = tid + i * 256;
        int row = idx >> 4, c = idx & 15;
        cp16(smaddr(Qs + row * FL_QS + c * 4), Qg + (long)row * 4096 + c * 4);
    }
    loadKV(0, 0);
    cp_commit();
    cp_wait0();
    __syncthreads();

    // preload Q fragments (pre-rounded tf32 in gmem)
    uint32_t qf[8][4];
    {
        const float* qp = Qs + (16 * w + g) * FL_QS;
        #pragma unroll
        for (int kk = 0; kk < 8; kk++) {
            qf[kk][0] = __float_as_uint(qp[kk * 8 + tg]);
            qf[kk][1] = __float_as_uint(qp[8 * FL_QS + kk * 8 + tg]);
            qf[kk][2] = __float_as_uint(qp[kk * 8 + tg + 4]);
            qf[kk][3] = __float_as_uint(qp[8 * FL_QS + kk * 8 + tg + 4]);
        }
    }

    float acc_o[8][4];
    #pragma unroll
    for (int ni = 0; ni < 8; ni++)
        #pragma unroll
        for (int r = 0; r < 4; r++) acc_o[ni][r] = 0.f;
    float m0 = -1e30f, m1 = -1e30f, l0 = 0.f, l1 = 0.f;

    for (int j = 0; j < nIter; j++) {
        const int buf = j & 1;
        if (j + 1 < nIter) { loadKV(j + 1, buf ^ 1); cp_commit(); }

        // ---- S = Q K^T ----
        float s_acc[8][4];
        #pragma unroll
        for (int ni = 0; ni < 8; ni++)
            #pragma unroll
            for (int r = 0; r < 4; r++) s_acc[ni][r] = 0.f;
        const float* kb = Ks + buf * 64 * FL_KS;
        #pragma unroll
        for (int kk = 0; kk < 8; kk++) {
            #pragma unroll
            for (int ni = 0; ni < 8; ni++) {
                const float* bp = kb + (ni * 8 + g) * FL_KS + kk * 8;
                uint32_t bfr[2];
                bfr[0] = __float_as_uint(bp[tg]);
                bfr[1] = __float_as_uint(bp[tg + 4]);
                mma_tf32(s_acc[ni], qf[kk], bfr);
            }
        }

        // ---- scale + mask + online softmax ----
        const int s0 = j * 64;
        const bool need = CAUSAL && (s0 + 63 > t0 + 16 * w);
        const int tr0 = t0 + 16 * w + g, tr1 = tr0 + 8;
        float mx0 = -1e30f, mx1 = -1e30f;
        #pragma unroll
        for (int ni = 0; ni < 8; ni++) {
            float v0 = s_acc[ni][0] * 0.125f;
            float v1 = s_acc[ni][1] * 0.125f;
            float v2 = s_acc[ni][2] * 0.125f;
            float v3 = s_acc[ni][3] * 0.125f;
            if (need) {
                int c0 = s0 + ni * 8 + 2 * tg, c1 = c0 + 1;
                if (c0 > tr0) v0 -= 1e9f;
                if (c1 > tr0) v1 -= 1e9f;
                if (c0 > tr1) v2 -= 1e9f;
                if (c1 > tr1) v3 -= 1e9f;
            }
            s_acc[ni][0] = v0; s_acc[ni][1] = v1;
            s_acc[ni][2] = v2; s_acc[ni][3] = v3;
            mx0 = fmaxf(mx0, fmaxf(v0, v1));
            mx1 = fmaxf(mx1, fmaxf(v2, v3));
        }
        mx0 = fmaxf(mx0, __shfl_xor_sync(0xffffffffu, mx0, 1));
        mx0 = fmaxf(mx0, __shfl_xor_sync(0xffffffffu, mx0, 2));
        mx1 = fmaxf(mx1, __shfl_xor_sync(0xffffffffu, mx1, 1));
        mx1 = fmaxf(mx1, __shfl_xor_sync(0xffffffffu, mx1, 2));
        const float mn0 = fmaxf(m0, mx0), mn1 = fmaxf(m1, mx1);
        const float sc0 = expf(m0 - mn0), sc1 = expf(m1 - mn1);
        m0 = mn0; m1 = mn1;

        float sum0 = 0.f, sum1 = 0.f;
        float* prow0 = Ps + (16 * w + g) * FL_PS;
        float* prow1 = prow0 + 8 * FL_PS;
        #pragma unroll
        for (int ni = 0; ni < 8; ni++) {
            float p0 = expf(s_acc[ni][0] - m0);
            float p1 = expf(s_acc[ni][1] - m0);
            float p2 = expf(s_acc[ni][2] - m1);
            float p3 = expf(s_acc[ni][3] - m1);
            sum0 += p0 + p1; sum1 += p2 + p3;
            *(float2*)&prow0[ni * 8 + 2 * tg] = make_float2(roundtf(p0), roundtf(p1));
            *(float2*)&prow1[ni * 8 + 2 * tg] = make_float2(roundtf(p2), roundtf(p3));
        }
        sum0 += __shfl_xor_sync(0xffffffffu, sum0, 1);
        sum0 += __shfl_xor_sync(0xffffffffu, sum0, 2);
        sum1 += __shfl_xor_sync(0xffffffffu, sum1, 1);
        sum1 += __shfl_xor_sync(0xffffffffu, sum1, 2);
        l0 = l0 * sc0 + sum0;
        l1 = l1 * sc1 + sum1;
        #pragma unroll
        for (int ni = 0; ni < 8; ni++) {
            acc_o[ni][0] *= sc0; acc_o[ni][1] *= sc0;
            acc_o[ni][2] *= sc1; acc_o[ni][3] *= sc1;
        }
        __syncthreads();   // P visible; all warps done reading Ks[buf]

        // ---- O += P V ----
        const float* vb = Vs + buf * 64 * FL_VS;
        const float* pp = Ps + (16 * w + g) * FL_PS;
        #pragma unroll
        for (int kk = 0; kk < 8; kk++) {
            uint32_t pf[4];
            pf[0] = __float_as_uint(pp[kk * 8 + tg]);
            pf[1] = __float_as_uint(pp[8 * FL_PS + kk * 8 + tg]);
            pf[2] = __float_as_uint(pp[kk * 8 + tg + 4]);
            pf[3] = __float_as_uint(pp[8 * FL_PS + kk * 8 + tg + 4]);
            #pragma unroll
            for (int ni = 0; ni < 8; ni++) {
                const float* vp = vb + (kk * 8 + tg) * FL_VS + ni * 8 + g;
                uint32_t bfr[2];
                bfr[0] = __float_as_uint(vp[0]);
                bfr[1] = __float_as_uint(vp[4 * FL_VS]);
                mma_tf32(acc_o[ni], pf, bfr);
            }
        }
        if (j + 1 < nIter) cp_wait0();
        __syncthreads();   // Ps/Vs free; next KV landed
    }

    // ---- epilogue ----
    const float inv0 = 1.f / l0, inv1 = 1.f / l1;
    const int r0 = t0 + 16 * w + g;
    float* o0 = Op + (long)r0 * 4096 + bh * 64;
    float* o1 = o0 + 8L * 4096;
    #pragma unroll
    for (int ni = 0; ni < 8; ni++) {
        *(float2*)&o0[ni * 8 + 2 * tg] =
            make_float2(roundtf(acc_o[ni][0] * inv0), roundtf(acc_o[ni][1] * inv0));
        *(float2*)&o1[ni * 8 + 2 * tg] =
            make_float2(roundtf(acc_o[ni][2] * inv1), roundtf(acc_o[ni][3] * inv1));
    }
    if (!CAUSAL && tg == 0) {
        stats[bh * Tn + r0]     = make_float2(m0, l0);
        stats[bh * Tn + r0 + 8] = make_float2(m1, l1);
    }
}

// ======================= HMMA tf32 GEMM =======================
// C[m,n] = alpha * sum_k A[m,k]*B[n,k] (+bias) ; A k-contiguous, pre-rounded.
// postop: 0 bias only; 1 bias+relu+round; 2 bias+round;
//         3 softmax-normalize: C = exp(alpha*acc - m_row)/l_row (stats per batch row).
template<int BN, bool KN>
__global__ __launch_bounds__(256, 2) void tgemm(
    const float* __restrict__ A, const float* __restrict__ B,
    const float* __restrict__ bias, const float2* __restrict__ stats,
    float* __restrict__ C,
    int K,
    long lda_m, long a_bs,
    long ldb_n, long ldb_k, long b_bs,
    long ldc_m, long c_bs,
    float alpha, int postop)
{
    constexpr int BM = 128, BK = 32;
    constexpr int WARPS_N = BN / 32;
    constexpr int WARPS_M = 8 / WARPS_N;
    constexpr int MI = (BM / WARPS_M) / 16;
    constexpr int NI = 4;
    constexpr int A_STRIDE = BK + 4;
    constexpr int B_STRIDE = KN ? (BN + 8) : (BK + 4);
    constexpr int B_ROWS   = KN ? BK : BN;
    constexpr int A_TILE = BM * A_STRIDE;
    constexpr int B_TILE = B_ROWS * B_STRIDE;
    constexpr int BCPT = (BK * BN / 4) / 256;

    extern __shared__ float smf[];
    float* As = smf;
    float* Bs = smf + 2 * A_TILE;

    const int tid  = threadIdx.x;
    const int lane = tid & 31;
    const int wid  = tid >> 5;
    const int wm = wid % WARPS_M, wn = wid / WARPS_M;
    const int m_base = wm * (BM / WARPS_M);
    const int n_base = wn * 32;
    const int g  = lane >> 2;
    const int tg = lane & 3;

    const int bm = blockIdx.y * BM;
    const int bn = blockIdx.x * BN;
    A += (long)blockIdx.z * a_bs + (long)bm * lda_m;
    B += (long)blockIdx.z * b_bs + (long)bn * ldb_n;
    C += (long)blockIdx.z * c_bs;

    const float* aSrc[4];
    uint32_t aDst[4];
    #pragma unroll
    for (int i = 0; i < 4; i++) {
        int idx = tid + i * 256;
        int row = idx >> 3, c4 = idx & 7;
        aSrc[i] = A + (long)row * lda_m + c4 * 4;
        aDst[i] = smaddr(As + row * A_STRIDE + c4 * 4);
    }
    const float* bSrc[BCPT];
    uint32_t bDst[BCPT];
    #pragma unroll
    for (int i = 0; i < BCPT; i++) {
        int idx = tid + i * 256;
        if (KN) {
            int row = idx / (BN / 4), c4 = idx % (BN / 4);
            bSrc[i] = B + (long)row * ldb_k + c4 * 4;
            bDst[i] = smaddr(Bs + row * B_STRIDE + c4 * 4);
        } else {
            int row = idx >> 3, c4 = idx & 7;
            bSrc[i] = B + (long)row * ldb_n + c4 * 4;
            bDst[i] = smaddr(Bs + row * B_STRIDE + c4 * 4);
        }
    }
    const long bAdv = KN ? (long)BK * ldb_k : (long)BK;

    auto load_slab = [&](int st) {
        uint32_t ao = st * (A_TILE * 4);
        uint32_t bo = st * (B_TILE * 4);
        #pragma unroll
        for (int i = 0; i < 4; i++) { cp16(aDst[i] + ao, aSrc[i]); aSrc[i] += BK; }
        #pragma unroll
        for (int i = 0; i < BCPT; i++) { cp16(bDst[i] + bo, bSrc[i]); bSrc[i] += bAdv; }
        cp_commit();
    };

    float acc[MI][NI][4];
    #pragma unroll
    for (int mi = 0; mi < MI; mi++)
        #pragma unroll
        for (int ni = 0; ni < NI; ni++)
            #pragma unroll
            for (int r = 0; r < 4; r++) acc[mi][ni][r] = 0.f;

    const int nslab = K / BK;
    load_slab(0);

    for (int s = 0; s < nslab; s++) {
        cp_wait0();
        __syncthreads();
        if (s + 1 < nslab) load_slab((s + 1) & 1);

        const int st = s & 1;
        const float* Ab = As + st * A_TILE;
        const float* Bb = Bs + st * B_TILE;

        #pragma unroll
        for (int kk = 0; kk < BK; kk += 8) {
            uint32_t afr[MI][4], bfr[NI][2];
            #pragma unroll
            for (int mi = 0; mi < MI; mi++) {
                const float* ap = Ab + (m_base + mi * 16 + g) * A_STRIDE + kk;
                afr[mi][0] = __float_as_uint(ap[tg]);
                afr[mi][1] = __float_as_uint(ap[8 * A_STRIDE + tg]);
                afr[mi][2] = __float_as_uint(ap[tg + 4]);
                afr[mi][3] = __float_as_uint(ap[8 * A_STRIDE + tg + 4]);
            }
            #pragma unroll
            for (int ni = 0; ni < NI; ni++) {
                if (KN) {
                    const float* bp = Bb + (kk + tg) * B_STRIDE + n_base + ni * 8 + g;
                    bfr[ni][0] = __float_as_uint(bp[0]);
                    bfr[ni][1] = __float_as_uint(bp[4 * B_STRIDE]);
                } else {
                    const float* bp = Bb + (n_base + ni * 8 + g) * B_STRIDE + kk;
                    bfr[ni][0] = __float_as_uint(bp[tg]);
                    bfr[ni][1] = __float_as_uint(bp[tg + 4]);
                }
            }
            #pragma unroll
            for (int mi = 0; mi < MI; mi++)
                #pragma unroll
                for (int ni = 0; ni < NI; ni++)
                    mma_tf32(acc[mi][ni], afr[mi], bfr[ni]);
        }
        __syncthreads();
    }

    #pragma unroll
    for (int mi = 0; mi < MI; mi++) {
        int row0 = bm + m_base + mi * 16 + g;
        float2 ml0 = make_float2(0.f, 1.f), ml1 = make_float2(0.f, 1.f);
        float i0 = 0.f, i1 = 0.f;
        if (postop == 3) {
            ml0 = stats[(long)blockIdx.z * Tn + row0];
            ml1 = stats[(long)blockIdx.z * Tn + row0 + 8];
            i0 = 1.f / ml0.y; i1 = 1.f / ml1.y;
        }
        #pragma unroll
        for (int ni = 0; ni < NI; ni++) {
            int col = bn + n_base + ni * 8 + tg * 2;
            float b0 = bias ? bias[col] : 0.f;
            float b1 = bias ? bias[col + 1] : 0.f;
            float v0 = acc[mi][ni][0] * alpha + b0;
            float v1 = acc[mi][ni][1] * alpha + b1;
            float v2 = acc[mi][ni][2] * alpha + b0;
            float v3 = acc[mi][ni][3] * alpha + b1;
            if (postop == 1) {
                v0 = roundtf(fmaxf(v0, 0.f)); v1 = roundtf(fmaxf(v1, 0.f));
                v2 = roundtf(fmaxf(v2, 0.f)); v3 = roundtf(fmaxf(v3, 0.f));
            } else if (postop == 2) {
                v0 = roundtf(v0); v1 = roundtf(v1);
                v2 = roundtf(v2); v3 = roundtf(v3);
            } else if (postop == 3) {
                v0 = expf(v0 - ml0.x) * i0; v1 = expf(v1 - ml0.x) * i0;
                v2 = expf(v2 - ml1.x) * i1; v3 = expf(v3 - ml1.x) * i1;
            }
            *(float2*)&C[(long)row0 * ldc_m + col]       = make_float2(v0, v1);
            *(float2*)&C[(long)(row0 + 8) * ldc_m + col] = make_float2(v2, v3);
        }
    }
}

// ======================= out = LayerNorm(x+res)*g+b ; optional tf32-rounded copy
__global__ __launch_bounds__(256) void add_ln_kernel(
    const float* __restrict__ x, const float* __restrict__ res,
    const float* __restrict__ g, const float* __restrict__ b,
    float* __restrict__ out, float* __restrict__ out_r)
{
    const long row = (long)blockIdx.x * En;
    const int tid = threadIdx.x;
    float v[4]; float s = 0.f, s2 = 0.f;
    #pragma unroll
    for (int j = 0; j < 4; j++) {
        int i = tid + j * 256;
        float val = x[row + i] + res[row + i];
        v[j] = val; s += val; s2 += val * val;
    }
    __shared__ float sh1[8], sh2[8];
    #pragma unroll
    for (int o = 16; o; o >>= 1) {
        s  += __shfl_xor_sync(0xffffffffu, s, o);
        s2 += __shfl_xor_sync(0xffffffffu, s2, o);
    }
    if ((tid & 31) == 0) { sh1[tid >> 5] = s; sh2[tid >> 5] = s2; }
    __syncthreads();
    float ts = 0.f, ts2 = 0.f;
    #pragma unroll
    for (int w = 0; w < 8; w++) { ts += sh1[w]; ts2 += sh2[w]; }
    const float mu  = ts * (1.f / En);
    const float var = ts2 * (1.f / En) - mu * mu;
    const float inv = rsqrtf(var + 1e-5f);
    #pragma unroll
    for (int j = 0; j < 4; j++) {
        int i = tid + j * 256;
        float o = (v[j] - mu) * inv * g[i] + b[i];
        out[row + i] = o;
        if (out_r) out_r[row + i] = roundtf(o);
    }
}

// ======================= tf32 rounding pre-pass =======================
__global__ __launch_bounds__(256) void cvt_kernel(const float4* __restrict__ in,
                                                  float4* __restrict__ out, int n4)
{
    for (int i = blockIdx.x * 256 + threadIdx.x; i < n4; i += gridDim.x * 256) {
        float4 v = in[i];
        v.x = roundtf(v.x); v.y = roundtf(v.y);
        v.z = roundtf(v.z); v.w = roundtf(v.w);
        out[i] = v;
    }
}

// ======================= host-side =======================
#define SMEM128 ((2*128*36 + 2*128*36) * 4)

static inline void gemm128(const float* A, const float* B, const float* bias,
                           const float2* stats, float* C,
                           int M, int N, int K,
                           long lda_m, long a_bs,
                           long ldb_n, long ldb_k, long b_bs,
                           long ldc_m, long c_bs, int batch,
                           float alpha, int postop)
{
    dim3 grid(N / 128, M / 128, batch);
    tgemm<128, false><<<grid, 256, SMEM128>>>(A, B, bias, stats, C, K, lda_m, a_bs,
                                              ldb_n, ldb_k, b_bs, ldc_m, c_bs,
                                              alpha, postop);
}
static inline void cvt(const float* in, float* out, long n)
{
    cvt_kernel<<<512, 256>>>((const float4*)in, (float4*)out, (int)(n / 4));
}

extern "C" void kernel_launch(void* const* d_in, const int* in_sizes, int n_in,
                              void* d_out, int out_size)
{
    static bool attr_done = false;
    if (!attr_done) {
        cudaFuncSetAttribute((const void*)tgemm<128, false>,
                             cudaFuncAttributeMaxDynamicSharedMemorySize, SMEM128);
        cudaFuncSetAttribute((const void*)flash_kernel<true>,
                             cudaFuncAttributeMaxDynamicSharedMemorySize, FL_SMEM);
        cudaFuncSetAttribute((const void*)flash_kernel<false>,
                             cudaFuncAttributeMaxDynamicSharedMemorySize, FL_SMEM);
        attr_done = true;
    }

    const float* state = (const float*)d_in[0];
    const float* enc   = (const float*)d_in[1];
    const float* sa_wq = (const float*)d_in[3];  const float* sa_bq = (const float*)d_in[4];
    const float* sa_wk = (const float*)d_in[5];  const float* sa_bk = (const float*)d_in[6];
    const float* sa_wv = (const float*)d_in[7];  const float* sa_bv = (const float*)d_in[8];
    const float* sa_wo = (const float*)d_in[9];  const float* sa_bo = (const float*)d_in[10];
    const float* ea_wq = (const float*)d_in[11]; const float* ea_bq = (const float*)d_in[12];
    const float* ea_wk = (const float*)d_in[13]; const float* ea_bk = (const float*)d_in[14];
    const float* ea_wv = (const float*)d_in[15]; const float* ea_bv = (const float*)d_in[16];
    const float* ea_wo = (const float*)d_in[17]; const float* ea_bo = (const float*)d_in[18];
    const float* fc1_w = (const float*)d_in[19]; const float* fc1_b = (const float*)d_in[20];
    const float* fc2_w = (const float*)d_in[21]; const float* fc2_b = (const float*)d_in[22];
    const float* ln1_g = (const float*)d_in[23]; const float* ln1_b = (const float*)d_in[24];
    const float* ln2_g = (const float*)d_in[25]; const float* ln2_b = (const float*)d_in[26];
    const float* ln3_g = (const float*)d_in[27]; const float* ln3_b = (const float*)d_in[28];

    float *xq, *xk, *xv, *attn, *tmp, *st1, *st2, *st1r, *st2r, *ffn, *rw;
    float2* stats;
    cudaGetSymbolAddress((void**)&xq,    g_xq);
    cudaGetSymbolAddress((void**)&xk,    g_xk);
    cudaGetSymbolAddress((void**)&xv,    g_xv);
    cudaGetSymbolAddress((void**)&attn,  g_attn);
    cudaGetSymbolAddress((void**)&tmp,   g_tmp);
    cudaGetSymbolAddress((void**)&st1,   g_state1);
    cudaGetSymbolAddress((void**)&st2,   g_state2);
    cudaGetSymbolAddress((void**)&st1r,  g_st1r);
    cudaGetSymbolAddress((void**)&st2r,  g_st2r);
    cudaGetSymbolAddress((void**)&ffn,   g_ffn);
    cudaGetSymbolAddress((void**)&stats, g_stats);
    cudaGetSymbolAddress((void**)&rw,    g_rw);

    float* r_state = rw + 0L  * MEG;
    float* r_enc   = rw + 4L  * MEG;
    float* r_saq   = rw + 8L  * MEG;
    float* r_sak   = rw + 9L  * MEG;
    float* r_sav   = rw + 10L * MEG;
    float* r_sao   = rw + 11L * MEG;
    float* r_eaq   = rw + 12L * MEG;
    float* r_eak   = rw + 13L * MEG;
    float* r_eav   = rw + 14L * MEG;
    float* r_eao   = rw + 15L * MEG;
    float* r_fc1   = rw + 16L * MEG;
    float* r_fc2   = rw + 20L * MEG;

    float* out_state = (float*)d_out;
    float* out_attn  = (float*)d_out + (long)Tn * Bn * En;

    const float sc = 1.0f / 8.0f;
    const long BE = (long)Bn * En;
    const long TS = (long)Tn * Sn;

    // -------- tf32 pre-round pass --------
    cvt(state, r_state, (long)ROWS * En);
    cvt(enc,   r_enc,   (long)Sn * Bn * En);
    cvt(sa_wq, r_saq, (long)En * En);  cvt(sa_wk, r_sak, (long)En * En);
    cvt(sa_wv, r_sav, (long)En * En);  cvt(sa_wo, r_sao, (long)En * En);
    cvt(ea_wq, r_eaq, (long)En * En);  cvt(ea_wk, r_eak, (long)En * En);
    cvt(ea_wv, r_eav, (long)En * En);  cvt(ea_wo, r_eao, (long)En * En);
    cvt(fc1_w, r_fc1, (long)FFn * En); cvt(fc2_w, r_fc2, (long)En * FFn);

    // ---------------- self-attention (fused flash, causal) ----------------
    gemm128(r_state, r_saq, sa_bq, nullptr, xq, ROWS, En, En, En,0, En,1,0, En,0, 1, 1.f, 2);
    gemm128(r_state, r_sak, sa_bk, nullptr, xk, ROWS, En, En, En,0, En,1,0, En,0, 1, 1.f, 2);
    gemm128(r_state, r_sav, sa_bv, nullptr, xv, ROWS, En, En, En,0, En,1,0, En,0, 1, 1.f, 2);
    flash_kernel<true><<<dim3(Tn / 128, BH), 256, FL_SMEM>>>(xq, xk, xv, attn, nullptr);
    gemm128(attn, r_sao, sa_bo, nullptr, tmp, ROWS, En, En, En,0, En,1,0, En,0, 1, 1.f, 0);
    add_ln_kernel<<<ROWS, 256>>>(tmp, state, ln1_g, ln1_b, st1, st1r);

    // ---------------- encoder-decoder attention ----------------
    gemm128(st1r,  r_eaq, ea_bq, nullptr, xq, ROWS, En, En, En,0, En,1,0, En,0, 1, 1.f, 2);
    gemm128(r_enc, r_eak, ea_bk, nullptr, xk, ROWS, En, En, En,0, En,1,0, En,0, 1, 1.f, 2);
    gemm128(r_enc, r_eav, ea_bv, nullptr, xv, ROWS, En, En, En,0, En,1,0, En,0, 1, 1.f, 2);
    flash_kernel<false><<<dim3(Tn / 128, BH), 256, FL_SMEM>>>(xq, xk, xv, attn, stats);
    // normalized attention weights straight into d_out
    gemm128(xq, xk, nullptr, stats, out_attn, Tn, Sn, DHn,
            BE,DHn,  BE,1,DHn,  Sn,TS, BH, sc, 3);
    gemm128(attn, r_eao, ea_bo, nullptr, tmp, ROWS, En, En, En,0, En,1,0, En,0, 1, 1.f, 0);
    add_ln_kernel<<<ROWS, 256>>>(tmp, st1, ln2_g, ln2_b, st2, st2r);

    // ---------------- FFN ----------------
    gemm128(st2r, r_fc1, fc1_b, nullptr, ffn, ROWS, FFn, En, En,0, En,1,0, FFn,0, 1, 1.f, 1);
    gemm128(ffn,  r_fc2, fc2_b, nullptr, tmp, ROWS, En, FFn, FFn,0, FFn,1,0, En,0, 1, 1.f, 0);
    add_ln_kernel<<<ROWS, 256>>>(tmp, st2, ln3_g, ln3_b, out_state, nullptr);
}

// round 7
// speedup vs baseline: 3.7663x; 1.0244x over previous
#include <cuda_runtime.h>
#include <math.h>
#include <stdint.h>

// Problem dims
#define Tn 1024
#define Sn 1024
#define Bn 4
#define En 1024
#define Hn 16
#define DHn 64
#define FFn 4096
#define ROWS (Tn*Bn)
#define BH (Bn*Hn)
#define MEG (1024*1024)

// -------- scratch (device globals; no allocation) --------
__device__ float g_xq[ROWS*En];
__device__ float g_xk[ROWS*En];
__device__ float g_xv[ROWS*En];
__device__ float g_attn[ROWS*En];
__device__ float g_tmp[ROWS*En];
__device__ float g_state1[ROWS*En];
__device__ float g_state2[ROWS*En];
__device__ float g_st1r[ROWS*En];
__device__ float g_st2r[ROWS*En];
__device__ float g_ffn[ROWS*FFn];
__device__ float2 g_stats[BH*Tn];
__device__ float g_rw[24*MEG];   // tf32-rounded weights & inputs

// ======================= helpers =======================
__device__ __forceinline__ uint32_t f2tf32(float x) {
    uint32_t r;
    asm("cvt.rna.tf32.f32 %0, %1;" : "=r"(r) : "f"(x));
    return r;
}
__device__ __forceinline__ float roundtf(float x) { return __uint_as_float(f2tf32(x)); }

__device__ __forceinline__ void mma_tf32(float* c, const uint32_t* a, const uint32_t* b) {
    asm volatile(
        "mma.sync.aligned.m16n8k8.row.col.f32.tf32.tf32.f32 "
        "{%0,%1,%2,%3}, {%4,%5,%6,%7}, {%8,%9}, {%0,%1,%2,%3};"
        : "+f"(c[0]), "+f"(c[1]), "+f"(c[2]), "+f"(c[3])
        : "r"(a[0]), "r"(a[1]), "r"(a[2]), "r"(a[3]), "r"(b[0]), "r"(b[1]));
}
__device__ __forceinline__ void cp16(uint32_t dst, const void* src) {
    asm volatile("cp.async.cg.shared.global [%0], [%1], 16;" :: "r"(dst), "l"(src));
}
__device__ __forceinline__ void cp_commit() {
    asm volatile("cp.async.commit_group;" ::: "memory");
}
__device__ __forceinline__ void cp_wait0() {
    asm volatile("cp.async.wait_group 0;" ::: "memory");
}
__device__ __forceinline__ uint32_t smaddr(const void* p) {
    return (uint32_t)__cvta_generic_to_shared(p);
}

// ======================= tgemm2: 64x64 warp tiles, multi-job =======================
// C[m,n] = sum_k A[m,k]*B[n,k] + bias[n]; A:[M,K] lda=K; B:[N,K] ldb=K; ldc=N.
// 128 threads, 4 warps 2x2, warp tile 64x64 (MI=4, NI=8). 2-stage cp.async.
// postop: 0 bias; 1 bias+relu+round; 2 bias+round. grid.z picks job.
struct Job3 { const float* A; const float* B; const float* bias; float* C; };
struct Jobs3 { Job3 j[3]; };

#define G2_STRIDE 36
#define G2_TILE (128*G2_STRIDE)            // floats per operand tile
#define G2_SMEM (4*G2_TILE*4)              // 2 stages x (A+B) bytes = 73728

__global__ __launch_bounds__(128, 2) void tgemm2(
    Jobs3 jobs, int K, int N, int postop)
{
    extern __shared__ float smf[];
    // layout: [stage][A(128x36) | B(128x36)]
    const int tid  = threadIdx.x;
    const int lane = tid & 31;
    const int wid  = tid >> 5;
    const int wm = wid & 1, wn = wid >> 1;
    const int m_base = wm * 64, n_base = wn * 64;
    const int g  = lane >> 2;
    const int tg = lane & 3;

    const Job3 job = jobs.j[blockIdx.z];
    const int bm = blockIdx.y * 128;
    const int bn = blockIdx.x * 128;
    const float* A = job.A + (long)bm * K;
    const float* B = job.B + (long)bn * K;

    const int r0 = tid >> 3, c4 = tid & 7;         // 8 chunks/row, rows r0+16*it
    const float* aPtr = A + (long)r0 * K + c4 * 4;
    const float* bPtr = B + (long)r0 * K + c4 * 4;
    const uint32_t aSm = smaddr(smf + r0 * G2_STRIDE + c4 * 4);
    const uint32_t bSm = smaddr(smf + G2_TILE + r0 * G2_STRIDE + c4 * 4);
    const long rowAdv = 16L * K;

    auto load_slab = [&](int st) {
        const uint32_t so = st * (2 * G2_TILE * 4);
        #pragma unroll
        for (int it = 0; it < 8; it++) {
            cp16(aSm + so + it * (16 * G2_STRIDE * 4), aPtr + it * rowAdv);
            cp16(bSm + so + it * (16 * G2_STRIDE * 4), bPtr + it * rowAdv);
        }
        cp_commit();
    };

    float acc[4][8][4];
    #pragma unroll
    for (int mi = 0; mi < 4; mi++)
        #pragma unroll
        for (int ni = 0; ni < 8; ni++)
            #pragma unroll
            for (int r = 0; r < 4; r++) acc[mi][ni][r] = 0.f;

    const int nslab = K >> 5;
    load_slab(0);
    const float* Abase = smf + (m_base + g) * G2_STRIDE;
    const float* Bbase = smf + G2_TILE + (n_base + g) * G2_STRIDE;

    for (int s = 0; s < nslab; s++) {
        cp_wait0();
        __syncthreads();
        aPtr += 32; bPtr += 32;
        if (s + 1 < nslab) load_slab((s + 1) & 1);

        const int st = s & 1;
        const float* Ab = Abase + st * (2 * G2_TILE);
        const float* Bb = Bbase + st * (2 * G2_TILE);

        #pragma unroll
        for (int kk = 0; kk < 32; kk += 8) {
            uint32_t afr[4][4], bfr[8][2];
            #pragma unroll
            for (int mi = 0; mi < 4; mi++) {
                const float* ap = Ab + mi * (16 * G2_STRIDE) + kk;
                afr[mi][0] = __float_as_uint(ap[tg]);
                afr[mi][1] = __float_as_uint(ap[8 * G2_STRIDE + tg]);
                afr[mi][2] = __float_as_uint(ap[tg + 4]);
                afr[mi][3] = __float_as_uint(ap[8 * G2_STRIDE + tg + 4]);
            }
            #pragma unroll
            for (int ni = 0; ni < 8; ni++) {
                const float* bp = Bb + ni * (8 * G2_STRIDE) + kk;
                bfr[ni][0] = __float_as_uint(bp[tg]);
                bfr[ni][1] = __float_as_uint(bp[tg + 4]);
            }
            #pragma unroll
            for (int mi = 0; mi < 4; mi++)
                #pragma unroll
                for (int ni = 0; ni < 8; ni++)
                    mma_tf32(acc[mi][ni], afr[mi], bfr[ni]);
        }
        __syncthreads();
    }

    // epilogue
    float* C = job.C;
    const float* bias = job.bias;
    #pragma unroll
    for (int mi = 0; mi < 4; mi++) {
        int row0 = bm + m_base + mi * 16 + g;
        #pragma unroll
        for (int ni = 0; ni < 8; ni++) {
            int col = bn + n_base + ni * 8 + tg * 2;
            float b0 = bias[col], b1 = bias[col + 1];
            float v0 = acc[mi][ni][0] + b0;
            float v1 = acc[mi][ni][1] + b1;
            float v2 = acc[mi][ni][2] + b0;
            float v3 = acc[mi][ni][3] + b1;
            if (postop == 1) {
                v0 = roundtf(fmaxf(v0, 0.f)); v1 = roundtf(fmaxf(v1, 0.f));
                v2 = roundtf(fmaxf(v2, 0.f)); v3 = roundtf(fmaxf(v3, 0.f));
            } else if (postop == 2) {
                v0 = roundtf(v0); v1 = roundtf(v1);
                v2 = roundtf(v2); v3 = roundtf(v3);
            }
            *(float2*)&C[(long)row0 * N + col]       = make_float2(v0, v1);
            *(float2*)&C[(long)(row0 + 8) * N + col] = make_float2(v2, v3);
        }
    }
}

// ======================= fused flash attention =======================
#define FL_QS 68
#define FL_KS 68
#define FL_VS 72
#define FL_PS 68
#define FL_SMEM ((128*FL_QS + 2*64*FL_KS + 2*64*FL_VS + 128*FL_PS) * 4)

template<bool CAUSAL>
__global__ __launch_bounds__(256, 1) void flash_kernel(
    const float* __restrict__ Qp, const float* __restrict__ Kp,
    const float* __restrict__ Vp, float* __restrict__ Op,
    float2* __restrict__ stats)
{
    extern __shared__ float fsm[];
    float* Qs = fsm;
    float* Ks = Qs + 128 * FL_QS;
    float* Vs = Ks + 2 * 64 * FL_KS;
    float* Ps = Vs + 2 * 64 * FL_VS;

    const int tid = threadIdx.x;
    const int lane = tid & 31, w = tid >> 5;
    const int g = lane >> 2, tg = lane & 3;
    const int bh = blockIdx.y;
    const int it = CAUSAL ? ((int)gridDim.x - 1 - (int)blockIdx.x) : (int)blockIdx.x;
    const int t0 = it * 128;
    const int nIter = CAUSAL ? 2 * it + 2 : 16;

    const float* Qg = Qp + (long)t0 * 4096 + bh * 64;
    const float* Kg = Kp + bh * 64;
    const float* Vg = Vp + bh * 64;

    auto loadKV = [&](int j, int buf) {
        float* kb = Ks + buf * 64 * FL_KS;
        float* vb = Vs + buf * 64 * FL_VS;
        const long s0 = (long)j * 64;
        #pragma unroll
        for (int i = 0; i < 4; i++) {
            int idx = tid + i * 256;
            int row = idx >> 4, c = idx & 15;
            cp16(smaddr(kb + row * FL_KS + c * 4), Kg + (s0 + row) * 4096 + c * 4);
            cp16(smaddr(vb + row * FL_VS + c * 4), Vg + (s0 + row) * 4096 + c * 4);
        }
    };

    #pragma unroll
    for (int i = 0; i < 8; i++) {
        int idx = tid + i * 256;
        int row = idx >> 4, c = idx & 15;
        cp16(smaddr(Qs + row * FL_QS + c * 4), Qg + (long)row * 4096 + c * 4);
    }
    loadKV(0, 0);
    cp_commit();
    cp_wait0();
    __syncthreads();

    uint32_t qf[8][4];
    {
        const float* qp = Qs + (16 * w + g) * FL_QS;
        #pragma unroll
        for (int kk = 0; kk < 8; kk++) {
            qf[kk][0] = __float_as_uint(qp[kk * 8 + tg]);
            qf[kk][1] = __float_as_uint(qp[8 * FL_QS + kk * 8 + tg]);
            qf[kk][2] = __float_as_uint(qp[kk * 8 + tg + 4]);
            qf[kk][3] = __float_as_uint(qp[8 * FL_QS + kk * 8 + tg + 4]);
        }
    }

    float acc_o[8][4];
    #pragma unroll
    for (int ni = 0; ni < 8; ni++)
        #pragma unroll
        for (int r = 0; r < 4; r++) acc_o[ni][r] = 0.f;
    float m0 = -1e30f, m1 = -1e30f, l0 = 0.f, l1 = 0.f;

    for (int j = 0; j < nIter; j++) {
        const int buf = j & 1;
        if (j + 1 < nIter) { loadKV(j + 1, buf ^ 1); cp_commit(); }

        float s_acc[8][4];
        #pragma unroll
        for (int ni = 0; ni < 8; ni++)
            #pragma unroll
            for (int r = 0; r < 4; r++) s_acc[ni][r] = 0.f;
        const float* kb = Ks + buf * 64 * FL_KS;
        #pragma unroll
        for (int kk = 0; kk < 8; kk++) {
            #pragma unroll
            for (int ni = 0; ni < 8; ni++) {
                const float* bp = kb + (ni * 8 + g) * FL_KS + kk * 8;
                uint32_t bfr[2];
                bfr[0] = __float_as_uint(bp[tg]);
                bfr[1] = __float_as_uint(bp[tg + 4]);
                mma_tf32(s_acc[ni], qf[kk], bfr);
            }
        }

        const int s0 = j * 64;
        const bool need = CAUSAL && (s0 + 63 > t0 + 16 * w);
        const int tr0 = t0 + 16 * w + g, tr1 = tr0 + 8;
        float mx0 = -1e30f, mx1 = -1e30f;
        #pragma unroll
        for (int ni = 0; ni < 8; ni++) {
            float v0 = s_acc[ni][0] * 0.125f;
            float v1 = s_acc[ni][1] * 0.125f;
            float v2 = s_acc[ni][2] * 0.125f;
            float v3 = s_acc[ni][3] * 0.125f;
            if (need) {
                int c0 = s0 + ni * 8 + 2 * tg, c1 = c0 + 1;
                if (c0 > tr0) v0 -= 1e9f;
                if (c1 > tr0) v1 -= 1e9f;
                if (c0 > tr1) v2 -= 1e9f;
                if (c1 > tr1) v3 -= 1e9f;
            }
            s_acc[ni][0] = v0; s_acc[ni][1] = v1;
            s_acc[ni][2] = v2; s_acc[ni][3] = v3;
            mx0 = fmaxf(mx0, fmaxf(v0, v1));
            mx1 = fmaxf(mx1, fmaxf(v2, v3));
        }
        mx0 = fmaxf(mx0, __shfl_xor_sync(0xffffffffu, mx0, 1));
        mx0 = fmaxf(mx0, __shfl_xor_sync(0xffffffffu, mx0, 2));
        mx1 = fmaxf(mx1, __shfl_xor_sync(0xffffffffu, mx1, 1));
        mx1 = fmaxf(mx1, __shfl_xor_sync(0xffffffffu, mx1, 2));
        const float mn0 = fmaxf(m0, mx0), mn1 = fmaxf(m1, mx1);
        const float sc0 = expf(m0 - mn0), sc1 = expf(m1 - mn1);
        m0 = mn0; m1 = mn1;

        float sum0 = 0.f, sum1 = 0.f;
        float* prow0 = Ps + (16 * w + g) * FL_PS;
        float* prow1 = prow0 + 8 * FL_PS;
        #pragma unroll
        for (int ni = 0; ni < 8; ni++) {
            float p0 = expf(s_acc[ni][0] - m0);
            float p1 = expf(s_acc[ni][1] - m0);
            float p2 = expf(s_acc[ni][2] - m1);
            float p3 = expf(s_acc[ni][3] - m1);
            sum0 += p0 + p1; sum1 += p2 + p3;
            *(float2*)&prow0[ni * 8 + 2 * tg] = make_float2(roundtf(p0), roundtf(p1));
            *(float2*)&prow1[ni * 8 + 2 * tg] = make_float2(roundtf(p2), roundtf(p3));
        }
        sum0 += __shfl_xor_sync(0xffffffffu, sum0, 1);
        sum0 += __shfl_xor_sync(0xffffffffu, sum0, 2);
        sum1 += __shfl_xor_sync(0xffffffffu, sum1, 1);
        sum1 += __shfl_xor_sync(0xffffffffu, sum1, 2);
        l0 = l0 * sc0 + sum0;
        l1 = l1 * sc1 + sum1;
        #pragma unroll
        for (int ni = 0; ni < 8; ni++) {
            acc_o[ni][0] *= sc0; acc_o[ni][1] *= sc0;
            acc_o[ni][2] *= sc1; acc_o[ni][3] *= sc1;
        }
        __syncthreads();

        const float* vb = Vs + buf * 64 * FL_VS;
        const float* pp = Ps + (16 * w + g) * FL_PS;
        #pragma unroll
        for (int kk = 0; kk < 8; kk++) {
            uint32_t pf[4];
            pf[0] = __float_as_uint(pp[kk * 8 + tg]);
            pf[1] = __float_as_uint(pp[8 * FL_PS + kk * 8 + tg]);
            pf[2] = __float_as_uint(pp[kk * 8 + tg + 4]);
            pf[3] = __float_as_uint(pp[8 * FL_PS + kk * 8 + tg + 4]);
            #pragma unroll
            for (int ni = 0; ni < 8; ni++) {
                const float* vp = vb + (kk * 8 + tg) * FL_VS + ni * 8 + g;
                uint32_t bfr[2];
                bfr[0] = __float_as_uint(vp[0]);
                bfr[1] = __float_as_uint(vp[4 * FL_VS]);
                mma_tf32(acc_o[ni], pf, bfr);
            }
        }
        if (j + 1 < nIter) cp_wait0();
        __syncthreads();
    }

    const float inv0 = 1.f / l0, inv1 = 1.f / l1;
    const int r0 = t0 + 16 * w + g;
    float* o0 = Op + (long)r0 * 4096 + bh * 64;
    float* o1 = o0 + 8L * 4096;
    #pragma unroll
    for (int ni = 0; ni < 8; ni++) {
        *(float2*)&o0[ni * 8 + 2 * tg] =
            make_float2(roundtf(acc_o[ni][0] * inv0), roundtf(acc_o[ni][1] * inv0));
        *(float2*)&o1[ni * 8 + 2 * tg] =
            make_float2(roundtf(acc_o[ni][2] * inv1), roundtf(acc_o[ni][3] * inv1));
    }
    if (!CAUSAL && tg == 0) {
        stats[bh * Tn + r0]     = make_float2(m0, l0);
        stats[bh * Tn + r0 + 8] = make_float2(m1, l1);
    }
}

// ======================= HMMA tf32 GEMM (EA normalized-weights pass) ============
// postop 3: C = exp(alpha*acc - m_row)/l_row, stats indexed per batch row.
template<int BN, bool KN>
__global__ __launch_bounds__(256, 2) void tgemm(
    const float* __restrict__ A, const float* __restrict__ B,
    const float2* __restrict__ stats, float* __restrict__ C,
    int K,
    long lda_m, long a_bs,
    long ldb_n, long ldb_k, long b_bs,
    long ldc_m, long c_bs,
    float alpha)
{
    constexpr int BM = 128, BK = 32;
    constexpr int WARPS_N = BN / 32;
    constexpr int WARPS_M = 8 / WARPS_N;
    constexpr int MI = (BM / WARPS_M) / 16;
    constexpr int NI = 4;
    constexpr int A_STRIDE = BK + 4;
    constexpr int B_STRIDE = KN ? (BN + 8) : (BK + 4);
    constexpr int B_ROWS   = KN ? BK : BN;
    constexpr int A_TILE = BM * A_STRIDE;
    constexpr int B_TILE = B_ROWS * B_STRIDE;
    constexpr int BCPT = (BK * BN / 4) / 256;

    extern __shared__ float smf[];
    float* As = smf;
    float* Bs = smf + 2 * A_TILE;

    const int tid  = threadIdx.x;
    const int lane = tid & 31;
    const int wid  = tid >> 5;
    const int wm = wid % WARPS_M, wn = wid / WARPS_M;
    const int m_base = wm * (BM / WARPS_M);
    const int n_base = wn * 32;
    const int g  = lane >> 2;
    const int tg = lane & 3;

    const int bm = blockIdx.y * BM;
    const int bn = blockIdx.x * BN;
    A += (long)blockIdx.z * a_bs + (long)bm * lda_m;
    B += (long)blockIdx.z * b_bs + (long)bn * ldb_n;
    C += (long)blockIdx.z * c_bs;

    const float* aSrc[4];
    uint32_t aDst[4];
    #pragma unroll
    for (int i = 0; i < 4; i++) {
        int idx = tid + i * 256;
        int row = idx >> 3, c4 = idx & 7;
        aSrc[i] = A + (long)row * lda_m + c4 * 4;
        aDst[i] = smaddr(As + row * A_STRIDE + c4 * 4);
    }
    const float* bSrc[BCPT];
    uint32_t bDst[BCPT];
    #pragma unroll
    for (int i = 0; i < BCPT; i++) {
        int idx = tid + i * 256;
        if (KN) {
            int row = idx / (BN / 4), c4 = idx % (BN / 4);
            bSrc[i] = B + (long)row * ldb_k + c4 * 4;
            bDst[i] = smaddr(Bs + row * B_STRIDE + c4 * 4);
        } else {
            int row = idx >> 3, c4 = idx & 7;
            bSrc[i] = B + (long)row * ldb_n + c4 * 4;
            bDst[i] = smaddr(Bs + row * B_STRIDE + c4 * 4);
        }
    }
    const long bAdv = KN ? (long)BK * ldb_k : (long)BK;

    auto load_slab = [&](int st) {
        uint32_t ao = st * (A_TILE * 4);
        uint32_t bo = st * (B_TILE * 4);
        #pragma unroll
        for (int i = 0; i < 4; i++) { cp16(aDst[i] + ao, aSrc[i]); aSrc[i] += BK; }
        #pragma unroll
        for (int i = 0; i < BCPT; i++) { cp16(bDst[i] + bo, bSrc[i]); bSrc[i] += bAdv; }
        cp_commit();
    };

    float acc[MI][NI][4];
    #pragma unroll
    for (int mi = 0; mi < MI; mi++)
        #pragma unroll
        for (int ni = 0; ni < NI; ni++)
            #pragma unroll
            for (int r = 0; r < 4; r++) acc[mi][ni][r] = 0.f;

    const int nslab = K / BK;
    load_slab(0);

    for (int s = 0; s < nslab; s++) {
        cp_wait0();
        __syncthreads();
        if (s + 1 < nslab) load_slab((s + 1) & 1);

        const int st = s & 1;
        const float* Ab = As + st * A_TILE;
        const float* Bb = Bs + st * B_TILE;

        #pragma unroll
        for (int kk = 0; kk < BK; kk += 8) {
            uint32_t afr[MI][4], bfr[NI][2];
            #pragma unroll
            for (int mi = 0; mi < MI; mi++) {
                const float* ap = Ab + (m_base + mi * 16 + g) * A_STRIDE + kk;
                afr[mi][0] = __float_as_uint(ap[tg]);
                afr[mi][1] = __float_as_uint(ap[8 * A_STRIDE + tg]);
                afr[mi][2] = __float_as_uint(ap[tg + 4]);
                afr[mi][3] = __float_as_uint(ap[8 * A_STRIDE + tg + 4]);
            }
            #pragma unroll
            for (int ni = 0; ni < NI; ni++) {
                if (KN) {
                    const float* bp = Bb + (kk + tg) * B_STRIDE + n_base + ni * 8 + g;
                    bfr[ni][0] = __float_as_uint(bp[0]);
                    bfr[ni][1] = __float_as_uint(bp[4 * B_STRIDE]);
                } else {
                    const float* bp = Bb + (n_base + ni * 8 + g) * B_STRIDE + kk;
                    bfr[ni][0] = __float_as_uint(bp[tg]);
                    bfr[ni][1] = __float_as_uint(bp[tg + 4]);
                }
            }
            #pragma unroll
            for (int mi = 0; mi < MI; mi++)
                #pragma unroll
                for (int ni = 0; ni < NI; ni++)
                    mma_tf32(acc[mi][ni], afr[mi], bfr[ni]);
        }
        __syncthreads();
    }

    #pragma unroll
    for (int mi = 0; mi < MI; mi++) {
        int row0 = bm + m_base + mi * 16 + g;
        float2 ml0 = stats[(long)blockIdx.z * Tn + row0];
        float2 ml1 = stats[(long)blockIdx.z * Tn + row0 + 8];
        float i0 = 1.f / ml0.y, i1 = 1.f / ml1.y;
        #pragma unroll
        for (int ni = 0; ni < NI; ni++) {
            int col = bn + n_base + ni * 8 + tg * 2;
            float v0 = expf(acc[mi][ni][0] * alpha - ml0.x) * i0;
            float v1 = expf(acc[mi][ni][1] * alpha - ml0.x) * i0;
            float v2 = expf(acc[mi][ni][2] * alpha - ml1.x) * i1;
            float v3 = expf(acc[mi][ni][3] * alpha - ml1.x) * i1;
            *(float2*)&C[(long)row0 * ldc_m + col]       = make_float2(v0, v1);
            *(float2*)&C[(long)(row0 + 8) * ldc_m + col] = make_float2(v2, v3);
        }
    }
}

// ======================= out = LayerNorm(x+res)*g+b ; optional tf32-rounded copy
__global__ __launch_bounds__(256) void add_ln_kernel(
    const float* __restrict__ x, const float* __restrict__ res,
    const float* __restrict__ g, const float* __restrict__ b,
    float* __restrict__ out, float* __restrict__ out_r)
{
    const long row = (long)blockIdx.x * En;
    const int tid = threadIdx.x;
    float v[4]; float s = 0.f, s2 = 0.f;
    #pragma unroll
    for (int j = 0; j < 4; j++) {
        int i = tid + j * 256;
        float val = x[row + i] + res[row + i];
        v[j] = val; s += val; s2 += val * val;
    }
    __shared__ float sh1[8], sh2[8];
    #pragma unroll
    for (int o = 16; o; o >>= 1) {
        s  += __shfl_xor_sync(0xffffffffu, s, o);
        s2 += __shfl_xor_sync(0xffffffffu, s2, o);
    }
    if ((tid & 31) == 0) { sh1[tid >> 5] = s; sh2[tid >> 5] = s2; }
    __syncthreads();
    float ts = 0.f, ts2 = 0.f;
    #pragma unroll
    for (int w = 0; w < 8; w++) { ts += sh1[w]; ts2 += sh2[w]; }
    const float mu  = ts * (1.f / En);
    const float var = ts2 * (1.f / En) - mu * mu;
    const float inv = rsqrtf(var + 1e-5f);
    #pragma unroll
    for (int j = 0; j < 4; j++) {
        int i = tid + j * 256;
        float o = (v[j] - mu) * inv * g[i] + b[i];
        out[row + i] = o;
        if (out_r) out_r[row + i] = roundtf(o);
    }
}

// ======================= fused tf32 rounding pass =======================
#define NCVT 12
struct CvtJobs {
    const float4* src[NCVT];
    float4* dst[NCVT];
    int cum[NCVT + 1];
};
__global__ __launch_bounds__(256) void cvt_multi(CvtJobs cj, int total4)
{
    for (int i = blockIdx.x * 256 + threadIdx.x; i < total4; i += gridDim.x * 256) {
        int job = 0;
        #pragma unroll
        for (int t = 0; t < NCVT - 1; t++) if (i >= cj.cum[t + 1]) job = t + 1;
        int off = i - cj.cum[job];
        float4 v = cj.src[job][off];
        v.x = roundtf(v.x); v.y = roundtf(v.y);
        v.z = roundtf(v.z); v.w = roundtf(v.w);
        cj.dst[job][off] = v;
    }
}

// ======================= host-side =======================
#define SMEM128 ((2*128*36 + 2*128*36) * 4)

static inline void g2(Jobs3 jobs, int M, int N, int K, int njobs, int postop)
{
    dim3 grid(N / 128, M / 128, njobs);
    tgemm2<<<grid, 128, G2_SMEM>>>(jobs, K, N, postop);
}

extern "C" void kernel_launch(void* const* d_in, const int* in_sizes, int n_in,
                              void* d_out, int out_size)
{
    static bool attr_done = false;
    if (!attr_done) {
        cudaFuncSetAttribute((const void*)tgemm2,
                             cudaFuncAttributeMaxDynamicSharedMemorySize, G2_SMEM);
        cudaFuncSetAttribute((const void*)tgemm<128, false>,
                             cudaFuncAttributeMaxDynamicSharedMemorySize, SMEM128);
        cudaFuncSetAttribute((const void*)flash_kernel<true>,
                             cudaFuncAttributeMaxDynamicSharedMemorySize, FL_SMEM);
        cudaFuncSetAttribute((const void*)flash_kernel<false>,
                             cudaFuncAttributeMaxDynamicSharedMemorySize, FL_SMEM);
        attr_done = true;
    }

    const float* state = (const float*)d_in[0];
    const float* enc   = (const float*)d_in[1];
    const float* sa_wq = (const float*)d_in[3];  const float* sa_bq = (const float*)d_in[4];
    const float* sa_wk = (const float*)d_in[5];  const float* sa_bk = (const float*)d_in[6];
    const float* sa_wv = (const float*)d_in[7];  const float* sa_bv = (const float*)d_in[8];
    const float* sa_wo = (const float*)d_in[9];  const float* sa_bo = (const float*)d_in[10];
    const float* ea_wq = (const float*)d_in[11]; const float* ea_bq = (const float*)d_in[12];
    const float* ea_wk = (const float*)d_in[13]; const float* ea_bk = (const float*)d_in[14];
    const float* ea_wv = (const float*)d_in[15]; const float* ea_bv = (const float*)d_in[16];
    const float* ea_wo = (const float*)d_in[17]; const float* ea_bo = (const float*)d_in[18];
    const float* fc1_w = (const float*)d_in[19]; const float* fc1_b = (const float*)d_in[20];
    const float* fc2_w = (const float*)d_in[21]; const float* fc2_b = (const float*)d_in[22];
    const float* ln1_g = (const float*)d_in[23]; const float* ln1_b = (const float*)d_in[24];
    const float* ln2_g = (const float*)d_in[25]; const float* ln2_b = (const float*)d_in[26];
    const float* ln3_g = (const float*)d_in[27]; const float* ln3_b = (const float*)d_in[28];

    float *xq, *xk, *xv, *attn, *tmp, *st1, *st2, *st1r, *st2r, *ffn, *rw;
    float2* stats;
    cudaGetSymbolAddress((void**)&xq,    g_xq);
    cudaGetSymbolAddress((void**)&xk,    g_xk);
    cudaGetSymbolAddress((void**)&xv,    g_xv);
    cudaGetSymbolAddress((void**)&attn,  g_attn);
    cudaGetSymbolAddress((void**)&tmp,   g_tmp);
    cudaGetSymbolAddress((void**)&st1,   g_state1);
    cudaGetSymbolAddress((void**)&st2,   g_state2);
    cudaGetSymbolAddress((void**)&st1r,  g_st1r);
    cudaGetSymbolAddress((void**)&st2r,  g_st2r);
    cudaGetSymbolAddress((void**)&ffn,   g_ffn);
    cudaGetSymbolAddress((void**)&stats, g_stats);
    cudaGetSymbolAddress((void**)&rw,    g_rw);

    float* r_state = rw + 0L  * MEG;
    float* r_enc   = rw + 4L  * MEG;
    float* r_saq   = rw + 8L  * MEG;
    float* r_sak   = rw + 9L  * MEG;
    float* r_sav   = rw + 10L * MEG;
    float* r_sao   = rw + 11L * MEG;
    float* r_eaq   = rw + 12L * MEG;
    float* r_eak   = rw + 13L * MEG;
    float* r_eav   = rw + 14L * MEG;
    float* r_eao   = rw + 15L * MEG;
    float* r_fc1   = rw + 16L * MEG;
    float* r_fc2   = rw + 20L * MEG;

    float* out_state = (float*)d_out;
    float* out_attn  = (float*)d_out + (long)Tn * Bn * En;

    const float sc = 1.0f / 8.0f;
    const long BE = (long)Bn * En;
    const long TS = (long)Tn * Sn;

    // -------- fused tf32 pre-round pass --------
    {
        CvtJobs cj;
        const float* srcs[NCVT] = {state, enc, sa_wq, sa_wk, sa_wv, sa_wo,
                                   ea_wq, ea_wk, ea_wv, ea_wo, fc1_w, fc2_w};
        float* dsts[NCVT] = {r_state, r_enc, r_saq, r_sak, r_sav, r_sao,
                             r_eaq, r_eak, r_eav, r_eao, r_fc1, r_fc2};
        const int n4s[NCVT] = {MEG, MEG, MEG/4, MEG/4, MEG/4, MEG/4,
                               MEG/4, MEG/4, MEG/4, MEG/4, MEG, MEG};
        int c = 0;
        for (int i = 0; i < NCVT; i++) {
            cj.src[i] = (const float4*)srcs[i];
            cj.dst[i] = (float4*)dsts[i];
            cj.cum[i] = c;
            c += n4s[i];
        }
        cj.cum[NCVT] = c;
        cvt_multi<<<1024, 256>>>(cj, c);
    }

    // ---------------- self-attention (fused flash, causal) ----------------
    {
        Jobs3 j = {{{r_state, r_saq, sa_bq, xq},
                    {r_state, r_sak, sa_bk, xk},
                    {r_state, r_sav, sa_bv, xv}}};
        g2(j, ROWS, En, En, 3, 2);
    }
    flash_kernel<true><<<dim3(Tn / 128, BH), 256, FL_SMEM>>>(xq, xk, xv, attn, nullptr);
    {
        Jobs3 j = {{{attn, r_sao, sa_bo, tmp}, {}, {}}};
        g2(j, ROWS, En, En, 1, 0);
    }
    add_ln_kernel<<<ROWS, 256>>>(tmp, state, ln1_g, ln1_b, st1, st1r);

    // ---------------- encoder-decoder attention ----------------
    {
        Jobs3 j = {{{st1r,  r_eaq, ea_bq, xq},
                    {r_enc, r_eak, ea_bk, xk},
                    {r_enc, r_eav, ea_bv, xv}}};
        g2(j, ROWS, En, En, 3, 2);
    }
    flash_kernel<false><<<dim3(Tn / 128, BH), 256, FL_SMEM>>>(xq, xk, xv, attn, stats);
    // normalized attention weights straight into d_out
    {
        dim3 grid(Sn / 128, Tn / 128, BH);
        tgemm<128, false><<<grid, 256, SMEM128>>>(xq, xk, stats, out_attn, DHn,
                                                  BE, DHn, BE, 1, DHn, Sn, TS, sc);
    }
    {
        Jobs3 j = {{{attn, r_eao, ea_bo, tmp}, {}, {}}};
        g2(j, ROWS, En, En, 1, 0);
    }
    add_ln_kernel<<<ROWS, 256>>>(tmp, st1, ln2_g, ln2_b, st2, st2r);

    // ---------------- FFN ----------------
    {
        Jobs3 j = {{{st2r, r_fc1, fc1_b, ffn}, {}, {}}};
        g2(j, ROWS, FFn, En, 1, 1);
    }
    {
        Jobs3 j = {{{ffn, r_fc2, fc2_b, tmp}, {}, {}}};
        g2(j, ROWS, En, FFn, 1, 0);
    }
    add_ln_kernel<<<ROWS, 256>>>(tmp, st2, ln3_g, ln3_b, out_state, nullptr);
}

// round 8
// speedup vs baseline: 5.5419x; 1.4715x over previous
#include <cuda_runtime.h>
#include <cuda_fp16.h>
#include <math.h>
#include <stdint.h>

// Problem dims
#define Tn 1024
#define Sn 1024
#define Bn 4
#define En 1024
#define Hn 16
#define DHn 64
#define FFn 4096
#define ROWS (Tn*Bn)
#define BH (Bn*Hn)
#define MEG (1024*1024)

// -------- scratch (device globals; no allocation) --------
__device__ float g_xq[ROWS*En];
__device__ float g_xk[ROWS*En];
__device__ float g_xv[ROWS*En];
__device__ float g_attn[ROWS*En];      // used as __half (cap 2x)
__device__ float g_tmp[ROWS*En];
__device__ float g_state1[ROWS*En];
__device__ float g_state2[ROWS*En];
__device__ float g_st1r[ROWS*En];      // used as __half
__device__ float g_st2r[ROWS*En];      // used as __half
__device__ float g_ffn[ROWS*FFn];      // used as __half
__device__ float2 g_stats[BH*Tn];
__device__ float g_rw[24*MEG];         // used as __half pool (48M halfs)

// ======================= helpers =======================
__device__ __forceinline__ uint32_t f2tf32(float x) {
    uint32_t r;
    asm("cvt.rna.tf32.f32 %0, %1;" : "=r"(r) : "f"(x));
    return r;
}
__device__ __forceinline__ float roundtf(float x) { return __uint_as_float(f2tf32(x)); }
__device__ __forceinline__ float round16(float x) { return __half2float(__float2half_rn(x)); }

__device__ __forceinline__ void mma_tf32(float* c, const uint32_t* a, const uint32_t* b) {
    asm volatile(
        "mma.sync.aligned.m16n8k8.row.col.f32.tf32.tf32.f32 "
        "{%0,%1,%2,%3}, {%4,%5,%6,%7}, {%8,%9}, {%0,%1,%2,%3};"
        : "+f"(c[0]), "+f"(c[1]), "+f"(c[2]), "+f"(c[3])
        : "r"(a[0]), "r"(a[1]), "r"(a[2]), "r"(a[3]), "r"(b[0]), "r"(b[1]));
}
__device__ __forceinline__ void mma_f16(float* c, const uint32_t* a, const uint32_t* b) {
    asm volatile(
        "mma.sync.aligned.m16n8k16.row.col.f32.f16.f16.f32 "
        "{%0,%1,%2,%3}, {%4,%5,%6,%7}, {%8,%9}, {%0,%1,%2,%3};"
        : "+f"(c[0]), "+f"(c[1]), "+f"(c[2]), "+f"(c[3])
        : "r"(a[0]), "r"(a[1]), "r"(a[2]), "r"(a[3]), "r"(b[0]), "r"(b[1]));
}
__device__ __forceinline__ void cp16(uint32_t dst, const void* src) {
    asm volatile("cp.async.cg.shared.global [%0], [%1], 16;" :: "r"(dst), "l"(src));
}
__device__ __forceinline__ void cp_commit() {
    asm volatile("cp.async.commit_group;" ::: "memory");
}
__device__ __forceinline__ void cp_wait0() {
    asm volatile("cp.async.wait_group 0;" ::: "memory");
}
__device__ __forceinline__ uint32_t smaddr(const void* p) {
    return (uint32_t)__cvta_generic_to_shared(p);
}

// ======================= hgemm2: fp16 MMA, 64x64 warp tiles, multi-job ============
// C[m,n] = sum_k A[m,k]*B[n,k] + bias[n]; A:[M,K] half lda=K; B:[N,K] half ldb=K.
// 128 threads, 4 warps 2x2, warp tile 64x64 (MI=4, NI=8). K-slab 64 halfs, 2 stages.
// postop: 0 = fp32 out; 1 = relu -> half out; 2 = fp32 out rounded to fp16 precision.
struct JobH { const __half* A; const __half* B; const float* bias; void* C; };
struct JobsH { JobH j[3]; };

#define H2_WS 36                       // words per row (64 halfs + 8 halfs pad)
#define H2_TILEW (128*H2_WS)           // words per operand tile
#define H2_SMEM (4*H2_TILEW*4)         // 2 stages x (A+B) bytes = 73728

__global__ __launch_bounds__(128, 2) void hgemm2(
    JobsH jobs, int K, int N, int postop)
{
    extern __shared__ uint32_t smw[];
    const int tid  = threadIdx.x;
    const int lane = tid & 31;
    const int wid  = tid >> 5;
    const int wm = wid & 1, wn = wid >> 1;
    const int m_base = wm * 64, n_base = wn * 64;
    const int g  = lane >> 2;
    const int tg = lane & 3;

    const JobH job = jobs.j[blockIdx.z];
    const int bm = blockIdx.y * 128;
    const int bn = blockIdx.x * 128;
    const __half* A = job.A + (long)bm * K;
    const __half* B = job.B + (long)bn * K;

    const int r0 = tid >> 3, c8 = tid & 7;     // 8 chunks of 8 halfs per 64-half row
    const __half* aPtr = A + (long)r0 * K + c8 * 8;
    const __half* bPtr = B + (long)r0 * K + c8 * 8;
    const uint32_t aSm = smaddr(smw + r0 * H2_WS + c8 * 4);
    const uint32_t bSm = smaddr(smw + H2_TILEW + r0 * H2_WS + c8 * 4);
    const long rowAdv = 16L * K;

    auto load_slab = [&](int st) {
        const uint32_t so = st * (2 * H2_TILEW * 4);
        #pragma unroll
        for (int it = 0; it < 8; it++) {
            cp16(aSm + so + it * (16 * H2_WS * 4), aPtr + it * rowAdv);
            cp16(bSm + so + it * (16 * H2_WS * 4), bPtr + it * rowAdv);
        }
        cp_commit();
    };

    float acc[4][8][4];
    #pragma unroll
    for (int mi = 0; mi < 4; mi++)
        #pragma unroll
        for (int ni = 0; ni < 8; ni++)
            #pragma unroll
            for (int r = 0; r < 4; r++) acc[mi][ni][r] = 0.f;

    const int nslab = K >> 6;
    load_slab(0);
    const uint32_t* Abase = smw + (m_base + g) * H2_WS + tg;
    const uint32_t* Bbase = smw + H2_TILEW + (n_base + g) * H2_WS + tg;

    for (int s = 0; s < nslab; s++) {
        cp_wait0();
        __syncthreads();
        aPtr += 64; bPtr += 64;
        if (s + 1 < nslab) load_slab((s + 1) & 1);

        const int st = s & 1;
        const uint32_t* Ab = Abase + st * (2 * H2_TILEW);
        const uint32_t* Bb = Bbase + st * (2 * H2_TILEW);

        #pragma unroll
        for (int kw = 0; kw < 32; kw += 8) {   // word offset per k16 step
            uint32_t afr[4][4], bfr[8][2];
            #pragma unroll
            for (int mi = 0; mi < 4; mi++) {
                const uint32_t* ap = Ab + mi * (16 * H2_WS) + kw;
                afr[mi][0] = ap[0];
                afr[mi][1] = ap[8 * H2_WS];
                afr[mi][2] = ap[4];
                afr[mi][3] = ap[8 * H2_WS + 4];
            }
            #pragma unroll
            for (int ni = 0; ni < 8; ni++) {
                const uint32_t* bp = Bb + ni * (8 * H2_WS) + kw;
                bfr[ni][0] = bp[0];
                bfr[ni][1] = bp[4];
            }
            #pragma unroll
            for (int mi = 0; mi < 4; mi++)
                #pragma unroll
                for (int ni = 0; ni < 8; ni++)
                    mma_f16(acc[mi][ni], afr[mi], bfr[ni]);
        }
        __syncthreads();
    }

    // epilogue
    const float* bias = job.bias;
    #pragma unroll
    for (int mi = 0; mi < 4; mi++) {
        int row0 = bm + m_base + mi * 16 + g;
        #pragma unroll
        for (int ni = 0; ni < 8; ni++) {
            int col = bn + n_base + ni * 8 + tg * 2;
            float b0 = bias[col], b1 = bias[col + 1];
            float v0 = acc[mi][ni][0] + b0;
            float v1 = acc[mi][ni][1] + b1;
            float v2 = acc[mi][ni][2] + b0;
            float v3 = acc[mi][ni][3] + b1;
            if (postop == 1) {                 // relu -> half output
                __half* C = (__half*)job.C;
                __half2 h0 = __floats2half2_rn(fmaxf(v0, 0.f), fmaxf(v1, 0.f));
                __half2 h1 = __floats2half2_rn(fmaxf(v2, 0.f), fmaxf(v3, 0.f));
                *(__half2*)&C[(long)row0 * N + col]       = h0;
                *(__half2*)&C[(long)(row0 + 8) * N + col] = h1;
            } else {
                float* C = (float*)job.C;
                if (postop == 2) {
                    v0 = round16(v0); v1 = round16(v1);
                    v2 = round16(v2); v3 = round16(v3);
                }
                *(float2*)&C[(long)row0 * N + col]       = make_float2(v0, v1);
                *(float2*)&C[(long)(row0 + 8) * N + col] = make_float2(v2, v3);
            }
        }
    }
}

// ======================= fused flash attention (tf32 internals, half O) ==========
#define FL_QS 68
#define FL_KS 68
#define FL_VS 72
#define FL_PS 68
#define FL_SMEM ((128*FL_QS + 2*64*FL_KS + 2*64*FL_VS + 128*FL_PS) * 4)

template<bool CAUSAL>
__global__ __launch_bounds__(256, 1) void flash_kernel(
    const float* __restrict__ Qp, const float* __restrict__ Kp,
    const float* __restrict__ Vp, __half* __restrict__ Op,
    float2* __restrict__ stats)
{
    extern __shared__ float fsm[];
    float* Qs = fsm;
    float* Ks = Qs + 128 * FL_QS;
    float* Vs = Ks + 2 * 64 * FL_KS;
    float* Ps = Vs + 2 * 64 * FL_VS;

    const int tid = threadIdx.x;
    const int lane = tid & 31, w = tid >> 5;
    const int g = lane >> 2, tg = lane & 3;
    const int bh = blockIdx.y;
    const int it = CAUSAL ? ((int)gridDim.x - 1 - (int)blockIdx.x) : (int)blockIdx.x;
    const int t0 = it * 128;
    const int nIter = CAUSAL ? 2 * it + 2 : 16;

    const float* Qg = Qp + (long)t0 * 4096 + bh * 64;
    const float* Kg = Kp + bh * 64;
    const float* Vg = Vp + bh * 64;

    auto loadKV = [&](int j, int buf) {
        float* kb = Ks + buf * 64 * FL_KS;
        float* vb = Vs + buf * 64 * FL_VS;
        const long s0 = (long)j * 64;
        #pragma unroll
        for (int i = 0; i < 4; i++) {
            int idx = tid + i * 256;
            int row = idx >> 4, c = idx & 15;
            cp16(smaddr(kb + row * FL_KS + c * 4), Kg + (s0 + row) * 4096 + c * 4);
            cp16(smaddr(vb + row * FL_VS + c * 4), Vg + (s0 + row) * 4096 + c * 4);
        }
    };

    #pragma unroll
    for (int i = 0; i < 8; i++) {
        int idx = tid + i * 256;
        int row = idx >> 4, c = idx & 15;
        cp16(smaddr(Qs + row * FL_QS + c * 4), Qg + (long)row * 4096 + c * 4);
    }
    loadKV(0, 0);
    cp_commit();
    cp_wait0();
    __syncthreads();

    uint32_t qf[8][4];
    {
        const float* qp = Qs + (16 * w + g) * FL_QS;
        #pragma unroll
        for (int kk = 0; kk < 8; kk++) {
            qf[kk][0] = __float_as_uint(qp[kk * 8 + tg]);
            qf[kk][1] = __float_as_uint(qp[8 * FL_QS + kk * 8 + tg]);
            qf[kk][2] = __float_as_uint(qp[kk * 8 + tg + 4]);
            qf[kk][3] = __float_as_uint(qp[8 * FL_QS + kk * 8 + tg + 4]);
        }
    }

    float acc_o[8][4];
    #pragma unroll
    for (int ni = 0; ni < 8; ni++)
        #pragma unroll
        for (int r = 0; r < 4; r++) acc_o[ni][r] = 0.f;
    float m0 = -1e30f, m1 = -1e30f, l0 = 0.f, l1 = 0.f;

    for (int j = 0; j < nIter; j++) {
        const int buf = j & 1;
        if (j + 1 < nIter) { loadKV(j + 1, buf ^ 1); cp_commit(); }

        float s_acc[8][4];
        #pragma unroll
        for (int ni = 0; ni < 8; ni++)
            #pragma unroll
            for (int r = 0; r < 4; r++) s_acc[ni][r] = 0.f;
        const float* kb = Ks + buf * 64 * FL_KS;
        #pragma unroll
        for (int kk = 0; kk < 8; kk++) {
            #pragma unroll
            for (int ni = 0; ni < 8; ni++) {
                const float* bp = kb + (ni * 8 + g) * FL_KS + kk * 8;
                uint32_t bfr[2];
                bfr[0] = __float_as_uint(bp[tg]);
                bfr[1] = __float_as_uint(bp[tg + 4]);
                mma_tf32(s_acc[ni], qf[kk], bfr);
            }
        }

        const int s0 = j * 64;
        const bool need = CAUSAL && (s0 + 63 > t0 + 16 * w);
        const int tr0 = t0 + 16 * w + g, tr1 = tr0 + 8;
        float mx0 = -1e30f, mx1 = -1e30f;
        #pragma unroll
        for (int ni = 0; ni < 8; ni++) {
            float v0 = s_acc[ni][0] * 0.125f;
            float v1 = s_acc[ni][1] * 0.125f;
            float v2 = s_acc[ni][2] * 0.125f;
            float v3 = s_acc[ni][3] * 0.125f;
            if (need) {
                int c0 = s0 + ni * 8 + 2 * tg, c1 = c0 + 1;
                if (c0 > tr0) v0 -= 1e9f;
                if (c1 > tr0) v1 -= 1e9f;
                if (c0 > tr1) v2 -= 1e9f;
                if (c1 > tr1) v3 -= 1e9f;
            }
            s_acc[ni][0] = v0; s_acc[ni][1] = v1;
            s_acc[ni][2] = v2; s_acc[ni][3] = v3;
            mx0 = fmaxf(mx0, fmaxf(v0, v1));
            mx1 = fmaxf(mx1, fmaxf(v2, v3));
        }
        mx0 = fmaxf(mx0, __shfl_xor_sync(0xffffffffu, mx0, 1));
        mx0 = fmaxf(mx0, __shfl_xor_sync(0xffffffffu, mx0, 2));
        mx1 = fmaxf(mx1, __shfl_xor_sync(0xffffffffu, mx1, 1));
        mx1 = fmaxf(mx1, __shfl_xor_sync(0xffffffffu, mx1, 2));
        const float mn0 = fmaxf(m0, mx0), mn1 = fmaxf(m1, mx1);
        const float sc0 = expf(m0 - mn0), sc1 = expf(m1 - mn1);
        m0 = mn0; m1 = mn1;

        float sum0 = 0.f, sum1 = 0.f;
        float* prow0 = Ps + (16 * w + g) * FL_PS;
        float* prow1 = prow0 + 8 * FL_PS;
        #pragma unroll
        for (int ni = 0; ni < 8; ni++) {
            float p0 = expf(s_acc[ni][0] - m0);
            float p1 = expf(s_acc[ni][1] - m0);
            float p2 = expf(s_acc[ni][2] - m1);
            float p3 = expf(s_acc[ni][3] - m1);
            sum0 += p0 + p1; sum1 += p2 + p3;
            *(float2*)&prow0[ni * 8 + 2 * tg] = make_float2(roundtf(p0), roundtf(p1));
            *(float2*)&prow1[ni * 8 + 2 * tg] = make_float2(roundtf(p2), roundtf(p3));
        }
        sum0 += __shfl_xor_sync(0xffffffffu, sum0, 1);
        sum0 += __shfl_xor_sync(0xffffffffu, sum0, 2);
        sum1 += __shfl_xor_sync(0xffffffffu, sum1, 1);
        sum1 += __shfl_xor_sync(0xffffffffu, sum1, 2);
        l0 = l0 * sc0 + sum0;
        l1 = l1 * sc1 + sum1;
        #pragma unroll
        for (int ni = 0; ni < 8; ni++) {
            acc_o[ni][0] *= sc0; acc_o[ni][1] *= sc0;
            acc_o[ni][2] *= sc1; acc_o[ni][3] *= sc1;
        }
        __syncthreads();

        const float* vb = Vs + buf * 64 * FL_VS;
        const float* pp = Ps + (16 * w + g) * FL_PS;
        #pragma unroll
        for (int kk = 0; kk < 8; kk++) {
            uint32_t pf[4];
            pf[0] = __float_as_uint(pp[kk * 8 + tg]);
            pf[1] = __float_as_uint(pp[8 * FL_PS + kk * 8 + tg]);
            pf[2] = __float_as_uint(pp[kk * 8 + tg + 4]);
            pf[3] = __float_as_uint(pp[8 * FL_PS + kk * 8 + tg + 4]);
            #pragma unroll
            for (int ni = 0; ni < 8; ni++) {
                const float* vp = vb + (kk * 8 + tg) * FL_VS + ni * 8 + g;
                uint32_t bfr[2];
                bfr[0] = __float_as_uint(vp[0]);
                bfr[1] = __float_as_uint(vp[4 * FL_VS]);
                mma_tf32(acc_o[ni], pf, bfr);
            }
        }
        if (j + 1 < nIter) cp_wait0();
        __syncthreads();
    }

    const float inv0 = 1.f / l0, inv1 = 1.f / l1;
    const int r0 = t0 + 16 * w + g;
    __half* o0 = Op + (long)r0 * 4096 + bh * 64;
    __half* o1 = o0 + 8L * 4096;
    #pragma unroll
    for (int ni = 0; ni < 8; ni++) {
        *(__half2*)&o0[ni * 8 + 2 * tg] =
            __floats2half2_rn(acc_o[ni][0] * inv0, acc_o[ni][1] * inv0);
        *(__half2*)&o1[ni * 8 + 2 * tg] =
            __floats2half2_rn(acc_o[ni][2] * inv1, acc_o[ni][3] * inv1);
    }
    if (!CAUSAL && tg == 0) {
        stats[bh * Tn + r0]     = make_float2(m0, l0);
        stats[bh * Tn + r0 + 8] = make_float2(m1, l1);
    }
}

// ======================= HMMA tf32 GEMM (EA normalized-weights pass) ============
template<int BN, bool KN>
__global__ __launch_bounds__(256, 2) void tgemm(
    const float* __restrict__ A, const float* __restrict__ B,
    const float2* __restrict__ stats, float* __restrict__ C,
    int K,
    long lda_m, long a_bs,
    long ldb_n, long ldb_k, long b_bs,
    long ldc_m, long c_bs,
    float alpha)
{
    constexpr int BM = 128, BK = 32;
    constexpr int WARPS_N = BN / 32;
    constexpr int WARPS_M = 8 / WARPS_N;
    constexpr int MI = (BM / WARPS_M) / 16;
    constexpr int NI = 4;
    constexpr int A_STRIDE = BK + 4;
    constexpr int B_STRIDE = KN ? (BN + 8) : (BK + 4);
    constexpr int B_ROWS   = KN ? BK : BN;
    constexpr int A_TILE = BM * A_STRIDE;
    constexpr int B_TILE = B_ROWS * B_STRIDE;
    constexpr int BCPT = (BK * BN / 4) / 256;

    extern __shared__ float smf[];
    float* As = smf;
    float* Bs = smf + 2 * A_TILE;

    const int tid  = threadIdx.x;
    const int lane = tid & 31;
    const int wid  = tid >> 5;
    const int wm = wid % WARPS_M, wn = wid / WARPS_M;
    const int m_base = wm * (BM / WARPS_M);
    const int n_base = wn * 32;
    const int g  = lane >> 2;
    const int tg = lane & 3;

    const int bm = blockIdx.y * BM;
    const int bn = blockIdx.x * BN;
    A += (long)blockIdx.z * a_bs + (long)bm * lda_m;
    B += (long)blockIdx.z * b_bs + (long)bn * ldb_n;
    C += (long)blockIdx.z * c_bs;

    const float* aSrc[4];
    uint32_t aDst[4];
    #pragma unroll
    for (int i = 0; i < 4; i++) {
        int idx = tid + i * 256;
        int row = idx >> 3, c4 = idx & 7;
        aSrc[i] = A + (long)row * lda_m + c4 * 4;
        aDst[i] = smaddr(As + row * A_STRIDE + c4 * 4);
    }
    const float* bSrc[BCPT];
    uint32_t bDst[BCPT];
    #pragma unroll
    for (int i = 0; i < BCPT; i++) {
        int idx = tid + i * 256;
        if (KN) {
            int row = idx / (BN / 4), c4 = idx % (BN / 4);
            bSrc[i] = B + (long)row * ldb_k + c4 * 4;
            bDst[i] = smaddr(Bs + row * B_STRIDE + c4 * 4);
        } else {
            int row = idx >> 3, c4 = idx & 7;
            bSrc[i] = B + (long)row * ldb_n + c4 * 4;
            bDst[i] = smaddr(Bs + row * B_STRIDE + c4 * 4);
        }
    }
    const long bAdv = KN ? (long)BK * ldb_k : (long)BK;

    auto load_slab = [&](int st) {
        uint32_t ao = st * (A_TILE * 4);
        uint32_t bo = st * (B_TILE * 4);
        #pragma unroll
        for (int i = 0; i < 4; i++) { cp16(aDst[i] + ao, aSrc[i]); aSrc[i] += BK; }
        #pragma unroll
        for (int i = 0; i < BCPT; i++) { cp16(bDst[i] + bo, bSrc[i]); bSrc[i] += bAdv; }
        cp_commit();
    };

    float acc[MI][NI][4];
    #pragma unroll
    for (int mi = 0; mi < MI; mi++)
        #pragma unroll
        for (int ni = 0; ni < NI; ni++)
            #pragma unroll
            for (int r = 0; r < 4; r++) acc[mi][ni][r] = 0.f;

    const int nslab = K / BK;
    load_slab(0);

    for (int s = 0; s < nslab; s++) {
        cp_wait0();
        __syncthreads();
        if (s + 1 < nslab) load_slab((s + 1) & 1);

        const int st = s & 1;
        const float* Ab = As + st * A_TILE;
        const float* Bb = Bs + st * B_TILE;

        #pragma unroll
        for (int kk = 0; kk < BK; kk += 8) {
            uint32_t afr[MI][4], bfr[NI][2];
            #pragma unroll
            for (int mi = 0; mi < MI; mi++) {
                const float* ap = Ab + (m_base + mi * 16 + g) * A_STRIDE + kk;
                afr[mi][0] = __float_as_uint(ap[tg]);
                afr[mi][1] = __float_as_uint(ap[8 * A_STRIDE + tg]);
                afr[mi][2] = __float_as_uint(ap[tg + 4]);
                afr[mi][3] = __float_as_uint(ap[8 * A_STRIDE + tg + 4]);
            }
            #pragma unroll
            for (int ni = 0; ni < NI; ni++) {
                if (KN) {
                    const float* bp = Bb + (kk + tg) * B_STRIDE + n_base + ni * 8 + g;
                    bfr[ni][0] = __float_as_uint(bp[0]);
                    bfr[ni][1] = __float_as_uint(bp[4 * B_STRIDE]);
                } else {
                    const float* bp = Bb + (n_base + ni * 8 + g) * B_STRIDE + kk;
                    bfr[ni][0] = __float_as_uint(bp[tg]);
                    bfr[ni][1] = __float_as_uint(bp[tg + 4]);
                }
            }
            #pragma unroll
            for (int mi = 0; mi < MI; mi++)
                #pragma unroll
                for (int ni = 0; ni < NI; ni++)
                    mma_tf32(acc[mi][ni], afr[mi], bfr[ni]);
        }
        __syncthreads();
    }

    #pragma unroll
    for (int mi = 0; mi < MI; mi++) {
        int row0 = bm + m_base + mi * 16 + g;
        float2 ml0 = stats[(long)blockIdx.z * Tn + row0];
        float2 ml1 = stats[(long)blockIdx.z * Tn + row0 + 8];
        float i0 = 1.f / ml0.y, i1 = 1.f / ml1.y;
        #pragma unroll
        for (int ni = 0; ni < NI; ni++) {
            int col = bn + n_base + ni * 8 + tg * 2;
            float v0 = expf(acc[mi][ni][0] * alpha - ml0.x) * i0;
            float v1 = expf(acc[mi][ni][1] * alpha - ml0.x) * i0;
            float v2 = expf(acc[mi][ni][2] * alpha - ml1.x) * i1;
            float v3 = expf(acc[mi][ni][3] * alpha - ml1.x) * i1;
            *(float2*)&C[(long)row0 * ldc_m + col]       = make_float2(v0, v1);
            *(float2*)&C[(long)(row0 + 8) * ldc_m + col] = make_float2(v2, v3);
        }
    }
}

// ======================= out = LayerNorm(x+res)*g+b ; optional half copy
__global__ __launch_bounds__(256) void add_ln_kernel(
    const float* __restrict__ x, const float* __restrict__ res,
    const float* __restrict__ g, const float* __restrict__ b,
    float* __restrict__ out, __half* __restrict__ out_r)
{
    const long row = (long)blockIdx.x * En;
    const int tid = threadIdx.x;
    float v[4]; float s = 0.f, s2 = 0.f;
    #pragma unroll
    for (int j = 0; j < 4; j++) {
        int i = tid + j * 256;
        float val = x[row + i] + res[row + i];
        v[j] = val; s += val; s2 += val * val;
    }
    __shared__ float sh1[8], sh2[8];
    #pragma unroll
    for (int o = 16; o; o >>= 1) {
        s  += __shfl_xor_sync(0xffffffffu, s, o);
        s2 += __shfl_xor_sync(0xffffffffu, s2, o);
    }
    if ((tid & 31) == 0) { sh1[tid >> 5] = s; sh2[tid >> 5] = s2; }
    __syncthreads();
    float ts = 0.f, ts2 = 0.f;
    #pragma unroll
    for (int w = 0; w < 8; w++) { ts += sh1[w]; ts2 += sh2[w]; }
    const float mu  = ts * (1.f / En);
    const float var = ts2 * (1.f / En) - mu * mu;
    const float inv = rsqrtf(var + 1e-5f);
    #pragma unroll
    for (int j = 0; j < 4; j++) {
        int i = tid + j * 256;
        float o = (v[j] - mu) * inv * g[i] + b[i];
        out[row + i] = o;
        if (out_r) out_r[row + i] = __float2half_rn(o);
    }
}

// ======================= fused fp16 conversion pass =======================
#define NCVT 12
struct CvtJobs {
    const float4* src[NCVT];
    uint2* dst[NCVT];
    int cum[NCVT + 1];
};
__global__ __launch_bounds__(256) void cvt_multi(CvtJobs cj, int total4)
{
    for (int i = blockIdx.x * 256 + threadIdx.x; i < total4; i += gridDim.x * 256) {
        int job = 0;
        #pragma unroll
        for (int t = 0; t < NCVT - 1; t++) if (i >= cj.cum[t + 1]) job = t + 1;
        int off = i - cj.cum[job];
        float4 v = cj.src[job][off];
        __half2 h0 = __floats2half2_rn(v.x, v.y);
        __half2 h1 = __floats2half2_rn(v.z, v.w);
        uint2 u;
        u.x = *(uint32_t*)&h0;
        u.y = *(uint32_t*)&h1;
        cj.dst[job][off] = u;
    }
}

// ======================= host-side =======================
#define SMEM128 ((2*128*36 + 2*128*36) * 4)

static inline void gh(JobsH jobs, int M, int N, int K, int njobs, int postop)
{
    dim3 grid(N / 128, M / 128, njobs);
    hgemm2<<<grid, 128, H2_SMEM>>>(jobs, K, N, postop);
}

extern "C" void kernel_launch(void* const* d_in, const int* in_sizes, int n_in,
                              void* d_out, int out_size)
{
    static bool attr_done = false;
    if (!attr_done) {
        cudaFuncSetAttribute((const void*)hgemm2,
                             cudaFuncAttributeMaxDynamicSharedMemorySize, H2_SMEM);
        cudaFuncSetAttribute((const void*)tgemm<128, false>,
                             cudaFuncAttributeMaxDynamicSharedMemorySize, SMEM128);
        cudaFuncSetAttribute((const void*)flash_kernel<true>,
                             cudaFuncAttributeMaxDynamicSharedMemorySize, FL_SMEM);
        cudaFuncSetAttribute((const void*)flash_kernel<false>,
                             cudaFuncAttributeMaxDynamicSharedMemorySize, FL_SMEM);
        attr_done = true;
    }

    const float* state = (const float*)d_in[0];
    const float* enc   = (const float*)d_in[1];
    const float* sa_wq = (const float*)d_in[3];  const float* sa_bq = (const float*)d_in[4];
    const float* sa_wk = (const float*)d_in[5];  const float* sa_bk = (const float*)d_in[6];
    const float* sa_wv = (const float*)d_in[7];  const float* sa_bv = (const float*)d_in[8];
    const float* sa_wo = (const float*)d_in[9];  const float* sa_bo = (const float*)d_in[10];
    const float* ea_wq = (const float*)d_in[11]; const float* ea_bq = (const float*)d_in[12];
    const float* ea_wk = (const float*)d_in[13]; const float* ea_bk = (const float*)d_in[14];
    const float* ea_wv = (const float*)d_in[15]; const float* ea_bv = (const float*)d_in[16];
    const float* ea_wo = (const float*)d_in[17]; const float* ea_bo = (const float*)d_in[18];
    const float* fc1_w = (const float*)d_in[19]; const float* fc1_b = (const float*)d_in[20];
    const float* fc2_w = (const float*)d_in[21]; const float* fc2_b = (const float*)d_in[22];
    const float* ln1_g = (const float*)d_in[23]; const float* ln1_b = (const float*)d_in[24];
    const float* ln2_g = (const float*)d_in[25]; const float* ln2_b = (const float*)d_in[26];
    const float* ln3_g = (const float*)d_in[27]; const float* ln3_b = (const float*)d_in[28];

    float *xq, *xk, *xv, *tmp, *st1, *st2, *rw;
    float *attn_f, *st1r_f, *st2r_f, *ffn_f;
    float2* stats;
    cudaGetSymbolAddress((void**)&xq,     g_xq);
    cudaGetSymbolAddress((void**)&xk,     g_xk);
    cudaGetSymbolAddress((void**)&xv,     g_xv);
    cudaGetSymbolAddress((void**)&attn_f, g_attn);
    cudaGetSymbolAddress((void**)&tmp,    g_tmp);
    cudaGetSymbolAddress((void**)&st1,    g_state1);
    cudaGetSymbolAddress((void**)&st2,    g_state2);
    cudaGetSymbolAddress((void**)&st1r_f, g_st1r);
    cudaGetSymbolAddress((void**)&st2r_f, g_st2r);
    cudaGetSymbolAddress((void**)&ffn_f,  g_ffn);
    cudaGetSymbolAddress((void**)&stats,  g_stats);
    cudaGetSymbolAddress((void**)&rw,     g_rw);

    __half* attn_h = (__half*)attn_f;
    __half* st1r_h = (__half*)st1r_f;
    __half* st2r_h = (__half*)st2r_f;
    __half* ffn_h  = (__half*)ffn_f;
    __half* hp = (__half*)rw;
    __half* h_state = hp + 0L  * MEG;
    __half* h_enc   = hp + 4L  * MEG;
    __half* h_saq   = hp + 8L  * MEG;
    __half* h_sak   = hp + 9L  * MEG;
    __half* h_sav   = hp + 10L * MEG;
    __half* h_sao   = hp + 11L * MEG;
    __half* h_eaq   = hp + 12L * MEG;
    __half* h_eak   = hp + 13L * MEG;
    __half* h_eav   = hp + 14L * MEG;
    __half* h_eao   = hp + 15L * MEG;
    __half* h_fc1   = hp + 16L * MEG;
    __half* h_fc2   = hp + 20L * MEG;

    float* out_state = (float*)d_out;
    float* out_attn  = (float*)d_out + (long)Tn * Bn * En;

    const float sc = 1.0f / 8.0f;
    const long BE = (long)Bn * En;
    const long TS = (long)Tn * Sn;

    // -------- fused fp16 conversion pass --------
    {
        CvtJobs cj;
        const float* srcs[NCVT] = {state, enc, sa_wq, sa_wk, sa_wv, sa_wo,
                                   ea_wq, ea_wk, ea_wv, ea_wo, fc1_w, fc2_w};
        __half* dsts[NCVT] = {h_state, h_enc, h_saq, h_sak, h_sav, h_sao,
                              h_eaq, h_eak, h_eav, h_eao, h_fc1, h_fc2};
        const int n4s[NCVT] = {MEG, MEG, MEG/4, MEG/4, MEG/4, MEG/4,
                               MEG/4, MEG/4, MEG/4, MEG/4, MEG, MEG};
        int c = 0;
        for (int i = 0; i < NCVT; i++) {
            cj.src[i] = (const float4*)srcs[i];
            cj.dst[i] = (uint2*)dsts[i];
            cj.cum[i] = c;
            c += n4s[i];
        }
        cj.cum[NCVT] = c;
        cvt_multi<<<1024, 256>>>(cj, c);
    }

    // ---------------- self-attention (fused flash, causal) ----------------
    {
        JobsH j = {{{h_state, h_saq, sa_bq, xq},
                    {h_state, h_sak, sa_bk, xk},
                    {h_state, h_sav, sa_bv, xv}}};
        gh(j, ROWS, En, En, 3, 2);
    }
    flash_kernel<true><<<dim3(Tn / 128, BH), 256, FL_SMEM>>>(xq, xk, xv, attn_h, nullptr);
    {
        JobsH j = {{{attn_h, h_sao, sa_bo, tmp}, {}, {}}};
        gh(j, ROWS, En, En, 1, 0);
    }
    add_ln_kernel<<<ROWS, 256>>>(tmp, state, ln1_g, ln1_b, st1, st1r_h);

    // ---------------- encoder-decoder attention ----------------
    {
        JobsH j = {{{st1r_h, h_eaq, ea_bq, xq},
                    {h_enc,  h_eak, ea_bk, xk},
                    {h_enc,  h_eav, ea_bv, xv}}};
        gh(j, ROWS, En, En, 3, 2);
    }
    flash_kernel<false><<<dim3(Tn / 128, BH), 256, FL_SMEM>>>(xq, xk, xv, attn_h, stats);
    // normalized attention weights straight into d_out
    {
        dim3 grid(Sn / 128, Tn / 128, BH);
        tgemm<128, false><<<grid, 256, SMEM128>>>(xq, xk, stats, out_attn, DHn,
                                                  BE, DHn, BE, 1, DHn, Sn, TS, sc);
    }
    {
        JobsH j = {{{attn_h, h_eao, ea_bo, tmp}, {}, {}}};
        gh(j, ROWS, En, En, 1, 0);
    }
    add_ln_kernel<<<ROWS, 256>>>(tmp, st1, ln2_g, ln2_b, st2, st2r_h);

    // ---------------- FFN ----------------
    {
        JobsH j = {{{st2r_h, h_fc1, fc1_b, ffn_h}, {}, {}}};
        gh(j, ROWS, FFn, En, 1, 1);
    }
    {
        JobsH j = {{{ffn_h, h_fc2, fc2_b, tmp}, {}, {}}};
        gh(j, ROWS, En, FFn, 1, 0);
    }
    add_ln_kernel<<<ROWS, 256>>>(tmp, st2, ln3_g, ln3_b, out_state, nullptr);
}

// round 9
// speedup vs baseline: 5.6511x; 1.0197x over previous
#include <cuda_runtime.h>
#include <cuda_fp16.h>
#include <math.h>
#include <stdint.h>

// Problem dims
#define Tn 1024
#define Sn 1024
#define Bn 4
#define En 1024
#define Hn 16
#define DHn 64
#define FFn 4096
#define ROWS (Tn*Bn)
#define BH (Bn*Hn)
#define MEG (1024*1024)

// -------- scratch (device globals; no allocation) --------
__device__ float g_xq[ROWS*En];
__device__ float g_xk[ROWS*En];
__device__ float g_xv[ROWS*En];
__device__ float g_attn[ROWS*En];      // used as __half
__device__ float g_tmp[ROWS*En];
__device__ float g_state1[ROWS*En];
__device__ float g_state2[ROWS*En];
__device__ float g_st1r[ROWS*En];      // used as __half
__device__ float g_st2r[ROWS*En];      // used as __half
__device__ float g_ffn[ROWS*FFn];      // used as __half
__device__ float2 g_stats[BH*Tn];
__device__ float g_rw[24*MEG];         // used as __half pool

// ======================= helpers =======================
__device__ __forceinline__ uint32_t f2tf32(float x) {
    uint32_t r;
    asm("cvt.rna.tf32.f32 %0, %1;" : "=r"(r) : "f"(x));
    return r;
}
__device__ __forceinline__ float roundtf(float x) { return __uint_as_float(f2tf32(x)); }
__device__ __forceinline__ float round16(float x) { return __half2float(__float2half_rn(x)); }

__device__ __forceinline__ void mma_tf32(float* c, const uint32_t* a, const uint32_t* b) {
    asm volatile(
        "mma.sync.aligned.m16n8k8.row.col.f32.tf32.tf32.f32 "
        "{%0,%1,%2,%3}, {%4,%5,%6,%7}, {%8,%9}, {%0,%1,%2,%3};"
        : "+f"(c[0]), "+f"(c[1]), "+f"(c[2]), "+f"(c[3])
        : "r"(a[0]), "r"(a[1]), "r"(a[2]), "r"(a[3]), "r"(b[0]), "r"(b[1]));
}
__device__ __forceinline__ void mma_f16(float* c, const uint32_t* a, const uint32_t* b) {
    asm volatile(
        "mma.sync.aligned.m16n8k16.row.col.f32.f16.f16.f32 "
        "{%0,%1,%2,%3}, {%4,%5,%6,%7}, {%8,%9}, {%0,%1,%2,%3};"
        : "+f"(c[0]), "+f"(c[1]), "+f"(c[2]), "+f"(c[3])
        : "r"(a[0]), "r"(a[1]), "r"(a[2]), "r"(a[3]), "r"(b[0]), "r"(b[1]));
}
__device__ __forceinline__ void ldsm4(uint32_t* r, uint32_t addr) {
    asm volatile("ldmatrix.sync.aligned.m8n8.x4.shared.b16 {%0,%1,%2,%3}, [%4];"
        : "=r"(r[0]), "=r"(r[1]), "=r"(r[2]), "=r"(r[3]) : "r"(addr));
}
__device__ __forceinline__ void cp16(uint32_t dst, const void* src) {
    asm volatile("cp.async.cg.shared.global [%0], [%1], 16;" :: "r"(dst), "l"(src));
}
__device__ __forceinline__ void cp_commit() {
    asm volatile("cp.async.commit_group;" ::: "memory");
}
__device__ __forceinline__ void cp_wait0() {
    asm volatile("cp.async.wait_group 0;" ::: "memory");
}
__device__ __forceinline__ uint32_t smaddr(const void* p) {
    return (uint32_t)__cvta_generic_to_shared(p);
}

// ======================= hgemm2: fp16 MMA + ldmatrix, 64x64 warp tiles ============
// C[m,n] = sum_k A[m,k]*B[n,k] + bias[n]; A:[M,K] half; B:[N,K] half.
// 128 threads, 4 warps 2x2, warp tile 64x64. K-slab 64 halfs, 2 stages.
// postop: 0 = fp32 out; 1 = relu -> half out; 2 = fp32 out rounded to fp16 precision.
struct JobH { const __half* A; const __half* B; const float* bias; void* C; };
struct JobsH { JobH j[3]; };

#define H2_WS 36                       // words per row (64 halfs + 8 halfs pad)
#define H2_TILEW (128*H2_WS)           // words per operand tile
#define H2_SMEM (4*H2_TILEW*4)         // 2 stages x (A+B) bytes = 73728

__global__ __launch_bounds__(128, 2) void hgemm2(
    JobsH jobs, int K, int N, int postop)
{
    extern __shared__ uint32_t smw[];
    const int tid  = threadIdx.x;
    const int lane = tid & 31;
    const int wid  = tid >> 5;
    const int wm = wid & 1, wn = wid >> 1;
    const int m_base = wm * 64, n_base = wn * 64;
    const int g  = lane >> 2;
    const int tg = lane & 3;

    const JobH job = jobs.j[blockIdx.z];
    const int bm = blockIdx.y * 128;
    const int bn = blockIdx.x * 128;
    const __half* A = job.A + (long)bm * K;
    const __half* B = job.B + (long)bn * K;

    const int r0 = tid >> 3, c8 = tid & 7;     // 8 chunks of 8 halfs per 64-half row
    const __half* aPtr = A + (long)r0 * K + c8 * 8;
    const __half* bPtr = B + (long)r0 * K + c8 * 8;
    const uint32_t aSm = smaddr(smw + r0 * H2_WS + c8 * 4);
    const uint32_t bSm = smaddr(smw + H2_TILEW + r0 * H2_WS + c8 * 4);
    const long rowAdv = 16L * K;

    auto load_slab = [&](int st) {
        const uint32_t so = st * (2 * H2_TILEW * 4);
        #pragma unroll
        for (int it = 0; it < 8; it++) {
            cp16(aSm + so + it * (16 * H2_WS * 4), aPtr + it * rowAdv);
            cp16(bSm + so + it * (16 * H2_WS * 4), bPtr + it * rowAdv);
        }
        cp_commit();
    };

    // ---- ldmatrix per-lane addresses ----
    // A (x4): m0 rows0-7/kc0, m1 rows8-15/kc0, m2 rows0-7/kc1, m3 rows8-15/kc1
    uint32_t aLd[4];
    {
        int rowl = lane & 15;
        uint32_t kcb = (lane >> 4) * 16;   // +16B for k-chunk 1
        #pragma unroll
        for (int mi = 0; mi < 4; mi++)
            aLd[mi] = smaddr(smw + (m_base + mi * 16 + rowl) * H2_WS) + kcb;
    }
    // B (x4, covers 2 n-groups): m0 rows n0-7/kc0, m1 rows n0-7/kc1,
    //                            m2 rows n8-15/kc0, m3 rows n8-15/kc1
    uint32_t bLd[4];
    {
        int rowl = (lane & 7) + ((lane >> 4) * 8);
        uint32_t kcb = ((lane >> 3) & 1) * 16;
        #pragma unroll
        for (int p = 0; p < 4; p++)
            bLd[p] = smaddr(smw + H2_TILEW + (n_base + p * 16 + rowl) * H2_WS) + kcb;
    }

    float acc[4][8][4];
    #pragma unroll
    for (int mi = 0; mi < 4; mi++)
        #pragma unroll
        for (int ni = 0; ni < 8; ni++)
            #pragma unroll
            for (int r = 0; r < 4; r++) acc[mi][ni][r] = 0.f;

    const int nslab = K >> 6;
    load_slab(0);

    for (int s = 0; s < nslab; s++) {
        cp_wait0();
        __syncthreads();
        aPtr += 64; bPtr += 64;
        if (s + 1 < nslab) load_slab((s + 1) & 1);

        const uint32_t so = (s & 1) * (2 * H2_TILEW * 4);

        #pragma unroll
        for (int kw = 0; kw < 32; kw += 8) {   // 8 words = 16 halfs per k-step
            uint32_t afr[4][4], bfr[4][4];
            #pragma unroll
            for (int mi = 0; mi < 4; mi++) ldsm4(afr[mi], aLd[mi] + so + kw * 4);
            #pragma unroll
            for (int p = 0; p < 4; p++)    ldsm4(bfr[p], bLd[p] + so + kw * 4);
            #pragma unroll
            for (int mi = 0; mi < 4; mi++)
                #pragma unroll
                for (int ni = 0; ni < 8; ni++) {
                    uint32_t bq[2] = { bfr[ni >> 1][(ni & 1) * 2],
                                       bfr[ni >> 1][(ni & 1) * 2 + 1] };
                    mma_f16(acc[mi][ni], afr[mi], bq);
                }
        }
        __syncthreads();
    }

    // epilogue
    const float* bias = job.bias;
    #pragma unroll
    for (int mi = 0; mi < 4; mi++) {
        int row0 = bm + m_base + mi * 16 + g;
        #pragma unroll
        for (int ni = 0; ni < 8; ni++) {
            int col = bn + n_base + ni * 8 + tg * 2;
            float b0 = bias[col], b1 = bias[col + 1];
            float v0 = acc[mi][ni][0] + b0;
            float v1 = acc[mi][ni][1] + b1;
            float v2 = acc[mi][ni][2] + b0;
            float v3 = acc[mi][ni][3] + b1;
            if (postop == 1) {                 // relu -> half output
                __half* C = (__half*)job.C;
                __half2 h0 = __floats2half2_rn(fmaxf(v0, 0.f), fmaxf(v1, 0.f));
                __half2 h1 = __floats2half2_rn(fmaxf(v2, 0.f), fmaxf(v3, 0.f));
                *(__half2*)&C[(long)row0 * N + col]       = h0;
                *(__half2*)&C[(long)(row0 + 8) * N + col] = h1;
            } else {
                float* C = (float*)job.C;
                if (postop == 2) {
                    v0 = round16(v0); v1 = round16(v1);
                    v2 = round16(v2); v3 = round16(v3);
                }
                *(float2*)&C[(long)row0 * N + col]       = make_float2(v0, v1);
                *(float2*)&C[(long)(row0 + 8) * N + col] = make_float2(v2, v3);
            }
        }
    }
}

// ======================= fused flash attention (tf32 internals, half O) ==========
#define FL_QS 68
#define FL_KS 68
#define FL_VS 72
#define FL_PS 68
#define FL_SMEM ((128*FL_QS + 2*64*FL_KS + 2*64*FL_VS + 128*FL_PS) * 4)

template<bool CAUSAL>
__global__ __launch_bounds__(256, 1) void flash_kernel(
    const float* __restrict__ Qp, const float* __restrict__ Kp,
    const float* __restrict__ Vp, __half* __restrict__ Op,
    float2* __restrict__ stats)
{
    extern __shared__ float fsm[];
    float* Qs = fsm;
    float* Ks = Qs + 128 * FL_QS;
    float* Vs = Ks + 2 * 64 * FL_KS;
    float* Ps = Vs + 2 * 64 * FL_VS;

    const int tid = threadIdx.x;
    const int lane = tid & 31, w = tid >> 5;
    const int g = lane >> 2, tg = lane & 3;
    const int bh = blockIdx.y;
    const int it = CAUSAL ? ((int)gridDim.x - 1 - (int)blockIdx.x) : (int)blockIdx.x;
    const int t0 = it * 128;
    const int nIter = CAUSAL ? 2 * it + 2 : 16;

    const float* Qg = Qp + (long)t0 * 4096 + bh * 64;
    const float* Kg = Kp + bh * 64;
    const float* Vg = Vp + bh * 64;

    auto loadKV = [&](int j, int buf) {
        float* kb = Ks + buf * 64 * FL_KS;
        float* vb = Vs + buf * 64 * FL_VS;
        const long s0 = (long)j * 64;
        #pragma unroll
        for (int i = 0; i < 4; i++) {
            int idx = tid + i * 256;
            int row = idx >> 4, c = idx & 15;
            cp16(smaddr(kb + row * FL_KS + c * 4), Kg + (s0 + row) * 4096 + c * 4);
            cp16(smaddr(vb + row * FL_VS + c * 4), Vg + (s0 + row) * 4096 + c * 4);
        }
    };

    #pragma unroll
    for (int i = 0; i < 8; i++) {
        int idx = tid + i * 256;
        int row = idx >> 4, c = idx & 15;
        cp16(smaddr(Qs + row * FL_QS + c * 4), Qg + (long)row * 4096 + c * 4);
    }
    loadKV(0, 0);
    cp_commit();
    cp_wait0();
    __syncthreads();

    uint32_t qf[8][4];
    {
        const float* qp = Qs + (16 * w + g) * FL_QS;
        #pragma unroll
        for (int kk = 0; kk < 8; kk++) {
            qf[kk][0] = __float_as_uint(qp[kk * 8 + tg]);
            qf[kk][1] = __float_as_uint(qp[8 * FL_QS + kk * 8 + tg]);
            qf[kk][2] = __float_as_uint(qp[kk * 8 + tg + 4]);
            qf[kk][3] = __float_as_uint(qp[8 * FL_QS + kk * 8 + tg + 4]);
        }
    }

    float acc_o[8][4];
    #pragma unroll
    for (int ni = 0; ni < 8; ni++)
        #pragma unroll
        for (int r = 0; r < 4; r++) acc_o[ni][r] = 0.f;
    float m0 = -1e30f, m1 = -1e30f, l0 = 0.f, l1 = 0.f;

    for (int j = 0; j < nIter; j++) {
        const int buf = j & 1;
        if (j + 1 < nIter) { loadKV(j + 1, buf ^ 1); cp_commit(); }

        float s_acc[8][4];
        #pragma unroll
        for (int ni = 0; ni < 8; ni++)
            #pragma unroll
            for (int r = 0; r < 4; r++) s_acc[ni][r] = 0.f;
        const float* kb = Ks + buf * 64 * FL_KS;
        #pragma unroll
        for (int kk = 0; kk < 8; kk++) {
            #pragma unroll
            for (int ni = 0; ni < 8; ni++) {
                const float* bp = kb + (ni * 8 + g) * FL_KS + kk * 8;
                uint32_t bfr[2];
                bfr[0] = __float_as_uint(bp[tg]);
                bfr[1] = __float_as_uint(bp[tg + 4]);
                mma_tf32(s_acc[ni], qf[kk], bfr);
            }
        }

        const int s0 = j * 64;
        const bool need = CAUSAL && (s0 + 63 > t0 + 16 * w);
        const int tr0 = t0 + 16 * w + g, tr1 = tr0 + 8;
        float mx0 = -1e30f, mx1 = -1e30f;
        #pragma unroll
        for (int ni = 0; ni < 8; ni++) {
            float v0 = s_acc[ni][0] * 0.125f;
            float v1 = s_acc[ni][1] * 0.125f;
            float v2 = s_acc[ni][2] * 0.125f;
            float v3 = s_acc[ni][3] * 0.125f;
            if (need) {
                int c0 = s0 + ni * 8 + 2 * tg, c1 = c0 + 1;
                if (c0 > tr0) v0 -= 1e9f;
                if (c1 > tr0) v1 -= 1e9f;
                if (c0 > tr1) v2 -= 1e9f;
                if (c1 > tr1) v3 -= 1e9f;
            }
            s_acc[ni][0] = v0; s_acc[ni][1] = v1;
            s_acc[ni][2] = v2; s_acc[ni][3] = v3;
            mx0 = fmaxf(mx0, fmaxf(v0, v1));
            mx1 = fmaxf(mx1, fmaxf(v2, v3));
        }
        mx0 = fmaxf(mx0, __shfl_xor_sync(0xffffffffu, mx0, 1));
        mx0 = fmaxf(mx0, __shfl_xor_sync(0xffffffffu, mx0, 2));
        mx1 = fmaxf(mx1, __shfl_xor_sync(0xffffffffu, mx1, 1));
        mx1 = fmaxf(mx1, __shfl_xor_sync(0xffffffffu, mx1, 2));
        const float mn0 = fmaxf(m0, mx0), mn1 = fmaxf(m1, mx1);
        const float sc0 = expf(m0 - mn0), sc1 = expf(m1 - mn1);
        m0 = mn0; m1 = mn1;

        float sum0 = 0.f, sum1 = 0.f;
        float* prow0 = Ps + (16 * w + g) * FL_PS;
        float* prow1 = prow0 + 8 * FL_PS;
        #pragma unroll
        for (int ni = 0; ni < 8; ni++) {
            float p0 = expf(s_acc[ni][0] - m0);
            float p1 = expf(s_acc[ni][1] - m0);
            float p2 = expf(s_acc[ni][2] - m1);
            float p3 = expf(s_acc[ni][3] - m1);
            sum0 += p0 + p1; sum1 += p2 + p3;
            *(float2*)&prow0[ni * 8 + 2 * tg] = make_float2(roundtf(p0), roundtf(p1));
            *(float2*)&prow1[ni * 8 + 2 * tg] = make_float2(roundtf(p2), roundtf(p3));
        }
        sum0 += __shfl_xor_sync(0xffffffffu, sum0, 1);
        sum0 += __shfl_xor_sync(0xffffffffu, sum0, 2);
        sum1 += __shfl_xor_sync(0xffffffffu, sum1, 1);
        sum1 += __shfl_xor_sync(0xffffffffu, sum1, 2);
        l0 = l0 * sc0 + sum0;
        l1 = l1 * sc1 + sum1;
        #pragma unroll
        for (int ni = 0; ni < 8; ni++) {
            acc_o[ni][0] *= sc0; acc_o[ni][1] *= sc0;
            acc_o[ni][2] *= sc1; acc_o[ni][3] *= sc1;
        }
        __syncthreads();

        const float* vb = Vs + buf * 64 * FL_VS;
        const float* pp = Ps + (16 * w + g) * FL_PS;
        #pragma unroll
        for (int kk = 0; kk < 8; kk++) {
            uint32_t pf[4];
            pf[0] = __float_as_uint(pp[kk * 8 + tg]);
            pf[1] = __float_as_uint(pp[8 * FL_PS + kk * 8 + tg]);
            pf[2] = __float_as_uint(pp[kk * 8 + tg + 4]);
            pf[3] = __float_as_uint(pp[8 * FL_PS + kk * 8 + tg + 4]);
            #pragma unroll
            for (int ni = 0; ni < 8; ni++) {
                const float* vp = vb + (kk * 8 + tg) * FL_VS + ni * 8 + g;
                uint32_t bfr[2];
                bfr[0] = __float_as_uint(vp[0]);
                bfr[1] = __float_as_uint(vp[4 * FL_VS]);
                mma_tf32(acc_o[ni], pf, bfr);
            }
        }
        if (j + 1 < nIter) cp_wait0();
        __syncthreads();
    }

    const float inv0 = 1.f / l0, inv1 = 1.f / l1;
    const int r0 = t0 + 16 * w + g;
    __half* o0 = Op + (long)r0 * 4096 + bh * 64;
    __half* o1 = o0 + 8L * 4096;
    #pragma unroll
    for (int ni = 0; ni < 8; ni++) {
        *(__half2*)&o0[ni * 8 + 2 * tg] =
            __floats2half2_rn(acc_o[ni][0] * inv0, acc_o[ni][1] * inv0);
        *(__half2*)&o1[ni * 8 + 2 * tg] =
            __floats2half2_rn(acc_o[ni][2] * inv1, acc_o[ni][3] * inv1);
    }
    if (!CAUSAL && tg == 0) {
        stats[bh * Tn + r0]     = make_float2(m0, l0);
        stats[bh * Tn + r0 + 8] = make_float2(m1, l1);
    }
}

// ======================= HMMA tf32 GEMM (EA normalized-weights pass) ============
template<int BN, bool KN>
__global__ __launch_bounds__(256, 2) void tgemm(
    const float* __restrict__ A, const float* __restrict__ B,
    const float2* __restrict__ stats, float* __restrict__ C,
    int K,
    long lda_m, long a_bs,
    long ldb_n, long ldb_k, long b_bs,
    long ldc_m, long c_bs,
    float alpha)
{
    constexpr int BM = 128, BK = 32;
    constexpr int WARPS_N = BN / 32;
    constexpr int WARPS_M = 8 / WARPS_N;
    constexpr int MI = (BM / WARPS_M) / 16;
    constexpr int NI = 4;
    constexpr int A_STRIDE = BK + 4;
    constexpr int B_STRIDE = KN ? (BN + 8) : (BK + 4);
    constexpr int B_ROWS   = KN ? BK : BN;
    constexpr int A_TILE = BM * A_STRIDE;
    constexpr int B_TILE = B_ROWS * B_STRIDE;
    constexpr int BCPT = (BK * BN / 4) / 256;

    extern __shared__ float smf[];
    float* As = smf;
    float* Bs = smf + 2 * A_TILE;

    const int tid  = threadIdx.x;
    const int lane = tid & 31;
    const int wid  = tid >> 5;
    const int wm = wid % WARPS_M, wn = wid / WARPS_M;
    const int m_base = wm * (BM / WARPS_M);
    const int n_base = wn * 32;
    const int g  = lane >> 2;
    const int tg = lane & 3;

    const int bm = blockIdx.y * BM;
    const int bn = blockIdx.x * BN;
    A += (long)blockIdx.z * a_bs + (long)bm * lda_m;
    B += (long)blockIdx.z * b_bs + (long)bn * ldb_n;
    C += (long)blockIdx.z * c_bs;

    const float* aSrc[4];
    uint32_t aDst[4];
    #pragma unroll
    for (int i = 0; i < 4; i++) {
        int idx = tid + i * 256;
        int row = idx >> 3, c4 = idx & 7;
        aSrc[i] = A + (long)row * lda_m + c4 * 4;
        aDst[i] = smaddr(As + row * A_STRIDE + c4 * 4);
    }
    const float* bSrc[BCPT];
    uint32_t bDst[BCPT];
    #pragma unroll
    for (int i = 0; i < BCPT; i++) {
        int idx = tid + i * 256;
        if (KN) {
            int row = idx / (BN / 4), c4 = idx % (BN / 4);
            bSrc[i] = B + (long)row * ldb_k + c4 * 4;
            bDst[i] = smaddr(Bs + row * B_STRIDE + c4 * 4);
        } else {
            int row = idx >> 3, c4 = idx & 7;
            bSrc[i] = B + (long)row * ldb_n + c4 * 4;
            bDst[i] = smaddr(Bs + row * B_STRIDE + c4 * 4);
        }
    }
    const long bAdv = KN ? (long)BK * ldb_k : (long)BK;

    auto load_slab = [&](int st) {
        uint32_t ao = st * (A_TILE * 4);
        uint32_t bo = st * (B_TILE * 4);
        #pragma unroll
        for (int i = 0; i < 4; i++) { cp16(aDst[i] + ao, aSrc[i]); aSrc[i] += BK; }
        #pragma unroll
        for (int i = 0; i < BCPT; i++) { cp16(bDst[i] + bo, bSrc[i]); bSrc[i] += bAdv; }
        cp_commit();
    };

    float acc[MI][NI][4];
    #pragma unroll
    for (int mi = 0; mi < MI; mi++)
        #pragma unroll
        for (int ni = 0; ni < NI; ni++)
            #pragma unroll
            for (int r = 0; r < 4; r++) acc[mi][ni][r] = 0.f;

    const int nslab = K / BK;
    load_slab(0);

    for (int s = 0; s < nslab; s++) {
        cp_wait0();
        __syncthreads();
        if (s + 1 < nslab) load_slab((s + 1) & 1);

        const int st = s & 1;
        const float* Ab = As + st * A_TILE;
        const float* Bb = Bs + st * B_TILE;

        #pragma unroll
        for (int kk = 0; kk < BK; kk += 8) {
            uint32_t afr[MI][4], bfr[NI][2];
            #pragma unroll
            for (int mi = 0; mi < MI; mi++) {
                const float* ap = Ab + (m_base + mi * 16 + g) * A_STRIDE + kk;
                afr[mi][0] = __float_as_uint(ap[tg]);
                afr[mi][1] = __float_as_uint(ap[8 * A_STRIDE + tg]);
                afr[mi][2] = __float_as_uint(ap[tg + 4]);
                afr[mi][3] = __float_as_uint(ap[8 * A_STRIDE + tg + 4]);
            }
            #pragma unroll
            for (int ni = 0; ni < NI; ni++) {
                if (KN) {
                    const float* bp = Bb + (kk + tg) * B_STRIDE + n_base + ni * 8 + g;
                    bfr[ni][0] = __float_as_uint(bp[0]);
                    bfr[ni][1] = __float_as_uint(bp[4 * B_STRIDE]);
                } else {
                    const float* bp = Bb + (n_base + ni * 8 + g) * B_STRIDE + kk;
                    bfr[ni][0] = __float_as_uint(bp[tg]);
                    bfr[ni][1] = __float_as_uint(bp[tg + 4]);
                }
            }
            #pragma unroll
            for (int mi = 0; mi < MI; mi++)
                #pragma unroll
                for (int ni = 0; ni < NI; ni++)
                    mma_tf32(acc[mi][ni], afr[mi], bfr[ni]);
        }
        __syncthreads();
    }

    #pragma unroll
    for (int mi = 0; mi < MI; mi++) {
        int row0 = bm + m_base + mi * 16 + g;
        float2 ml0 = stats[(long)blockIdx.z * Tn + row0];
        float2 ml1 = stats[(long)blockIdx.z * Tn + row0 + 8];
        float i0 = 1.f / ml0.y, i1 = 1.f / ml1.y;
        #pragma unroll
        for (int ni = 0; ni < NI; ni++) {
            int col = bn + n_base + ni * 8 + tg * 2;
            float v0 = expf(acc[mi][ni][0] * alpha - ml0.x) * i0;
            float v1 = expf(acc[mi][ni][1] * alpha - ml0.x) * i0;
            float v2 = expf(acc[mi][ni][2] * alpha - ml1.x) * i1;
            float v3 = expf(acc[mi][ni][3] * alpha - ml1.x) * i1;
            *(float2*)&C[(long)row0 * ldc_m + col]       = make_float2(v0, v1);
            *(float2*)&C[(long)(row0 + 8) * ldc_m + col] = make_float2(v2, v3);
        }
    }
}

// ======================= out = LayerNorm(x+res)*g+b ; optional half copy
__global__ __launch_bounds__(256) void add_ln_kernel(
    const float* __restrict__ x, const float* __restrict__ res,
    const float* __restrict__ g, const float* __restrict__ b,
    float* __restrict__ out, __half* __restrict__ out_r)
{
    const long row = (long)blockIdx.x * En;
    const int tid = threadIdx.x;
    float v[4]; float s = 0.f, s2 = 0.f;
    #pragma unroll
    for (int j = 0; j < 4; j++) {
        int i = tid + j * 256;
        float val = x[row + i] + res[row + i];
        v[j] = val; s += val; s2 += val * val;
    }
    __shared__ float sh1[8], sh2[8];
    #pragma unroll
    for (int o = 16; o; o >>= 1) {
        s  += __shfl_xor_sync(0xffffffffu, s, o);
        s2 += __shfl_xor_sync(0xffffffffu, s2, o);
    }
    if ((tid & 31) == 0) { sh1[tid >> 5] = s; sh2[tid >> 5] = s2; }
    __syncthreads();
    float ts = 0.f, ts2 = 0.f;
    #pragma unroll
    for (int w = 0; w < 8; w++) { ts += sh1[w]; ts2 += sh2[w]; }
    const float mu  = ts * (1.f / En);
    const float var = ts2 * (1.f / En) - mu * mu;
    const float inv = rsqrtf(var + 1e-5f);
    #pragma unroll
    for (int j = 0; j < 4; j++) {
        int i = tid + j * 256;
        float o = (v[j] - mu) * inv * g[i] + b[i];
        out[row + i] = o;
        if (out_r) out_r[row + i] = __float2half_rn(o);
    }
}

// ======================= fused fp16 conversion pass =======================
#define NCVT 12
struct CvtJobs {
    const float4* src[NCVT];
    uint2* dst[NCVT];
    int cum[NCVT + 1];
};
__global__ __launch_bounds__(256) void cvt_multi(CvtJobs cj, int total4)
{
    for (int i = blockIdx.x * 256 + threadIdx.x; i < total4; i += gridDim.x * 256) {
        int job = 0;
        #pragma unroll
        for (int t = 0; t < NCVT - 1; t++) if (i >= cj.cum[t + 1]) job = t + 1;
        int off = i - cj.cum[job];
        float4 v = cj.src[job][off];
        __half2 h0 = __floats2half2_rn(v.x, v.y);
        __half2 h1 = __floats2half2_rn(v.z, v.w);
        uint2 u;
        u.x = *(uint32_t*)&h0;
        u.y = *(uint32_t*)&h1;
        cj.dst[job][off] = u;
    }
}

// ======================= host-side =======================
#define SMEM128 ((2*128*36 + 2*128*36) * 4)

static inline void gh(JobsH jobs, int M, int N, int K, int njobs, int postop)
{
    dim3 grid(N / 128, M / 128, njobs);
    hgemm2<<<grid, 128, H2_SMEM>>>(jobs, K, N, postop);
}

extern "C" void kernel_launch(void* const* d_in, const int* in_sizes, int n_in,
                              void* d_out, int out_size)
{
    static bool attr_done = false;
    if (!attr_done) {
        cudaFuncSetAttribute((const void*)hgemm2,
                             cudaFuncAttributeMaxDynamicSharedMemorySize, H2_SMEM);
        cudaFuncSetAttribute((const void*)tgemm<128, false>,
                             cudaFuncAttributeMaxDynamicSharedMemorySize, SMEM128);
        cudaFuncSetAttribute((const void*)flash_kernel<true>,
                             cudaFuncAttributeMaxDynamicSharedMemorySize, FL_SMEM);
        cudaFuncSetAttribute((const void*)flash_kernel<false>,
                             cudaFuncAttributeMaxDynamicSharedMemorySize, FL_SMEM);
        attr_done = true;
    }

    const float* state = (const float*)d_in[0];
    const float* enc   = (const float*)d_in[1];
    const float* sa_wq = (const float*)d_in[3];  const float* sa_bq = (const float*)d_in[4];
    const float* sa_wk = (const float*)d_in[5];  const float* sa_bk = (const float*)d_in[6];
    const float* sa_wv = (const float*)d_in[7];  const float* sa_bv = (const float*)d_in[8];
    const float* sa_wo = (const float*)d_in[9];  const float* sa_bo = (const float*)d_in[10];
    const float* ea_wq = (const float*)d_in[11]; const float* ea_bq = (const float*)d_in[12];
    const float* ea_wk = (const float*)d_in[13]; const float* ea_bk = (const float*)d_in[14];
    const float* ea_wv = (const float*)d_in[15]; const float* ea_bv = (const float*)d_in[16];
    const float* ea_wo = (const float*)d_in[17]; const float* ea_bo = (const float*)d_in[18];
    const float* fc1_w = (const float*)d_in[19]; const float* fc1_b = (const float*)d_in[20];
    const float* fc2_w = (const float*)d_in[21]; const float* fc2_b = (const float*)d_in[22];
    const float* ln1_g = (const float*)d_in[23]; const float* ln1_b = (const float*)d_in[24];
    const float* ln2_g = (const float*)d_in[25]; const float* ln2_b = (const float*)d_in[26];
    const float* ln3_g = (const float*)d_in[27]; const float* ln3_b = (const float*)d_in[28];

    float *xq, *xk, *xv, *tmp, *st1, *st2, *rw;
    float *attn_f, *st1r_f, *st2r_f, *ffn_f;
    float2* stats;
    cudaGetSymbolAddress((void**)&xq,     g_xq);
    cudaGetSymbolAddress((void**)&xk,     g_xk);
    cudaGetSymbolAddress((void**)&xv,     g_xv);
    cudaGetSymbolAddress((void**)&attn_f, g_attn);
    cudaGetSymbolAddress((void**)&tmp,    g_tmp);
    cudaGetSymbolAddress((void**)&st1,    g_state1);
    cudaGetSymbolAddress((void**)&st2,    g_state2);
    cudaGetSymbolAddress((void**)&st1r_f, g_st1r);
    cudaGetSymbolAddress((void**)&st2r_f, g_st2r);
    cudaGetSymbolAddress((void**)&ffn_f,  g_ffn);
    cudaGetSymbolAddress((void**)&stats,  g_stats);
    cudaGetSymbolAddress((void**)&rw,     g_rw);

    __half* attn_h = (__half*)attn_f;
    __half* st1r_h = (__half*)st1r_f;
    __half* st2r_h = (__half*)st2r_f;
    __half* ffn_h  = (__half*)ffn_f;
    __half* hp = (__half*)rw;
    __half* h_state = hp + 0L  * MEG;
    __half* h_enc   = hp + 4L  * MEG;
    __half* h_saq   = hp + 8L  * MEG;
    __half* h_sak   = hp + 9L  * MEG;
    __half* h_sav   = hp + 10L * MEG;
    __half* h_sao   = hp + 11L * MEG;
    __half* h_eaq   = hp + 12L * MEG;
    __half* h_eak   = hp + 13L * MEG;
    __half* h_eav   = hp + 14L * MEG;
    __half* h_eao   = hp + 15L * MEG;
    __half* h_fc1   = hp + 16L * MEG;
    __half* h_fc2   = hp + 20L * MEG;

    float* out_state = (float*)d_out;
    float* out_attn  = (float*)d_out + (long)Tn * Bn * En;

    const float sc = 1.0f / 8.0f;
    const long BE = (long)Bn * En;
    const long TS = (long)Tn * Sn;

    // -------- fused fp16 conversion pass --------
    {
        CvtJobs cj;
        const float* srcs[NCVT] = {state, enc, sa_wq, sa_wk, sa_wv, sa_wo,
                                   ea_wq, ea_wk, ea_wv, ea_wo, fc1_w, fc2_w};
        __half* dsts[NCVT] = {h_state, h_enc, h_saq, h_sak, h_sav, h_sao,
                              h_eaq, h_eak, h_eav, h_eao, h_fc1, h_fc2};
        const int n4s[NCVT] = {MEG, MEG, MEG/4, MEG/4, MEG/4, MEG/4,
                               MEG/4, MEG/4, MEG/4, MEG/4, MEG, MEG};
        int c = 0;
        for (int i = 0; i < NCVT; i++) {
            cj.src[i] = (const float4*)srcs[i];
            cj.dst[i] = (uint2*)dsts[i];
            cj.cum[i] = c;
            c += n4s[i];
        }
        cj.cum[NCVT] = c;
        cvt_multi<<<1024, 256>>>(cj, c);
    }

    // ---------------- self-attention (fused flash, causal) ----------------
    {
        JobsH j = {{{h_state, h_saq, sa_bq, xq},
                    {h_state, h_sak, sa_bk, xk},
                    {h_state, h_sav, sa_bv, xv}}};
        gh(j, ROWS, En, En, 3, 2);
    }
    flash_kernel<true><<<dim3(Tn / 128, BH), 256, FL_SMEM>>>(xq, xk, xv, attn_h, nullptr);
    {
        JobsH j = {{{attn_h, h_sao, sa_bo, tmp}, {}, {}}};
        gh(j, ROWS, En, En, 1, 0);
    }
    add_ln_kernel<<<ROWS, 256>>>(tmp, state, ln1_g, ln1_b, st1, st1r_h);

    // ---------------- encoder-decoder attention ----------------
    {
        JobsH j = {{{st1r_h, h_eaq, ea_bq, xq},
                    {h_enc,  h_eak, ea_bk, xk},
                    {h_enc,  h_eav, ea_bv, xv}}};
        gh(j, ROWS, En, En, 3, 2);
    }
    flash_kernel<false><<<dim3(Tn / 128, BH), 256, FL_SMEM>>>(xq, xk, xv, attn_h, stats);
    // normalized attention weights straight into d_out
    {
        dim3 grid(Sn / 128, Tn / 128, BH);
        tgemm<128, false><<<grid, 256, SMEM128>>>(xq, xk, stats, out_attn, DHn,
                                                  BE, DHn, BE, 1, DHn, Sn, TS, sc);
    }
    {
        JobsH j = {{{attn_h, h_eao, ea_bo, tmp}, {}, {}}};
        gh(j, ROWS, En, En, 1, 0);
    }
    add_ln_kernel<<<ROWS, 256>>>(tmp, st1, ln2_g, ln2_b, st2, st2r_h);

    // ---------------- FFN ----------------
    {
        JobsH j = {{{st2r_h, h_fc1, fc1_b, ffn_h}, {}, {}}};
        gh(j, ROWS, FFn, En, 1, 1);
    }
    {
        JobsH j = {{{ffn_h, h_fc2, fc2_b, tmp}, {}, {}}};
        gh(j, ROWS, En, FFn, 1, 0);
    }
    add_ln_kernel<<<ROWS, 256>>>(tmp, st2, ln3_g, ln3_b, out_state, nullptr);
}

// round 10
// speedup vs baseline: 6.9290x; 1.2261x over previous
#include <cuda_runtime.h>
#include <cuda_fp16.h>
#include <math.h>
#include <stdint.h>

// Problem dims
#define Tn 1024
#define Sn 1024
#define Bn 4
#define En 1024
#define Hn 16
#define DHn 64
#define FFn 4096
#define ROWS (Tn*Bn)
#define BH (Bn*Hn)
#define MEG (1024*1024)

// -------- scratch (device globals; no allocation) --------
__device__ float g_xq[ROWS*En];        // used as __half
__device__ float g_xk[ROWS*En];        // used as __half
__device__ float g_xv[ROWS*En];        // used as __half
__device__ float g_attn[ROWS*En];      // used as __half
__device__ float g_tmp[ROWS*En];
__device__ float g_state1[ROWS*En];
__device__ float g_state2[ROWS*En];
__device__ float g_st1r[ROWS*En];      // used as __half
__device__ float g_st2r[ROWS*En];      // used as __half
__device__ float g_ffn[ROWS*FFn];      // used as __half
__device__ float2 g_stats[BH*Tn];
__device__ float g_rw[24*MEG];         // used as __half pool

// ======================= helpers =======================
__device__ __forceinline__ void mma_f16(float* c, const uint32_t* a, const uint32_t* b) {
    asm volatile(
        "mma.sync.aligned.m16n8k16.row.col.f32.f16.f16.f32 "
        "{%0,%1,%2,%3}, {%4,%5,%6,%7}, {%8,%9}, {%0,%1,%2,%3};"
        : "+f"(c[0]), "+f"(c[1]), "+f"(c[2]), "+f"(c[3])
        : "r"(a[0]), "r"(a[1]), "r"(a[2]), "r"(a[3]), "r"(b[0]), "r"(b[1]));
}
__device__ __forceinline__ void ldsm4(uint32_t* r, uint32_t addr) {
    asm volatile("ldmatrix.sync.aligned.m8n8.x4.shared.b16 {%0,%1,%2,%3}, [%4];"
        : "=r"(r[0]), "=r"(r[1]), "=r"(r[2]), "=r"(r[3]) : "r"(addr));
}
__device__ __forceinline__ void ldsm4t(uint32_t* r, uint32_t addr) {
    asm volatile("ldmatrix.sync.aligned.m8n8.x4.trans.shared.b16 {%0,%1,%2,%3}, [%4];"
        : "=r"(r[0]), "=r"(r[1]), "=r"(r[2]), "=r"(r[3]) : "r"(addr));
}
__device__ __forceinline__ void cp16(uint32_t dst, const void* src) {
    asm volatile("cp.async.cg.shared.global [%0], [%1], 16;" :: "r"(dst), "l"(src));
}
__device__ __forceinline__ void cp_commit() {
    asm volatile("cp.async.commit_group;" ::: "memory");
}
__device__ __forceinline__ void cp_wait0() {
    asm volatile("cp.async.wait_group 0;" ::: "memory");
}
__device__ __forceinline__ uint32_t smaddr(const void* p) {
    return (uint32_t)__cvta_generic_to_shared(p);
}

// ======================= hgemm2: fp16 MMA + ldmatrix, 64x64 warp tiles ============
// C[m,n] = sum_k A[m,k]*B[n,k] + bias[n]; A:[M,K] half; B:[N,K] half.
// 128 threads, 4 warps 2x2, warp tile 64x64. K-slab 64 halfs, 2 stages.
// postop: 0 = fp32 out; 1 = relu -> half out; 2 = half out.
struct JobH { const __half* A; const __half* B; const float* bias; void* C; };
struct JobsH { JobH j[3]; };

#define H2_WS 36                       // words per row (64 halfs + 8 halfs pad)
#define H2_TILEW (128*H2_WS)
#define H2_SMEM (4*H2_TILEW*4)         // 73728

__global__ __launch_bounds__(128, 2) void hgemm2(
    JobsH jobs, int K, int N, int postop)
{
    extern __shared__ uint32_t smw[];
    const int tid  = threadIdx.x;
    const int lane = tid & 31;
    const int wid  = tid >> 5;
    const int wm = wid & 1, wn = wid >> 1;
    const int m_base = wm * 64, n_base = wn * 64;
    const int g  = lane >> 2;
    const int tg = lane & 3;

    const JobH job = jobs.j[blockIdx.z];
    const int bm = blockIdx.y * 128;
    const int bn = blockIdx.x * 128;
    const __half* A = job.A + (long)bm * K;
    const __half* B = job.B + (long)bn * K;

    const int r0 = tid >> 3, c8 = tid & 7;
    const __half* aPtr = A + (long)r0 * K + c8 * 8;
    const __half* bPtr = B + (long)r0 * K + c8 * 8;
    const uint32_t aSm = smaddr(smw + r0 * H2_WS + c8 * 4);
    const uint32_t bSm = smaddr(smw + H2_TILEW + r0 * H2_WS + c8 * 4);
    const long rowAdv = 16L * K;

    auto load_slab = [&](int st) {
        const uint32_t so = st * (2 * H2_TILEW * 4);
        #pragma unroll
        for (int it = 0; it < 8; it++) {
            cp16(aSm + so + it * (16 * H2_WS * 4), aPtr + it * rowAdv);
            cp16(bSm + so + it * (16 * H2_WS * 4), bPtr + it * rowAdv);
        }
        cp_commit();
    };

    uint32_t aLd[4];
    {
        int rowl = lane & 15;
        uint32_t kcb = (lane >> 4) * 16;
        #pragma unroll
        for (int mi = 0; mi < 4; mi++)
            aLd[mi] = smaddr(smw + (m_base + mi * 16 + rowl) * H2_WS) + kcb;
    }
    uint32_t bLd[4];
    {
        int rowl = (lane & 7) + ((lane >> 4) * 8);
        uint32_t kcb = ((lane >> 3) & 1) * 16;
        #pragma unroll
        for (int p = 0; p < 4; p++)
            bLd[p] = smaddr(smw + H2_TILEW + (n_base + p * 16 + rowl) * H2_WS) + kcb;
    }

    float acc[4][8][4];
    #pragma unroll
    for (int mi = 0; mi < 4; mi++)
        #pragma unroll
        for (int ni = 0; ni < 8; ni++)
            #pragma unroll
            for (int r = 0; r < 4; r++) acc[mi][ni][r] = 0.f;

    const int nslab = K >> 6;
    load_slab(0);

    for (int s = 0; s < nslab; s++) {
        cp_wait0();
        __syncthreads();
        aPtr += 64; bPtr += 64;
        if (s + 1 < nslab) load_slab((s + 1) & 1);

        const uint32_t so = (s & 1) * (2 * H2_TILEW * 4);

        #pragma unroll
        for (int kw = 0; kw < 32; kw += 8) {
            uint32_t afr[4][4], bfr[4][4];
            #pragma unroll
            for (int mi = 0; mi < 4; mi++) ldsm4(afr[mi], aLd[mi] + so + kw * 4);
            #pragma unroll
            for (int p = 0; p < 4; p++)    ldsm4(bfr[p], bLd[p] + so + kw * 4);
            #pragma unroll
            for (int mi = 0; mi < 4; mi++)
                #pragma unroll
                for (int ni = 0; ni < 8; ni++) {
                    uint32_t bq[2] = { bfr[ni >> 1][(ni & 1) * 2],
                                       bfr[ni >> 1][(ni & 1) * 2 + 1] };
                    mma_f16(acc[mi][ni], afr[mi], bq);
                }
        }
        __syncthreads();
    }

    const float* bias = job.bias;
    #pragma unroll
    for (int mi = 0; mi < 4; mi++) {
        int row0 = bm + m_base + mi * 16 + g;
        #pragma unroll
        for (int ni = 0; ni < 8; ni++) {
            int col = bn + n_base + ni * 8 + tg * 2;
            float b0 = bias[col], b1 = bias[col + 1];
            float v0 = acc[mi][ni][0] + b0;
            float v1 = acc[mi][ni][1] + b1;
            float v2 = acc[mi][ni][2] + b0;
            float v3 = acc[mi][ni][3] + b1;
            if (postop == 0) {
                float* C = (float*)job.C;
                *(float2*)&C[(long)row0 * N + col]       = make_float2(v0, v1);
                *(float2*)&C[(long)(row0 + 8) * N + col] = make_float2(v2, v3);
            } else {
                if (postop == 1) {
                    v0 = fmaxf(v0, 0.f); v1 = fmaxf(v1, 0.f);
                    v2 = fmaxf(v2, 0.f); v3 = fmaxf(v3, 0.f);
                }
                __half* C = (__half*)job.C;
                *(__half2*)&C[(long)row0 * N + col]       = __floats2half2_rn(v0, v1);
                *(__half2*)&C[(long)(row0 + 8) * N + col] = __floats2half2_rn(v2, v3);
            }
        }
    }
}

// ======================= fp16 fused flash attention =======================
// Q/K/V/O: half [t][4096], head offset bh*64. S tile 64, Q tile 128, 8 warps.
// smem words: Qs 0..4608, Ks 4608 (2x2304), Vs 9216 (2x2304), Ps 13824.
#define FLH_SMEM (18432*4)

template<bool CAUSAL>
__global__ __launch_bounds__(256, 2) void flash_h(
    const __half* __restrict__ Qp, const __half* __restrict__ Kp,
    const __half* __restrict__ Vp, __half* __restrict__ Op,
    float2* __restrict__ stats)
{
    extern __shared__ uint32_t smw[];
    const int tid = threadIdx.x;
    const int lane = tid & 31, w = tid >> 5;
    const int g = lane >> 2, tg = lane & 3;
    const int bh = blockIdx.y;
    const int it = CAUSAL ? ((int)gridDim.x - 1 - (int)blockIdx.x) : (int)blockIdx.x;
    const int t0 = it * 128;
    const int nIter = CAUSAL ? 2 * it + 2 : 16;

    const __half* Qg = Qp + (long)t0 * 4096 + bh * 64;
    const __half* Kg = Kp + bh * 64;
    const __half* Vg = Vp + bh * 64;

    auto loadKV = [&](int j, int buf) {
        const long s0 = (long)j * 64;
        const uint32_t kb = smaddr(smw + 4608 + buf * 2304);
        const uint32_t vb = smaddr(smw + 9216 + buf * 2304);
        #pragma unroll
        for (int i = 0; i < 2; i++) {
            int idx = tid + i * 256;
            int row = idx >> 3, c = idx & 7;
            cp16(kb + row * 144 + c * 16, Kg + (s0 + row) * 4096 + c * 8);
            cp16(vb + row * 144 + c * 16, Vg + (s0 + row) * 4096 + c * 8);
        }
    };

    #pragma unroll
    for (int i = 0; i < 4; i++) {
        int idx = tid + i * 256;
        int row = idx >> 3, c = idx & 7;
        cp16(smaddr(smw) + row * 144 + c * 16, Qg + (long)row * 4096 + c * 8);
    }
    loadKV(0, 0);
    cp_commit();
    cp_wait0();
    __syncthreads();

    // Q fragments (A operand), preloaded once
    uint32_t qf[4][4];
    {
        uint32_t qbase = smaddr(smw) + (16 * w + (lane & 15)) * 144 + (lane >> 4) * 16;
        #pragma unroll
        for (int kk = 0; kk < 4; kk++) ldsm4(qf[kk], qbase + kk * 32);
    }
    // K fragment addresses (B operand, non-trans; [n=s][k=d] storage)
    uint32_t kbl[4];
    {
        int rowl = (lane & 7) + ((lane >> 4) * 8);
        uint32_t kcb = ((lane >> 3) & 1) * 16;
        #pragma unroll
        for (int p = 0; p < 4; p++)
            kbl[p] = smaddr(smw + 4608) + (p * 16 + rowl) * 144 + kcb;
    }
    // V fragment addresses (B operand, TRANS; [k=s][n=d] storage)
    uint32_t vbl[4];
    {
        int rowv = (lane & 7) + (((lane >> 3) & 1) * 8);
        uint32_t kcv = (lane >> 4) * 16;
        #pragma unroll
        for (int p = 0; p < 4; p++)
            vbl[p] = smaddr(smw + 9216) + rowv * 144 + kcv + p * 32;
    }
    // P (A operand for PV)
    uint32_t pbase = smaddr(smw + 13824) + (16 * w + (lane & 15)) * 144 + (lane >> 4) * 16;
    __half* Pw = (__half*)(smw + 13824) + (16 * w + g) * 72;

    float acc_o[8][4];
    #pragma unroll
    for (int ni = 0; ni < 8; ni++)
        #pragma unroll
        for (int r = 0; r < 4; r++) acc_o[ni][r] = 0.f;
    float m0 = -1e30f, m1 = -1e30f, l0 = 0.f, l1 = 0.f;

    for (int j = 0; j < nIter; j++) {
        const int buf = j & 1;
        const uint32_t bofs = buf * 9216;   // 2304 words
        if (j + 1 < nIter) { loadKV(j + 1, buf ^ 1); cp_commit(); }

        // ---- S = Q K^T ----
        float s_acc[8][4];
        #pragma unroll
        for (int ni = 0; ni < 8; ni++)
            #pragma unroll
            for (int r = 0; r < 4; r++) s_acc[ni][r] = 0.f;
        #pragma unroll
        for (int kk = 0; kk < 4; kk++) {
            uint32_t kfr[4][4];
            #pragma unroll
            for (int p = 0; p < 4; p++) ldsm4(kfr[p], kbl[p] + bofs + kk * 32);
            #pragma unroll
            for (int ni = 0; ni < 8; ni++) {
                uint32_t bq[2] = { kfr[ni >> 1][(ni & 1) * 2],
                                   kfr[ni >> 1][(ni & 1) * 2 + 1] };
                mma_f16(s_acc[ni], qf[kk], bq);
            }
        }

        // ---- scale + mask + online softmax ----
        const int s0 = j * 64;
        const bool need = CAUSAL && (s0 + 63 > t0 + 16 * w);
        const int tr0 = t0 + 16 * w + g, tr1 = tr0 + 8;
        float mx0 = -1e30f, mx1 = -1e30f;
        #pragma unroll
        for (int ni = 0; ni < 8; ni++) {
            float v0 = s_acc[ni][0] * 0.125f;
            float v1 = s_acc[ni][1] * 0.125f;
            float v2 = s_acc[ni][2] * 0.125f;
            float v3 = s_acc[ni][3] * 0.125f;
            if (need) {
                int c0 = s0 + ni * 8 + 2 * tg, c1 = c0 + 1;
                if (c0 > tr0) v0 -= 1e9f;
                if (c1 > tr0) v1 -= 1e9f;
                if (c0 > tr1) v2 -= 1e9f;
                if (c1 > tr1) v3 -= 1e9f;
            }
            s_acc[ni][0] = v0; s_acc[ni][1] = v1;
            s_acc[ni][2] = v2; s_acc[ni][3] = v3;
            mx0 = fmaxf(mx0, fmaxf(v0, v1));
            mx1 = fmaxf(mx1, fmaxf(v2, v3));
        }
        mx0 = fmaxf(mx0, __shfl_xor_sync(0xffffffffu, mx0, 1));
        mx0 = fmaxf(mx0, __shfl_xor_sync(0xffffffffu, mx0, 2));
        mx1 = fmaxf(mx1, __shfl_xor_sync(0xffffffffu, mx1, 1));
        mx1 = fmaxf(mx1, __shfl_xor_sync(0xffffffffu, mx1, 2));
        const float mn0 = fmaxf(m0, mx0), mn1 = fmaxf(m1, mx1);
        const float sc0 = expf(m0 - mn0), sc1 = expf(m1 - mn1);
        m0 = mn0; m1 = mn1;

        float sum0 = 0.f, sum1 = 0.f;
        #pragma unroll
        for (int ni = 0; ni < 8; ni++) {
            float p0 = expf(s_acc[ni][0] - m0);
            float p1 = expf(s_acc[ni][1] - m0);
            float p2 = expf(s_acc[ni][2] - m1);
            float p3 = expf(s_acc[ni][3] - m1);
            sum0 += p0 + p1; sum1 += p2 + p3;
            *(__half2*)&Pw[ni * 8 + 2 * tg]          = __floats2half2_rn(p0, p1);
            *(__half2*)&Pw[8 * 72 + ni * 8 + 2 * tg] = __floats2half2_rn(p2, p3);
        }
        sum0 += __shfl_xor_sync(0xffffffffu, sum0, 1);
        sum0 += __shfl_xor_sync(0xffffffffu, sum0, 2);
        sum1 += __shfl_xor_sync(0xffffffffu, sum1, 1);
        sum1 += __shfl_xor_sync(0xffffffffu, sum1, 2);
        l0 = l0 * sc0 + sum0;
        l1 = l1 * sc1 + sum1;
        #pragma unroll
        for (int ni = 0; ni < 8; ni++) {
            acc_o[ni][0] *= sc0; acc_o[ni][1] *= sc0;
            acc_o[ni][2] *= sc1; acc_o[ni][3] *= sc1;
        }
        __syncwarp();   // P rows are warp-private

        // ---- O += P V ----
        #pragma unroll
        for (int kk = 0; kk < 4; kk++) {
            uint32_t pf[4];
            ldsm4(pf, pbase + kk * 32);
            uint32_t vfr[4][4];
            #pragma unroll
            for (int p = 0; p < 4; p++) ldsm4t(vfr[p], vbl[p] + bofs + kk * 2304);
            #pragma unroll
            for (int ni = 0; ni < 8; ni++) {
                uint32_t bq[2] = { vfr[ni >> 1][(ni & 1) * 2],
                                   vfr[ni >> 1][(ni & 1) * 2 + 1] };
                mma_f16(acc_o[ni], pf, bq);
            }
        }
        if (j + 1 < nIter) cp_wait0();
        __syncthreads();
    }

    const float inv0 = 1.f / l0, inv1 = 1.f / l1;
    const int r0 = t0 + 16 * w + g;
    __half* o0 = Op + (long)r0 * 4096 + bh * 64;
    __half* o1 = o0 + 8L * 4096;
    #pragma unroll
    for (int ni = 0; ni < 8; ni++) {
        *(__half2*)&o0[ni * 8 + 2 * tg] =
            __floats2half2_rn(acc_o[ni][0] * inv0, acc_o[ni][1] * inv0);
        *(__half2*)&o1[ni * 8 + 2 * tg] =
            __floats2half2_rn(acc_o[ni][2] * inv1, acc_o[ni][3] * inv1);
    }
    if (!CAUSAL && tg == 0) {
        stats[bh * Tn + r0]     = make_float2(m0, l0);
        stats[bh * Tn + r0 + 8] = make_float2(m1, l1);
    }
}

// ======================= wgemm: EA normalized attention weights ============
// C[z, t, s] = exp(q.k/8 - m)/l ; Q/K half [t][4096] head offset z*64.
// grid (Sn/128, Tn/128, BH), 256 threads, warp tile 64x32, K=64 single slab.
#define WG_SMEM (9216*4)

__global__ __launch_bounds__(256, 2) void wgemm(
    const __half* __restrict__ Qh, const __half* __restrict__ Kh,
    const float2* __restrict__ stats, float* __restrict__ C)
{
    extern __shared__ uint32_t smw[];
    const int tid  = threadIdx.x;
    const int lane = tid & 31;
    const int wid  = tid >> 5;
    const int wm = wid & 1, wn = wid >> 1;
    const int m_base = wm * 64, n_base = wn * 32;
    const int g  = lane >> 2;
    const int tg = lane & 3;
    const int z  = blockIdx.z;
    const int bm = blockIdx.y * 128;
    const int bn = blockIdx.x * 128;

    const __half* A = Qh + (long)z * 64 + (long)bm * 4096;
    const __half* B = Kh + (long)z * 64 + (long)bn * 4096;

    #pragma unroll
    for (int i = 0; i < 4; i++) {
        int idx = tid + i * 256;
        int row = idx >> 3, c = idx & 7;
        cp16(smaddr(smw) + row * 144 + c * 16, A + (long)row * 4096 + c * 8);
        cp16(smaddr(smw + 4608) + row * 144 + c * 16, B + (long)row * 4096 + c * 8);
    }
    cp_commit();
    cp_wait0();
    __syncthreads();

    uint32_t aLd[4], bLd[2];
    {
        int rowl = lane & 15;
        uint32_t kcb = (lane >> 4) * 16;
        #pragma unroll
        for (int mi = 0; mi < 4; mi++)
            aLd[mi] = smaddr(smw) + (m_base + mi * 16 + rowl) * 144 + kcb;
    }
    {
        int rowl = (lane & 7) + ((lane >> 4) * 8);
        uint32_t kcb = ((lane >> 3) & 1) * 16;
        #pragma unroll
        for (int p = 0; p < 2; p++)
            bLd[p] = smaddr(smw + 4608) + (n_base + p * 16 + rowl) * 144 + kcb;
    }

    float acc[4][4][4];
    #pragma unroll
    for (int mi = 0; mi < 4; mi++)
        #pragma unroll
        for (int ni = 0; ni < 4; ni++)
            #pragma unroll
            for (int r = 0; r < 4; r++) acc[mi][ni][r] = 0.f;

    #pragma unroll
    for (int kk = 0; kk < 4; kk++) {
        uint32_t afr[4][4], bfr[2][4];
        #pragma unroll
        for (int mi = 0; mi < 4; mi++) ldsm4(afr[mi], aLd[mi] + kk * 32);
        #pragma unroll
        for (int p = 0; p < 2; p++)    ldsm4(bfr[p], bLd[p] + kk * 32);
        #pragma unroll
        for (int mi = 0; mi < 4; mi++)
            #pragma unroll
            for (int ni = 0; ni < 4; ni++) {
                uint32_t bq[2] = { bfr[ni >> 1][(ni & 1) * 2],
                                   bfr[ni >> 1][(ni & 1) * 2 + 1] };
                mma_f16(acc[mi][ni], afr[mi], bq);
            }
    }

    #pragma unroll
    for (int mi = 0; mi < 4; mi++) {
        int row0 = bm + m_base + mi * 16 + g;
        float2 ml0 = stats[z * Tn + row0];
        float2 ml1 = stats[z * Tn + row0 + 8];
        float i0 = 1.f / ml0.y, i1 = 1.f / ml1.y;
        #pragma unroll
        for (int ni = 0; ni < 4; ni++) {
            int col = bn + n_base + ni * 8 + tg * 2;
            float v0 = expf(acc[mi][ni][0] * 0.125f - ml0.x) * i0;
            float v1 = expf(acc[mi][ni][1] * 0.125f - ml0.x) * i0;
            float v2 = expf(acc[mi][ni][2] * 0.125f - ml1.x) * i1;
            float v3 = expf(acc[mi][ni][3] * 0.125f - ml1.x) * i1;
            float* Cz = C + (long)z * Tn * Sn;
            *(float2*)&Cz[(long)row0 * Sn + col]       = make_float2(v0, v1);
            *(float2*)&Cz[(long)(row0 + 8) * Sn + col] = make_float2(v2, v3);
        }
    }
}

// ======================= out = LayerNorm(x+res)*g+b ; optional half copy
__global__ __launch_bounds__(256) void add_ln_kernel(
    const float* __restrict__ x, const float* __restrict__ res,
    const float* __restrict__ g, const float* __restrict__ b,
    float* __restrict__ out, __half* __restrict__ out_r)
{
    const long row = (long)blockIdx.x * En;
    const int tid = threadIdx.x;
    float v[4]; float s = 0.f, s2 = 0.f;
    #pragma unroll
    for (int j = 0; j < 4; j++) {
        int i = tid + j * 256;
        float val = x[row + i] + res[row + i];
        v[j] = val; s += val; s2 += val * val;
    }
    __shared__ float sh1[8], sh2[8];
    #pragma unroll
    for (int o = 16; o; o >>= 1) {
        s  += __shfl_xor_sync(0xffffffffu, s, o);
        s2 += __shfl_xor_sync(0xffffffffu, s2, o);
    }
    if ((tid & 31) == 0) { sh1[tid >> 5] = s; sh2[tid >> 5] = s2; }
    __syncthreads();
    float ts = 0.f, ts2 = 0.f;
    #pragma unroll
    for (int w = 0; w < 8; w++) { ts += sh1[w]; ts2 += sh2[w]; }
    const float mu  = ts * (1.f / En);
    const float var = ts2 * (1.f / En) - mu * mu;
    const float inv = rsqrtf(var + 1e-5f);
    #pragma unroll
    for (int j = 0; j < 4; j++) {
        int i = tid + j * 256;
        float o = (v[j] - mu) * inv * g[i] + b[i];
        out[row + i] = o;
        if (out_r) out_r[row + i] = __float2half_rn(o);
    }
}

// ======================= fused fp16 conversion pass =======================
#define NCVT 12
struct CvtJobs {
    const float4* src[NCVT];
    uint2* dst[NCVT];
    int cum[NCVT + 1];
};
__global__ __launch_bounds__(256) void cvt_multi(CvtJobs cj, int total4)
{
    for (int i = blockIdx.x * 256 + threadIdx.x; i < total4; i += gridDim.x * 256) {
        int job = 0;
        #pragma unroll
        for (int t = 0; t < NCVT - 1; t++) if (i >= cj.cum[t + 1]) job = t + 1;
        int off = i - cj.cum[job];
        float4 v = cj.src[job][off];
        __half2 h0 = __floats2half2_rn(v.x, v.y);
        __half2 h1 = __floats2half2_rn(v.z, v.w);
        uint2 u;
        u.x = *(uint32_t*)&h0;
        u.y = *(uint32_t*)&h1;
        cj.dst[job][off] = u;
    }
}

// ======================= host-side =======================
static inline void gh(JobsH jobs, int M, int N, int K, int njobs, int postop)
{
    dim3 grid(N / 128, M / 128, njobs);
    hgemm2<<<grid, 128, H2_SMEM>>>(jobs, K, N, postop);
}

extern "C" void kernel_launch(void* const* d_in, const int* in_sizes, int n_in,
                              void* d_out, int out_size)
{
    static bool attr_done = false;
    if (!attr_done) {
        cudaFuncSetAttribute((const void*)hgemm2,
                             cudaFuncAttributeMaxDynamicSharedMemorySize, H2_SMEM);
        cudaFuncSetAttribute((const void*)flash_h<true>,
                             cudaFuncAttributeMaxDynamicSharedMemorySize, FLH_SMEM);
        cudaFuncSetAttribute((const void*)flash_h<false>,
                             cudaFuncAttributeMaxDynamicSharedMemorySize, FLH_SMEM);
        cudaFuncSetAttribute((const void*)wgemm,
                             cudaFuncAttributeMaxDynamicSharedMemorySize, WG_SMEM);
        attr_done = true;
    }

    const float* state = (const float*)d_in[0];
    const float* enc   = (const float*)d_in[1];
    const float* sa_wq = (const float*)d_in[3];  const float* sa_bq = (const float*)d_in[4];
    const float* sa_wk = (const float*)d_in[5];  const float* sa_bk = (const float*)d_in[6];
    const float* sa_wv = (const float*)d_in[7];  const float* sa_bv = (const float*)d_in[8];
    const float* sa_wo = (const float*)d_in[9];  const float* sa_bo = (const float*)d_in[10];
    const float* ea_wq = (const float*)d_in[11]; const float* ea_bq = (const float*)d_in[12];
    const float* ea_wk = (const float*)d_in[13]; const float* ea_bk = (const float*)d_in[14];
    const float* ea_wv = (const float*)d_in[15]; const float* ea_bv = (const float*)d_in[16];
    const float* ea_wo = (const float*)d_in[17]; const float* ea_bo = (const float*)d_in[18];
    const float* fc1_w = (const float*)d_in[19]; const float* fc1_b = (const float*)d_in[20];
    const float* fc2_w = (const float*)d_in[21]; const float* fc2_b = (const float*)d_in[22];
    const float* ln1_g = (const float*)d_in[23]; const float* ln1_b = (const float*)d_in[24];
    const float* ln2_g = (const float*)d_in[25]; const float* ln2_b = (const float*)d_in[26];
    const float* ln3_g = (const float*)d_in[27]; const float* ln3_b = (const float*)d_in[28];

    float *xq_f, *xk_f, *xv_f, *tmp, *st1, *st2, *rw;
    float *attn_f, *st1r_f, *st2r_f, *ffn_f;
    float2* stats;
    cudaGetSymbolAddress((void**)&xq_f,   g_xq);
    cudaGetSymbolAddress((void**)&xk_f,   g_xk);
    cudaGetSymbolAddress((void**)&xv_f,   g_xv);
    cudaGetSymbolAddress((void**)&attn_f, g_attn);
    cudaGetSymbolAddress((void**)&tmp,    g_tmp);
    cudaGetSymbolAddress((void**)&st1,    g_state1);
    cudaGetSymbolAddress((void**)&st2,    g_state2);
    cudaGetSymbolAddress((void**)&st1r_f, g_st1r);
    cudaGetSymbolAddress((void**)&st2r_f, g_st2r);
    cudaGetSymbolAddress((void**)&ffn_f,  g_ffn);
    cudaGetSymbolAddress((void**)&stats,  g_stats);
    cudaGetSymbolAddress((void**)&rw,     g_rw);

    __half* xq_h   = (__half*)xq_f;
    __half* xk_h   = (__half*)xk_f;
    __half* xv_h   = (__half*)xv_f;
    __half* attn_h = (__half*)attn_f;
    __half* st1r_h = (__half*)st1r_f;
    __half* st2r_h = (__half*)st2r_f;
    __half* ffn_h  = (__half*)ffn_f;
    __half* hp = (__half*)rw;
    __half* h_state = hp + 0L  * MEG;
    __half* h_enc   = hp + 4L  * MEG;
    __half* h_saq   = hp + 8L  * MEG;
    __half* h_sak   = hp + 9L  * MEG;
    __half* h_sav   = hp + 10L * MEG;
    __half* h_sao   = hp + 11L * MEG;
    __half* h_eaq   = hp + 12L * MEG;
    __half* h_eak   = hp + 13L * MEG;
    __half* h_eav   = hp + 14L * MEG;
    __half* h_eao   = hp + 15L * MEG;
    __half* h_fc1   = hp + 16L * MEG;
    __half* h_fc2   = hp + 20L * MEG;

    float* out_state = (float*)d_out;
    float* out_attn  = (float*)d_out + (long)Tn * Bn * En;

    // -------- fused fp16 conversion pass --------
    {
        CvtJobs cj;
        const float* srcs[NCVT] = {state, enc, sa_wq, sa_wk, sa_wv, sa_wo,
                                   ea_wq, ea_wk, ea_wv, ea_wo, fc1_w, fc2_w};
        __half* dsts[NCVT] = {h_state, h_enc, h_saq, h_sak, h_sav, h_sao,
                              h_eaq, h_eak, h_eav, h_eao, h_fc1, h_fc2};
        const int n4s[NCVT] = {MEG, MEG, MEG/4, MEG/4, MEG/4, MEG/4,
                               MEG/4, MEG/4, MEG/4, MEG/4, MEG, MEG};
        int c = 0;
        for (int i = 0; i < NCVT; i++) {
            cj.src[i] = (const float4*)srcs[i];
            cj.dst[i] = (uint2*)dsts[i];
            cj.cum[i] = c;
            c += n4s[i];
        }
        cj.cum[NCVT] = c;
        cvt_multi<<<1024, 256>>>(cj, c);
    }

    // ---------------- self-attention (fused flash, causal) ----------------
    {
        JobsH j = {{{h_state, h_saq, sa_bq, xq_h},
                    {h_state, h_sak, sa_bk, xk_h},
                    {h_state, h_sav, sa_bv, xv_h}}};
        gh(j, ROWS, En, En, 3, 2);
    }
    flash_h<true><<<dim3(Tn / 128, BH), 256, FLH_SMEM>>>(xq_h, xk_h, xv_h, attn_h, nullptr);
    {
        JobsH j = {{{attn_h, h_sao, sa_bo, tmp}, {}, {}}};
        gh(j, ROWS, En, En, 1, 0);
    }
    add_ln_kernel<<<ROWS, 256>>>(tmp, state, ln1_g, ln1_b, st1, st1r_h);

    // ---------------- encoder-decoder attention ----------------
    {
        JobsH j = {{{st1r_h, h_eaq, ea_bq, xq_h},
                    {h_enc,  h_eak, ea_bk, xk_h},
                    {h_enc,  h_eav, ea_bv, xv_h}}};
        gh(j, ROWS, En, En, 3, 2);
    }
    flash_h<false><<<dim3(Tn / 128, BH), 256, FLH_SMEM>>>(xq_h, xk_h, xv_h, attn_h, stats);
    // normalized attention weights straight into d_out
    wgemm<<<dim3(Sn / 128, Tn / 128, BH), 256, WG_SMEM>>>(xq_h, xk_h, stats, out_attn);
    {
        JobsH j = {{{attn_h, h_eao, ea_bo, tmp}, {}, {}}};
        gh(j, ROWS, En, En, 1, 0);
    }
    add_ln_kernel<<<ROWS, 256>>>(tmp, st1, ln2_g, ln2_b, st2, st2r_h);

    // ---------------- FFN ----------------
    {
        JobsH j = {{{st2r_h, h_fc1, fc1_b, ffn_h}, {}, {}}};
        gh(j, ROWS, FFn, En, 1, 1);
    }
    {
        JobsH j = {{{ffn_h, h_fc2, fc2_b, tmp}, {}, {}}};
        gh(j, ROWS, En, FFn, 1, 0);
    }
    add_ln_kernel<<<ROWS, 256>>>(tmp, st2, ln3_g, ln3_b, out_state, nullptr);
}

// round 11
// speedup vs baseline: 7.0957x; 1.0240x over previous
#include <cuda_runtime.h>
#include <cuda_fp16.h>
#include <math.h>
#include <stdint.h>

// Problem dims
#define Tn 1024
#define Sn 1024
#define Bn 4
#define En 1024
#define Hn 16
#define DHn 64
#define FFn 4096
#define ROWS (Tn*Bn)
#define BH (Bn*Hn)
#define MEG (1024*1024)

// -------- scratch (device globals; no allocation) --------
__device__ float g_xq[ROWS*En];        // used as __half
__device__ float g_xk[ROWS*En];        // used as __half
__device__ float g_xv[ROWS*En];        // used as __half
__device__ float g_attn[ROWS*En];      // used as __half
__device__ float g_tmp[ROWS*En];
__device__ float g_state1[ROWS*En];
__device__ float g_state2[ROWS*En];
__device__ float g_st1r[ROWS*En];      // used as __half
__device__ float g_st2r[ROWS*En];      // used as __half
__device__ float g_ffn[ROWS*FFn];      // used as __half
__device__ float2 g_stats[BH*Tn];
__device__ float g_rw[24*MEG];         // used as __half pool

// ======================= helpers =======================
__device__ __forceinline__ void mma_f16(float* c, const uint32_t* a, const uint32_t* b) {
    asm volatile(
        "mma.sync.aligned.m16n8k16.row.col.f32.f16.f16.f32 "
        "{%0,%1,%2,%3}, {%4,%5,%6,%7}, {%8,%9}, {%0,%1,%2,%3};"
        : "+f"(c[0]), "+f"(c[1]), "+f"(c[2]), "+f"(c[3])
        : "r"(a[0]), "r"(a[1]), "r"(a[2]), "r"(a[3]), "r"(b[0]), "r"(b[1]));
}
__device__ __forceinline__ void ldsm4(uint32_t* r, uint32_t addr) {
    asm volatile("ldmatrix.sync.aligned.m8n8.x4.shared.b16 {%0,%1,%2,%3}, [%4];"
        : "=r"(r[0]), "=r"(r[1]), "=r"(r[2]), "=r"(r[3]) : "r"(addr));
}
__device__ __forceinline__ void ldsm4t(uint32_t* r, uint32_t addr) {
    asm volatile("ldmatrix.sync.aligned.m8n8.x4.trans.shared.b16 {%0,%1,%2,%3}, [%4];"
        : "=r"(r[0]), "=r"(r[1]), "=r"(r[2]), "=r"(r[3]) : "r"(addr));
}
__device__ __forceinline__ void cp16(uint32_t dst, const void* src) {
    asm volatile("cp.async.cg.shared.global [%0], [%1], 16;" :: "r"(dst), "l"(src));
}
__device__ __forceinline__ void cp_commit() {
    asm volatile("cp.async.commit_group;" ::: "memory");
}
__device__ __forceinline__ void cp_wait0() {
    asm volatile("cp.async.wait_group 0;" ::: "memory");
}
__device__ __forceinline__ void cp_wait1() {
    asm volatile("cp.async.wait_group 1;" ::: "memory");
}
__device__ __forceinline__ uint32_t smaddr(const void* p) {
    return (uint32_t)__cvta_generic_to_shared(p);
}

// ======================= hgemm2: fp16 MMA + ldmatrix, 3-stage, 8 warps ============
// C[m,n] = sum_k A[m,k]*B[n,k] + bias[n]; A:[M,K] half; B:[N,K] half.
// 256 threads, 8 warps 2x4, warp tile 64x32. K-slab 64 halfs, 3 cp.async stages.
// postop: 0 = fp32 out; 1 = relu -> half out; 2 = half out.
struct JobH { const __half* A; const __half* B; const float* bias; void* C; };
struct JobsH { JobH j[3]; };

#define H2_WS 36                       // words per row (64 halfs + 8 halfs pad)
#define H2_TILEW (128*H2_WS)           // words per operand tile
#define H2_SMEM (6*H2_TILEW*4)         // 3 stages x (A+B) = 110592

__global__ __launch_bounds__(256, 2) void hgemm2(
    JobsH jobs, int K, int N, int postop)
{
    extern __shared__ uint32_t smw[];
    const int tid  = threadIdx.x;
    const int lane = tid & 31;
    const int wid  = tid >> 5;
    const int wm = wid & 1, wn = wid >> 1;       // 2 x 4 warp grid
    const int m_base = wm * 64, n_base = wn * 32;
    const int g  = lane >> 2;
    const int tg = lane & 3;

    const JobH job = jobs.j[blockIdx.z];
    const int bm = blockIdx.y * 128;
    const int bn = blockIdx.x * 128;
    const __half* A = job.A + (long)bm * K;
    const __half* B = job.B + (long)bn * K;

    const int r0 = tid >> 3, c8 = tid & 7;       // rows 0..31, 8 chunks/row
    const __half* aPtr = A + (long)r0 * K + c8 * 8;
    const __half* bPtr = B + (long)r0 * K + c8 * 8;
    const uint32_t aSm = smaddr(smw + r0 * H2_WS + c8 * 4);
    const uint32_t bSm = smaddr(smw + H2_TILEW + r0 * H2_WS + c8 * 4);
    const long rowAdv = 32L * K;

    auto load_slab = [&](int s, int st) {
        const uint32_t so = st * (2 * H2_TILEW * 4);
        const __half* ap = aPtr + s * 64;
        const __half* bp = bPtr + s * 64;
        #pragma unroll
        for (int it = 0; it < 4; it++) {
            cp16(aSm + so + it * (32 * H2_WS * 4), ap + it * rowAdv);
            cp16(bSm + so + it * (32 * H2_WS * 4), bp + it * rowAdv);
        }
        cp_commit();
    };

    // ldmatrix per-lane addresses (stage 0 base; add stage offset at use)
    uint32_t aLd[4];
    {
        int rowl = lane & 15;
        uint32_t kcb = (lane >> 4) * 16;
        #pragma unroll
        for (int mi = 0; mi < 4; mi++)
            aLd[mi] = smaddr(smw + (m_base + mi * 16 + rowl) * H2_WS) + kcb;
    }
    uint32_t bLd[2];
    {
        int rowl = (lane & 7) + ((lane >> 4) * 8);
        uint32_t kcb = ((lane >> 3) & 1) * 16;
        #pragma unroll
        for (int p = 0; p < 2; p++)
            bLd[p] = smaddr(smw + H2_TILEW + (n_base + p * 16 + rowl) * H2_WS) + kcb;
    }

    float acc[4][4][4];
    #pragma unroll
    for (int mi = 0; mi < 4; mi++)
        #pragma unroll
        for (int ni = 0; ni < 4; ni++)
            #pragma unroll
            for (int r = 0; r < 4; r++) acc[mi][ni][r] = 0.f;

    const int nslab = K >> 6;
    load_slab(0, 0);
    if (nslab > 1) load_slab(1, 1); else cp_commit();

    int st = 0;
    for (int s = 0; s < nslab; s++) {
        cp_wait1();          // slab s resident (only newest group may be pending)
        __syncthreads();     // also: everyone done computing slab s-1
        if (s + 2 < nslab) load_slab(s + 2, (st + 2) % 3);
        else cp_commit();    // keep group-count semantics for cp_wait1

        const uint32_t so = st * (2 * H2_TILEW * 4);

        #pragma unroll
        for (int kw = 0; kw < 32; kw += 8) {
            uint32_t afr[4][4], bfr[2][4];
            #pragma unroll
            for (int mi = 0; mi < 4; mi++) ldsm4(afr[mi], aLd[mi] + so + kw * 4);
            #pragma unroll
            for (int p = 0; p < 2; p++)    ldsm4(bfr[p], bLd[p] + so + kw * 4);
            #pragma unroll
            for (int mi = 0; mi < 4; mi++)
                #pragma unroll
                for (int ni = 0; ni < 4; ni++) {
                    uint32_t bq[2] = { bfr[ni >> 1][(ni & 1) * 2],
                                       bfr[ni >> 1][(ni & 1) * 2 + 1] };
                    mma_f16(acc[mi][ni], afr[mi], bq);
                }
        }
        st = (st + 1) % 3;
    }

    // epilogue
    const float* bias = job.bias;
    #pragma unroll
    for (int mi = 0; mi < 4; mi++) {
        int row0 = bm + m_base + mi * 16 + g;
        #pragma unroll
        for (int ni = 0; ni < 4; ni++) {
            int col = bn + n_base + ni * 8 + tg * 2;
            float b0 = bias[col], b1 = bias[col + 1];
            float v0 = acc[mi][ni][0] + b0;
            float v1 = acc[mi][ni][1] + b1;
            float v2 = acc[mi][ni][2] + b0;
            float v3 = acc[mi][ni][3] + b1;
            if (postop == 0) {
                float* C = (float*)job.C;
                *(float2*)&C[(long)row0 * N + col]       = make_float2(v0, v1);
                *(float2*)&C[(long)(row0 + 8) * N + col] = make_float2(v2, v3);
            } else {
                if (postop == 1) {
                    v0 = fmaxf(v0, 0.f); v1 = fmaxf(v1, 0.f);
                    v2 = fmaxf(v2, 0.f); v3 = fmaxf(v3, 0.f);
                }
                __half* C = (__half*)job.C;
                *(__half2*)&C[(long)row0 * N + col]       = __floats2half2_rn(v0, v1);
                *(__half2*)&C[(long)(row0 + 8) * N + col] = __floats2half2_rn(v2, v3);
            }
        }
    }
}

// ======================= fp16 fused flash attention =======================
// Q/K/V/O: half [t][4096], head offset bh*64. S tile 64, Q tile 128, 8 warps.
#define FLH_SMEM (18432*4)

template<bool CAUSAL>
__global__ __launch_bounds__(256, 2) void flash_h(
    const __half* __restrict__ Qp, const __half* __restrict__ Kp,
    const __half* __restrict__ Vp, __half* __restrict__ Op,
    float2* __restrict__ stats)
{
    extern __shared__ uint32_t smw[];
    const int tid = threadIdx.x;
    const int lane = tid & 31, w = tid >> 5;
    const int g = lane >> 2, tg = lane & 3;
    const int bh = blockIdx.y;
    const int it = CAUSAL ? ((int)gridDim.x - 1 - (int)blockIdx.x) : (int)blockIdx.x;
    const int t0 = it * 128;
    const int nIter = CAUSAL ? 2 * it + 2 : 16;

    const __half* Qg = Qp + (long)t0 * 4096 + bh * 64;
    const __half* Kg = Kp + bh * 64;
    const __half* Vg = Vp + bh * 64;

    auto loadKV = [&](int j, int buf) {
        const long s0 = (long)j * 64;
        const uint32_t kb = smaddr(smw + 4608 + buf * 2304);
        const uint32_t vb = smaddr(smw + 9216 + buf * 2304);
        #pragma unroll
        for (int i = 0; i < 2; i++) {
            int idx = tid + i * 256;
            int row = idx >> 3, c = idx & 7;
            cp16(kb + row * 144 + c * 16, Kg + (s0 + row) * 4096 + c * 8);
            cp16(vb + row * 144 + c * 16, Vg + (s0 + row) * 4096 + c * 8);
        }
    };

    #pragma unroll
    for (int i = 0; i < 4; i++) {
        int idx = tid + i * 256;
        int row = idx >> 3, c = idx & 7;
        cp16(smaddr(smw) + row * 144 + c * 16, Qg + (long)row * 4096 + c * 8);
    }
    loadKV(0, 0);
    cp_commit();
    cp_wait0();
    __syncthreads();

    uint32_t qf[4][4];
    {
        uint32_t qbase = smaddr(smw) + (16 * w + (lane & 15)) * 144 + (lane >> 4) * 16;
        #pragma unroll
        for (int kk = 0; kk < 4; kk++) ldsm4(qf[kk], qbase + kk * 32);
    }
    uint32_t kbl[4];
    {
        int rowl = (lane & 7) + ((lane >> 4) * 8);
        uint32_t kcb = ((lane >> 3) & 1) * 16;
        #pragma unroll
        for (int p = 0; p < 4; p++)
            kbl[p] = smaddr(smw + 4608) + (p * 16 + rowl) * 144 + kcb;
    }
    uint32_t vbl[4];
    {
        int rowv = (lane & 7) + (((lane >> 3) & 1) * 8);
        uint32_t kcv = (lane >> 4) * 16;
        #pragma unroll
        for (int p = 0; p < 4; p++)
            vbl[p] = smaddr(smw + 9216) + rowv * 144 + kcv + p * 32;
    }
    uint32_t pbase = smaddr(smw + 13824) + (16 * w + (lane & 15)) * 144 + (lane >> 4) * 16;
    __half* Pw = (__half*)(smw + 13824) + (16 * w + g) * 72;

    float acc_o[8][4];
    #pragma unroll
    for (int ni = 0; ni < 8; ni++)
        #pragma unroll
        for (int r = 0; r < 4; r++) acc_o[ni][r] = 0.f;
    float m0 = -1e30f, m1 = -1e30f, l0 = 0.f, l1 = 0.f;

    for (int j = 0; j < nIter; j++) {
        const int buf = j & 1;
        const uint32_t bofs = buf * 9216;
        if (j + 1 < nIter) { loadKV(j + 1, buf ^ 1); cp_commit(); }

        float s_acc[8][4];
        #pragma unroll
        for (int ni = 0; ni < 8; ni++)
            #pragma unroll
            for (int r = 0; r < 4; r++) s_acc[ni][r] = 0.f;
        #pragma unroll
        for (int kk = 0; kk < 4; kk++) {
            uint32_t kfr[4][4];
            #pragma unroll
            for (int p = 0; p < 4; p++) ldsm4(kfr[p], kbl[p] + bofs + kk * 32);
            #pragma unroll
            for (int ni = 0; ni < 8; ni++) {
                uint32_t bq[2] = { kfr[ni >> 1][(ni & 1) * 2],
                                   kfr[ni >> 1][(ni & 1) * 2 + 1] };
                mma_f16(s_acc[ni], qf[kk], bq);
            }
        }

        const int s0 = j * 64;
        const bool need = CAUSAL && (s0 + 63 > t0 + 16 * w);
        const int tr0 = t0 + 16 * w + g, tr1 = tr0 + 8;
        float mx0 = -1e30f, mx1 = -1e30f;
        #pragma unroll
        for (int ni = 0; ni < 8; ni++) {
            float v0 = s_acc[ni][0] * 0.125f;
            float v1 = s_acc[ni][1] * 0.125f;
            float v2 = s_acc[ni][2] * 0.125f;
            float v3 = s_acc[ni][3] * 0.125f;
            if (need) {
                int c0 = s0 + ni * 8 + 2 * tg, c1 = c0 + 1;
                if (c0 > tr0) v0 -= 1e9f;
                if (c1 > tr0) v1 -= 1e9f;
                if (c0 > tr1) v2 -= 1e9f;
                if (c1 > tr1) v3 -= 1e9f;
            }
            s_acc[ni][0] = v0; s_acc[ni][1] = v1;
            s_acc[ni][2] = v2; s_acc[ni][3] = v3;
            mx0 = fmaxf(mx0, fmaxf(v0, v1));
            mx1 = fmaxf(mx1, fmaxf(v2, v3));
        }
        mx0 = fmaxf(mx0, __shfl_xor_sync(0xffffffffu, mx0, 1));
        mx0 = fmaxf(mx0, __shfl_xor_sync(0xffffffffu, mx0, 2));
        mx1 = fmaxf(mx1, __shfl_xor_sync(0xffffffffu, mx1, 1));
        mx1 = fmaxf(mx1, __shfl_xor_sync(0xffffffffu, mx1, 2));
        const float mn0 = fmaxf(m0, mx0), mn1 = fmaxf(m1, mx1);
        const float sc0 = expf(m0 - mn0), sc1 = expf(m1 - mn1);
        m0 = mn0; m1 = mn1;

        float sum0 = 0.f, sum1 = 0.f;
        #pragma unroll
        for (int ni = 0; ni < 8; ni++) {
            float p0 = expf(s_acc[ni][0] - m0);
            float p1 = expf(s_acc[ni][1] - m0);
            float p2 = expf(s_acc[ni][2] - m1);
            float p3 = expf(s_acc[ni][3] - m1);
            sum0 += p0 + p1; sum1 += p2 + p3;
            *(__half2*)&Pw[ni * 8 + 2 * tg]          = __floats2half2_rn(p0, p1);
            *(__half2*)&Pw[8 * 72 + ni * 8 + 2 * tg] = __floats2half2_rn(p2, p3);
        }
        sum0 += __shfl_xor_sync(0xffffffffu, sum0, 1);
        sum0 += __shfl_xor_sync(0xffffffffu, sum0, 2);
        sum1 += __shfl_xor_sync(0xffffffffu, sum1, 1);
        sum1 += __shfl_xor_sync(0xffffffffu, sum1, 2);
        l0 = l0 * sc0 + sum0;
        l1 = l1 * sc1 + sum1;
        #pragma unroll
        for (int ni = 0; ni < 8; ni++) {
            acc_o[ni][0] *= sc0; acc_o[ni][1] *= sc0;
            acc_o[ni][2] *= sc1; acc_o[ni][3] *= sc1;
        }
        __syncwarp();

        #pragma unroll
        for (int kk = 0; kk < 4; kk++) {
            uint32_t pf[4];
            ldsm4(pf, pbase + kk * 32);
            uint32_t vfr[4][4];
            #pragma unroll
            for (int p = 0; p < 4; p++) ldsm4t(vfr[p], vbl[p] + bofs + kk * 2304);
            #pragma unroll
            for (int ni = 0; ni < 8; ni++) {
                uint32_t bq[2] = { vfr[ni >> 1][(ni & 1) * 2],
                                   vfr[ni >> 1][(ni & 1) * 2 + 1] };
                mma_f16(acc_o[ni], pf, bq);
            }
        }
        if (j + 1 < nIter) cp_wait0();
        __syncthreads();
    }

    const float inv0 = 1.f / l0, inv1 = 1.f / l1;
    const int r0 = t0 + 16 * w + g;
    __half* o0 = Op + (long)r0 * 4096 + bh * 64;
    __half* o1 = o0 + 8L * 4096;
    #pragma unroll
    for (int ni = 0; ni < 8; ni++) {
        *(__half2*)&o0[ni * 8 + 2 * tg] =
            __floats2half2_rn(acc_o[ni][0] * inv0, acc_o[ni][1] * inv0);
        *(__half2*)&o1[ni * 8 + 2 * tg] =
            __floats2half2_rn(acc_o[ni][2] * inv1, acc_o[ni][3] * inv1);
    }
    if (!CAUSAL && tg == 0) {
        stats[bh * Tn + r0]     = make_float2(m0, l0);
        stats[bh * Tn + r0 + 8] = make_float2(m1, l1);
    }
}

// ======================= wgemm: EA normalized attention weights ============
#define WG_SMEM (9216*4)

__global__ __launch_bounds__(256, 2) void wgemm(
    const __half* __restrict__ Qh, const __half* __restrict__ Kh,
    const float2* __restrict__ stats, float* __restrict__ C)
{
    extern __shared__ uint32_t smw[];
    const int tid  = threadIdx.x;
    const int lane = tid & 31;
    const int wid  = tid >> 5;
    const int wm = wid & 1, wn = wid >> 1;
    const int m_base = wm * 64, n_base = wn * 32;
    const int g  = lane >> 2;
    const int tg = lane & 3;
    const int z  = blockIdx.z;
    const int bm = blockIdx.y * 128;
    const int bn = blockIdx.x * 128;

    const __half* A = Qh + (long)z * 64 + (long)bm * 4096;
    const __half* B = Kh + (long)z * 64 + (long)bn * 4096;

    #pragma unroll
    for (int i = 0; i < 4; i++) {
        int idx = tid + i * 256;
        int row = idx >> 3, c = idx & 7;
        cp16(smaddr(smw) + row * 144 + c * 16, A + (long)row * 4096 + c * 8);
        cp16(smaddr(smw + 4608) + row * 144 + c * 16, B + (long)row * 4096 + c * 8);
    }
    cp_commit();
    cp_wait0();
    __syncthreads();

    uint32_t aLd[4], bLd[2];
    {
        int rowl = lane & 15;
        uint32_t kcb = (lane >> 4) * 16;
        #pragma unroll
        for (int mi = 0; mi < 4; mi++)
            aLd[mi] = smaddr(smw) + (m_base + mi * 16 + rowl) * 144 + kcb;
    }
    {
        int rowl = (lane & 7) + ((lane >> 4) * 8);
        uint32_t kcb = ((lane >> 3) & 1) * 16;
        #pragma unroll
        for (int p = 0; p < 2; p++)
            bLd[p] = smaddr(smw + 4608) + (n_base + p * 16 + rowl) * 144 + kcb;
    }

    float acc[4][4][4];
    #pragma unroll
    for (int mi = 0; mi < 4; mi++)
        #pragma unroll
        for (int ni = 0; ni < 4; ni++)
            #pragma unroll
            for (int r = 0; r < 4; r++) acc[mi][ni][r] = 0.f;

    #pragma unroll
    for (int kk = 0; kk < 4; kk++) {
        uint32_t afr[4][4], bfr[2][4];
        #pragma unroll
        for (int mi = 0; mi < 4; mi++) ldsm4(afr[mi], aLd[mi] + kk * 32);
        #pragma unroll
        for (int p = 0; p < 2; p++)    ldsm4(bfr[p], bLd[p] + kk * 32);
        #pragma unroll
        for (int mi = 0; mi < 4; mi++)
            #pragma unroll
            for (int ni = 0; ni < 4; ni++) {
                uint32_t bq[2] = { bfr[ni >> 1][(ni & 1) * 2],
                                   bfr[ni >> 1][(ni & 1) * 2 + 1] };
                mma_f16(acc[mi][ni], afr[mi], bq);
            }
    }

    #pragma unroll
    for (int mi = 0; mi < 4; mi++) {
        int row0 = bm + m_base + mi * 16 + g;
        float2 ml0 = stats[z * Tn + row0];
        float2 ml1 = stats[z * Tn + row0 + 8];
        float i0 = 1.f / ml0.y, i1 = 1.f / ml1.y;
        #pragma unroll
        for (int ni = 0; ni < 4; ni++) {
            int col = bn + n_base + ni * 8 + tg * 2;
            float v0 = expf(acc[mi][ni][0] * 0.125f - ml0.x) * i0;
            float v1 = expf(acc[mi][ni][1] * 0.125f - ml0.x) * i0;
            float v2 = expf(acc[mi][ni][2] * 0.125f - ml1.x) * i1;
            float v3 = expf(acc[mi][ni][3] * 0.125f - ml1.x) * i1;
            float* Cz = C + (long)z * Tn * Sn;
            *(float2*)&Cz[(long)row0 * Sn + col]       = make_float2(v0, v1);
            *(float2*)&Cz[(long)(row0 + 8) * Sn + col] = make_float2(v2, v3);
        }
    }
}

// ======================= out = LayerNorm(x+res)*g+b ; optional half copy
__global__ __launch_bounds__(256) void add_ln_kernel(
    const float* __restrict__ x, const float* __restrict__ res,
    const float* __restrict__ g, const float* __restrict__ b,
    float* __restrict__ out, __half* __restrict__ out_r)
{
    const long row = (long)blockIdx.x * En;
    const int tid = threadIdx.x;
    float v[4]; float s = 0.f, s2 = 0.f;
    #pragma unroll
    for (int j = 0; j < 4; j++) {
        int i = tid + j * 256;
        float val = x[row + i] + res[row + i];
        v[j] = val; s += val; s2 += val * val;
    }
    __shared__ float sh1[8], sh2[8];
    #pragma unroll
    for (int o = 16; o; o >>= 1) {
        s  += __shfl_xor_sync(0xffffffffu, s, o);
        s2 += __shfl_xor_sync(0xffffffffu, s2, o);
    }
    if ((tid & 31) == 0) { sh1[tid >> 5] = s; sh2[tid >> 5] = s2; }
    __syncthreads();
    float ts = 0.f, ts2 = 0.f;
    #pragma unroll
    for (int w = 0; w < 8; w++) { ts += sh1[w]; ts2 += sh2[w]; }
    const float mu  = ts * (1.f / En);
    const float var = ts2 * (1.f / En) - mu * mu;
    const float inv = rsqrtf(var + 1e-5f);
    #pragma unroll
    for (int j = 0; j < 4; j++) {
        int i = tid + j * 256;
        float o = (v[j] - mu) * inv * g[i] + b[i];
        out[row + i] = o;
        if (out_r) out_r[row + i] = __float2half_rn(o);
    }
}

// ======================= fused fp16 conversion pass =======================
#define NCVT 12
struct CvtJobs {
    const float4* src[NCVT];
    uint2* dst[NCVT];
    int cum[NCVT + 1];
};
__global__ __launch_bounds__(256) void cvt_multi(CvtJobs cj, int total4)
{
    for (int i = blockIdx.x * 256 + threadIdx.x; i < total4; i += gridDim.x * 256) {
        int job = 0;
        #pragma unroll
        for (int t = 0; t < NCVT - 1; t++) if (i >= cj.cum[t + 1]) job = t + 1;
        int off = i - cj.cum[job];
        float4 v = cj.src[job][off];
        __half2 h0 = __floats2half2_rn(v.x, v.y);
        __half2 h1 = __floats2half2_rn(v.z, v.w);
        uint2 u;
        u.x = *(uint32_t*)&h0;
        u.y = *(uint32_t*)&h1;
        cj.dst[job][off] = u;
    }
}

// ======================= host-side =======================
static inline void gh(JobsH jobs, int M, int N, int K, int njobs, int postop)
{
    dim3 grid(N / 128, M / 128, njobs);
    hgemm2<<<grid, 256, H2_SMEM>>>(jobs, K, N, postop);
}

extern "C" void kernel_launch(void* const* d_in, const int* in_sizes, int n_in,
                              void* d_out, int out_size)
{
    static bool attr_done = false;
    if (!attr_done) {
        cudaFuncSetAttribute((const void*)hgemm2,
                             cudaFuncAttributeMaxDynamicSharedMemorySize, H2_SMEM);
        cudaFuncSetAttribute((const void*)flash_h<true>,
                             cudaFuncAttributeMaxDynamicSharedMemorySize, FLH_SMEM);
        cudaFuncSetAttribute((const void*)flash_h<false>,
                             cudaFuncAttributeMaxDynamicSharedMemorySize, FLH_SMEM);
        cudaFuncSetAttribute((const void*)wgemm,
                             cudaFuncAttributeMaxDynamicSharedMemorySize, WG_SMEM);
        attr_done = true;
    }

    const float* state = (const float*)d_in[0];
    const float* enc   = (const float*)d_in[1];
    const float* sa_wq = (const float*)d_in[3];  const float* sa_bq = (const float*)d_in[4];
    const float* sa_wk = (const float*)d_in[5];  const float* sa_bk = (const float*)d_in[6];
    const float* sa_wv = (const float*)d_in[7];  const float* sa_bv = (const float*)d_in[8];
    const float* sa_wo = (const float*)d_in[9];  const float* sa_bo = (const float*)d_in[10];
    const float* ea_wq = (const float*)d_in[11]; const float* ea_bq = (const float*)d_in[12];
    const float* ea_wk = (const float*)d_in[13]; const float* ea_bk = (const float*)d_in[14];
    const float* ea_wv = (const float*)d_in[15]; const float* ea_bv = (const float*)d_in[16];
    const float* ea_wo = (const float*)d_in[17]; const float* ea_bo = (const float*)d_in[18];
    const float* fc1_w = (const float*)d_in[19]; const float* fc1_b = (const float*)d_in[20];
    const float* fc2_w = (const float*)d_in[21]; const float* fc2_b = (const float*)d_in[22];
    const float* ln1_g = (const float*)d_in[23]; const float* ln1_b = (const float*)d_in[24];
    const float* ln2_g = (const float*)d_in[25]; const float* ln2_b = (const float*)d_in[26];
    const float* ln3_g = (const float*)d_in[27]; const float* ln3_b = (const float*)d_in[28];

    float *xq_f, *xk_f, *xv_f, *tmp, *st1, *st2, *rw;
    float *attn_f, *st1r_f, *st2r_f, *ffn_f;
    float2* stats;
    cudaGetSymbolAddress((void**)&xq_f,   g_xq);
    cudaGetSymbolAddress((void**)&xk_f,   g_xk);
    cudaGetSymbolAddress((void**)&xv_f,   g_xv);
    cudaGetSymbolAddress((void**)&attn_f, g_attn);
    cudaGetSymbolAddress((void**)&tmp,    g_tmp);
    cudaGetSymbolAddress((void**)&st1,    g_state1);
    cudaGetSymbolAddress((void**)&st2,    g_state2);
    cudaGetSymbolAddress((void**)&st1r_f, g_st1r);
    cudaGetSymbolAddress((void**)&st2r_f, g_st2r);
    cudaGetSymbolAddress((void**)&ffn_f,  g_ffn);
    cudaGetSymbolAddress((void**)&stats,  g_stats);
    cudaGetSymbolAddress((void**)&rw,     g_rw);

    __half* xq_h   = (__half*)xq_f;
    __half* xk_h   = (__half*)xk_f;
    __half* xv_h   = (__half*)xv_f;
    __half* attn_h = (__half*)attn_f;
    __half* st1r_h = (__half*)st1r_f;
    __half* st2r_h = (__half*)st2r_f;
    __half* ffn_h  = (__half*)ffn_f;
    __half* hp = (__half*)rw;
    __half* h_state = hp + 0L  * MEG;
    __half* h_enc   = hp + 4L  * MEG;
    __half* h_saq   = hp + 8L  * MEG;
    __half* h_sak   = hp + 9L  * MEG;
    __half* h_sav   = hp + 10L * MEG;
    __half* h_sao   = hp + 11L * MEG;
    __half* h_eaq   = hp + 12L * MEG;
    __half* h_eak   = hp + 13L * MEG;
    __half* h_eav   = hp + 14L * MEG;
    __half* h_eao   = hp + 15L * MEG;
    __half* h_fc1   = hp + 16L * MEG;
    __half* h_fc2   = hp + 20L * MEG;

    float* out_state = (float*)d_out;
    float* out_attn  = (float*)d_out + (long)Tn * Bn * En;

    // -------- fused fp16 conversion pass --------
    {
        CvtJobs cj;
        const float* srcs[NCVT] = {state, enc, sa_wq, sa_wk, sa_wv, sa_wo,
                                   ea_wq, ea_wk, ea_wv, ea_wo, fc1_w, fc2_w};
        __half* dsts[NCVT] = {h_state, h_enc, h_saq, h_sak, h_sav, h_sao,
                              h_eaq, h_eak, h_eav, h_eao, h_fc1, h_fc2};
        const int n4s[NCVT] = {MEG, MEG, MEG/4, MEG/4, MEG/4, MEG/4,
                               MEG/4, MEG/4, MEG/4, MEG/4, MEG, MEG};
        int c = 0;
        for (int i = 0; i < NCVT; i++) {
            cj.src[i] = (const float4*)srcs[i];
            cj.dst[i] = (uint2*)dsts[i];
            cj.cum[i] = c;
            c += n4s[i];
        }
        cj.cum[NCVT] = c;
        cvt_multi<<<1024, 256>>>(cj, c);
    }

    // ---------------- self-attention (fused flash, causal) ----------------
    {
        JobsH j = {{{h_state, h_saq, sa_bq, xq_h},
                    {h_state, h_sak, sa_bk, xk_h},
                    {h_state, h_sav, sa_bv, xv_h}}};
        gh(j, ROWS, En, En, 3, 2);
    }
    flash_h<true><<<dim3(Tn / 128, BH), 256, FLH_SMEM>>>(xq_h, xk_h, xv_h, attn_h, nullptr);
    {
        JobsH j = {{{attn_h, h_sao, sa_bo, tmp}, {}, {}}};
        gh(j, ROWS, En, En, 1, 0);
    }
    add_ln_kernel<<<ROWS, 256>>>(tmp, state, ln1_g, ln1_b, st1, st1r_h);

    // ---------------- encoder-decoder attention ----------------
    {
        JobsH j = {{{st1r_h, h_eaq, ea_bq, xq_h},
                    {h_enc,  h_eak, ea_bk, xk_h},
                    {h_enc,  h_eav, ea_bv, xv_h}}};
        gh(j, ROWS, En, En, 3, 2);
    }
    flash_h<false><<<dim3(Tn / 128, BH), 256, FLH_SMEM>>>(xq_h, xk_h, xv_h, attn_h, stats);
    // normalized attention weights straight into d_out
    wgemm<<<dim3(Sn / 128, Tn / 128, BH), 256, WG_SMEM>>>(xq_h, xk_h, stats, out_attn);
    {
        JobsH j = {{{attn_h, h_eao, ea_bo, tmp}, {}, {}}};
        gh(j, ROWS, En, En, 1, 0);
    }
    add_ln_kernel<<<ROWS, 256>>>(tmp, st1, ln2_g, ln2_b, st2, st2r_h);

    // ---------------- FFN ----------------
    {
        JobsH j = {{{st2r_h, h_fc1, fc1_b, ffn_h}, {}, {}}};
        gh(j, ROWS, FFn, En, 1, 1);
    }
    {
        JobsH j = {{{ffn_h, h_fc2, fc2_b, tmp}, {}, {}}};
        gh(j, ROWS, En, FFn, 1, 0);
    }
    add_ln_kernel<<<ROWS, 256>>>(tmp, st2, ln3_g, ln3_b, out_state, nullptr);
}

// round 12
// speedup vs baseline: 7.2482x; 1.0215x over previous
#include <cuda_runtime.h>
#include <cuda_fp16.h>
#include <math.h>
#include <stdint.h>

// Problem dims
#define Tn 1024
#define Sn 1024
#define Bn 4
#define En 1024
#define Hn 16
#define DHn 64
#define FFn 4096
#define ROWS (Tn*Bn)
#define BH (Bn*Hn)
#define MEG (1024*1024)

// -------- scratch (device globals; no allocation) --------
__device__ float g_xq[ROWS*En];        // used as __half
__device__ float g_xk[ROWS*En];        // used as __half
__device__ float g_xv[ROWS*En];        // used as __half
__device__ float g_attn[ROWS*En];      // used as __half
__device__ float g_tmp[ROWS*En];
__device__ float g_state1[ROWS*En];
__device__ float g_state2[ROWS*En];
__device__ float g_st1r[ROWS*En];      // used as __half
__device__ float g_st2r[ROWS*En];      // used as __half
__device__ float g_ffn[ROWS*FFn];      // used as __half
__device__ float2 g_stats[BH*Tn];
__device__ float g_rw[24*MEG];         // used as __half pool (48M halfs)

// ======================= helpers =======================
__device__ __forceinline__ void mma_f16(float* c, const uint32_t* a, const uint32_t* b) {
    asm volatile(
        "mma.sync.aligned.m16n8k16.row.col.f32.f16.f16.f32 "
        "{%0,%1,%2,%3}, {%4,%5,%6,%7}, {%8,%9}, {%0,%1,%2,%3};"
        : "+f"(c[0]), "+f"(c[1]), "+f"(c[2]), "+f"(c[3])
        : "r"(a[0]), "r"(a[1]), "r"(a[2]), "r"(a[3]), "r"(b[0]), "r"(b[1]));
}
__device__ __forceinline__ void ldsm4(uint32_t* r, uint32_t addr) {
    asm volatile("ldmatrix.sync.aligned.m8n8.x4.shared.b16 {%0,%1,%2,%3}, [%4];"
        : "=r"(r[0]), "=r"(r[1]), "=r"(r[2]), "=r"(r[3]) : "r"(addr));
}
__device__ __forceinline__ void ldsm4t(uint32_t* r, uint32_t addr) {
    asm volatile("ldmatrix.sync.aligned.m8n8.x4.trans.shared.b16 {%0,%1,%2,%3}, [%4];"
        : "=r"(r[0]), "=r"(r[1]), "=r"(r[2]), "=r"(r[3]) : "r"(addr));
}
__device__ __forceinline__ void cp16(uint32_t dst, const void* src) {
    asm volatile("cp.async.cg.shared.global [%0], [%1], 16;" :: "r"(dst), "l"(src));
}
__device__ __forceinline__ void cp_commit() {
    asm volatile("cp.async.commit_group;" ::: "memory");
}
__device__ __forceinline__ void cp_wait0() {
    asm volatile("cp.async.wait_group 0;" ::: "memory");
}
__device__ __forceinline__ void cp_wait1() {
    asm volatile("cp.async.wait_group 1;" ::: "memory");
}
__device__ __forceinline__ uint32_t smaddr(const void* p) {
    return (uint32_t)__cvta_generic_to_shared(p);
}

// ======================= hgemm2: fp16 MMA + ldmatrix, 3-stage, 8 warps ============
struct JobH { const __half* A; const __half* B; const float* bias; void* C; };
struct JobsH { JobH j[3]; };

#define H2_WS 36
#define H2_TILEW (128*H2_WS)
#define H2_SMEM (6*H2_TILEW*4)

__global__ __launch_bounds__(256, 2) void hgemm2(
    JobsH jobs, int K, int N, int postop)
{
    extern __shared__ uint32_t smw[];
    const int tid  = threadIdx.x;
    const int lane = tid & 31;
    const int wid  = tid >> 5;
    const int wm = wid & 1, wn = wid >> 1;
    const int m_base = wm * 64, n_base = wn * 32;
    const int g  = lane >> 2;
    const int tg = lane & 3;

    const JobH job = jobs.j[blockIdx.z];
    const int bm = blockIdx.y * 128;
    const int bn = blockIdx.x * 128;
    const __half* A = job.A + (long)bm * K;
    const __half* B = job.B + (long)bn * K;

    const int r0 = tid >> 3, c8 = tid & 7;
    const __half* aPtr = A + (long)r0 * K + c8 * 8;
    const __half* bPtr = B + (long)r0 * K + c8 * 8;
    const uint32_t aSm = smaddr(smw + r0 * H2_WS + c8 * 4);
    const uint32_t bSm = smaddr(smw + H2_TILEW + r0 * H2_WS + c8 * 4);
    const long rowAdv = 32L * K;

    auto load_slab = [&](int s, int st) {
        const uint32_t so = st * (2 * H2_TILEW * 4);
        const __half* ap = aPtr + s * 64;
        const __half* bp = bPtr + s * 64;
        #pragma unroll
        for (int it = 0; it < 4; it++) {
            cp16(aSm + so + it * (32 * H2_WS * 4), ap + it * rowAdv);
            cp16(bSm + so + it * (32 * H2_WS * 4), bp + it * rowAdv);
        }
        cp_commit();
    };

    uint32_t aLd[4];
    {
        int rowl = lane & 15;
        uint32_t kcb = (lane >> 4) * 16;
        #pragma unroll
        for (int mi = 0; mi < 4; mi++)
            aLd[mi] = smaddr(smw + (m_base + mi * 16 + rowl) * H2_WS) + kcb;
    }
    uint32_t bLd[2];
    {
        int rowl = (lane & 7) + ((lane >> 4) * 8);
        uint32_t kcb = ((lane >> 3) & 1) * 16;
        #pragma unroll
        for (int p = 0; p < 2; p++)
            bLd[p] = smaddr(smw + H2_TILEW + (n_base + p * 16 + rowl) * H2_WS) + kcb;
    }

    float acc[4][4][4];
    #pragma unroll
    for (int mi = 0; mi < 4; mi++)
        #pragma unroll
        for (int ni = 0; ni < 4; ni++)
            #pragma unroll
            for (int r = 0; r < 4; r++) acc[mi][ni][r] = 0.f;

    const int nslab = K >> 6;
    load_slab(0, 0);
    if (nslab > 1) load_slab(1, 1); else cp_commit();

    int st = 0;
    for (int s = 0; s < nslab; s++) {
        cp_wait1();
        __syncthreads();
        if (s + 2 < nslab) load_slab(s + 2, (st + 2) % 3);
        else cp_commit();

        const uint32_t so = st * (2 * H2_TILEW * 4);

        #pragma unroll
        for (int kw = 0; kw < 32; kw += 8) {
            uint32_t afr[4][4], bfr[2][4];
            #pragma unroll
            for (int mi = 0; mi < 4; mi++) ldsm4(afr[mi], aLd[mi] + so + kw * 4);
            #pragma unroll
            for (int p = 0; p < 2; p++)    ldsm4(bfr[p], bLd[p] + so + kw * 4);
            #pragma unroll
            for (int mi = 0; mi < 4; mi++)
                #pragma unroll
                for (int ni = 0; ni < 4; ni++) {
                    uint32_t bq[2] = { bfr[ni >> 1][(ni & 1) * 2],
                                       bfr[ni >> 1][(ni & 1) * 2 + 1] };
                    mma_f16(acc[mi][ni], afr[mi], bq);
                }
        }
        st = (st + 1) % 3;
    }

    const float* bias = job.bias;
    #pragma unroll
    for (int mi = 0; mi < 4; mi++) {
        int row0 = bm + m_base + mi * 16 + g;
        #pragma unroll
        for (int ni = 0; ni < 4; ni++) {
            int col = bn + n_base + ni * 8 + tg * 2;
            float b0 = bias[col], b1 = bias[col + 1];
            float v0 = acc[mi][ni][0] + b0;
            float v1 = acc[mi][ni][1] + b1;
            float v2 = acc[mi][ni][2] + b0;
            float v3 = acc[mi][ni][3] + b1;
            if (postop == 0) {
                float* C = (float*)job.C;
                *(float2*)&C[(long)row0 * N + col]       = make_float2(v0, v1);
                *(float2*)&C[(long)(row0 + 8) * N + col] = make_float2(v2, v3);
            } else {
                if (postop == 1) {
                    v0 = fmaxf(v0, 0.f); v1 = fmaxf(v1, 0.f);
                    v2 = fmaxf(v2, 0.f); v3 = fmaxf(v3, 0.f);
                }
                __half* C = (__half*)job.C;
                *(__half2*)&C[(long)row0 * N + col]       = __floats2half2_rn(v0, v1);
                *(__half2*)&C[(long)(row0 + 8) * N + col] = __floats2half2_rn(v2, v3);
            }
        }
    }
}

// ======================= fp16 fused flash attention =======================
#define FLH_SMEM (18432*4)

template<bool CAUSAL>
__global__ __launch_bounds__(256, 2) void flash_h(
    const __half* __restrict__ Qp, const __half* __restrict__ Kp,
    const __half* __restrict__ Vp, __half* __restrict__ Op,
    float2* __restrict__ stats)
{
    extern __shared__ uint32_t smw[];
    const int tid = threadIdx.x;
    const int lane = tid & 31, w = tid >> 5;
    const int g = lane >> 2, tg = lane & 3;
    const int bh = blockIdx.y;
    const int it = CAUSAL ? ((int)gridDim.x - 1 - (int)blockIdx.x) : (int)blockIdx.x;
    const int t0 = it * 128;
    const int nIter = CAUSAL ? 2 * it + 2 : 16;

    const __half* Qg = Qp + (long)t0 * 4096 + bh * 64;
    const __half* Kg = Kp + bh * 64;
    const __half* Vg = Vp + bh * 64;

    auto loadKV = [&](int j, int buf) {
        const long s0 = (long)j * 64;
        const uint32_t kb = smaddr(smw + 4608 + buf * 2304);
        const uint32_t vb = smaddr(smw + 9216 + buf * 2304);
        #pragma unroll
        for (int i = 0; i < 2; i++) {
            int idx = tid + i * 256;
            int row = idx >> 3, c = idx & 7;
            cp16(kb + row * 144 + c * 16, Kg + (s0 + row) * 4096 + c * 8);
            cp16(vb + row * 144 + c * 16, Vg + (s0 + row) * 4096 + c * 8);
        }
    };

    #pragma unroll
    for (int i = 0; i < 4; i++) {
        int idx = tid + i * 256;
        int row = idx >> 3, c = idx & 7;
        cp16(smaddr(smw) + row * 144 + c * 16, Qg + (long)row * 4096 + c * 8);
    }
    loadKV(0, 0);
    cp_commit();
    cp_wait0();
    __syncthreads();

    uint32_t qf[4][4];
    {
        uint32_t qbase = smaddr(smw) + (16 * w + (lane & 15)) * 144 + (lane >> 4) * 16;
        #pragma unroll
        for (int kk = 0; kk < 4; kk++) ldsm4(qf[kk], qbase + kk * 32);
    }
    uint32_t kbl[4];
    {
        int rowl = (lane & 7) + ((lane >> 4) * 8);
        uint32_t kcb = ((lane >> 3) & 1) * 16;
        #pragma unroll
        for (int p = 0; p < 4; p++)
            kbl[p] = smaddr(smw + 4608) + (p * 16 + rowl) * 144 + kcb;
    }
    uint32_t vbl[4];
    {
        int rowv = (lane & 7) + (((lane >> 3) & 1) * 8);
        uint32_t kcv = (lane >> 4) * 16;
        #pragma unroll
        for (int p = 0; p < 4; p++)
            vbl[p] = smaddr(smw + 9216) + rowv * 144 + kcv + p * 32;
    }
    uint32_t pbase = smaddr(smw + 13824) + (16 * w + (lane & 15)) * 144 + (lane >> 4) * 16;
    __half* Pw = (__half*)(smw + 13824) + (16 * w + g) * 72;

    float acc_o[8][4];
    #pragma unroll
    for (int ni = 0; ni < 8; ni++)
        #pragma unroll
        for (int r = 0; r < 4; r++) acc_o[ni][r] = 0.f;
    float m0 = -1e30f, m1 = -1e30f, l0 = 0.f, l1 = 0.f;

    for (int j = 0; j < nIter; j++) {
        const int buf = j & 1;
        const uint32_t bofs = buf * 9216;
        if (j + 1 < nIter) { loadKV(j + 1, buf ^ 1); cp_commit(); }

        float s_acc[8][4];
        #pragma unroll
        for (int ni = 0; ni < 8; ni++)
            #pragma unroll
            for (int r = 0; r < 4; r++) s_acc[ni][r] = 0.f;
        #pragma unroll
        for (int kk = 0; kk < 4; kk++) {
            uint32_t kfr[4][4];
            #pragma unroll
            for (int p = 0; p < 4; p++) ldsm4(kfr[p], kbl[p] + bofs + kk * 32);
            #pragma unroll
            for (int ni = 0; ni < 8; ni++) {
                uint32_t bq[2] = { kfr[ni >> 1][(ni & 1) * 2],
                                   kfr[ni >> 1][(ni & 1) * 2 + 1] };
                mma_f16(s_acc[ni], qf[kk], bq);
            }
        }

        const int s0 = j * 64;
        const bool need = CAUSAL && (s0 + 63 > t0 + 16 * w);
        const int tr0 = t0 + 16 * w + g, tr1 = tr0 + 8;
        float mx0 = -1e30f, mx1 = -1e30f;
        #pragma unroll
        for (int ni = 0; ni < 8; ni++) {
            float v0 = s_acc[ni][0] * 0.125f;
            float v1 = s_acc[ni][1] * 0.125f;
            float v2 = s_acc[ni][2] * 0.125f;
            float v3 = s_acc[ni][3] * 0.125f;
            if (need) {
                int c0 = s0 + ni * 8 + 2 * tg, c1 = c0 + 1;
                if (c0 > tr0) v0 -= 1e9f;
                if (c1 > tr0) v1 -= 1e9f;
                if (c0 > tr1) v2 -= 1e9f;
                if (c1 > tr1) v3 -= 1e9f;
            }
            s_acc[ni][0] = v0; s_acc[ni][1] = v1;
            s_acc[ni][2] = v2; s_acc[ni][3] = v3;
            mx0 = fmaxf(mx0, fmaxf(v0, v1));
            mx1 = fmaxf(mx1, fmaxf(v2, v3));
        }
        mx0 = fmaxf(mx0, __shfl_xor_sync(0xffffffffu, mx0, 1));
        mx0 = fmaxf(mx0, __shfl_xor_sync(0xffffffffu, mx0, 2));
        mx1 = fmaxf(mx1, __shfl_xor_sync(0xffffffffu, mx1, 1));
        mx1 = fmaxf(mx1, __shfl_xor_sync(0xffffffffu, mx1, 2));
        const float mn0 = fmaxf(m0, mx0), mn1 = fmaxf(m1, mx1);
        const float sc0 = expf(m0 - mn0), sc1 = expf(m1 - mn1);
        m0 = mn0; m1 = mn1;

        float sum0 = 0.f, sum1 = 0.f;
        #pragma unroll
        for (int ni = 0; ni < 8; ni++) {
            float p0 = expf(s_acc[ni][0] - m0);
            float p1 = expf(s_acc[ni][1] - m0);
            float p2 = expf(s_acc[ni][2] - m1);
            float p3 = expf(s_acc[ni][3] - m1);
            sum0 += p0 + p1; sum1 += p2 + p3;
            *(__half2*)&Pw[ni * 8 + 2 * tg]          = __floats2half2_rn(p0, p1);
            *(__half2*)&Pw[8 * 72 + ni * 8 + 2 * tg] = __floats2half2_rn(p2, p3);
        }
        sum0 += __shfl_xor_sync(0xffffffffu, sum0, 1);
        sum0 += __shfl_xor_sync(0xffffffffu, sum0, 2);
        sum1 += __shfl_xor_sync(0xffffffffu, sum1, 1);
        sum1 += __shfl_xor_sync(0xffffffffu, sum1, 2);
        l0 = l0 * sc0 + sum0;
        l1 = l1 * sc1 + sum1;
        #pragma unroll
        for (int ni = 0; ni < 8; ni++) {
            acc_o[ni][0] *= sc0; acc_o[ni][1] *= sc0;
            acc_o[ni][2] *= sc1; acc_o[ni][3] *= sc1;
        }
        __syncwarp();

        #pragma unroll
        for (int kk = 0; kk < 4; kk++) {
            uint32_t pf[4];
            ldsm4(pf, pbase + kk * 32);
            uint32_t vfr[4][4];
            #pragma unroll
            for (int p = 0; p < 4; p++) ldsm4t(vfr[p], vbl[p] + bofs + kk * 2304);
            #pragma unroll
            for (int ni = 0; ni < 8; ni++) {
                uint32_t bq[2] = { vfr[ni >> 1][(ni & 1) * 2],
                                   vfr[ni >> 1][(ni & 1) * 2 + 1] };
                mma_f16(acc_o[ni], pf, bq);
            }
        }
        if (j + 1 < nIter) cp_wait0();
        __syncthreads();
    }

    const float inv0 = 1.f / l0, inv1 = 1.f / l1;
    const int r0 = t0 + 16 * w + g;
    __half* o0 = Op + (long)r0 * 4096 + bh * 64;
    __half* o1 = o0 + 8L * 4096;
    #pragma unroll
    for (int ni = 0; ni < 8; ni++) {
        *(__half2*)&o0[ni * 8 + 2 * tg] =
            __floats2half2_rn(acc_o[ni][0] * inv0, acc_o[ni][1] * inv0);
        *(__half2*)&o1[ni * 8 + 2 * tg] =
            __floats2half2_rn(acc_o[ni][2] * inv1, acc_o[ni][3] * inv1);
    }
    if (!CAUSAL && tg == 0) {
        stats[bh * Tn + r0]     = make_float2(m0, l0);
        stats[bh * Tn + r0 + 8] = make_float2(m1, l1);
    }
}

// ======================= wgemm: EA normalized attention weights ============
#define WG_SMEM (9216*4)

__global__ __launch_bounds__(256, 2) void wgemm(
    const __half* __restrict__ Qh, const __half* __restrict__ Kh,
    const float2* __restrict__ stats, float* __restrict__ C)
{
    extern __shared__ uint32_t smw[];
    const int tid  = threadIdx.x;
    const int lane = tid & 31;
    const int wid  = tid >> 5;
    const int wm = wid & 1, wn = wid >> 1;
    const int m_base = wm * 64, n_base = wn * 32;
    const int g  = lane >> 2;
    const int tg = lane & 3;
    const int z  = blockIdx.z;
    const int bm = blockIdx.y * 128;
    const int bn = blockIdx.x * 128;

    const __half* A = Qh + (long)z * 64 + (long)bm * 4096;
    const __half* B = Kh + (long)z * 64 + (long)bn * 4096;

    #pragma unroll
    for (int i = 0; i < 4; i++) {
        int idx = tid + i * 256;
        int row = idx >> 3, c = idx & 7;
        cp16(smaddr(smw) + row * 144 + c * 16, A + (long)row * 4096 + c * 8);
        cp16(smaddr(smw + 4608) + row * 144 + c * 16, B + (long)row * 4096 + c * 8);
    }
    cp_commit();
    cp_wait0();
    __syncthreads();

    uint32_t aLd[4], bLd[2];
    {
        int rowl = lane & 15;
        uint32_t kcb = (lane >> 4) * 16;
        #pragma unroll
        for (int mi = 0; mi < 4; mi++)
            aLd[mi] = smaddr(smw) + (m_base + mi * 16 + rowl) * 144 + kcb;
    }
    {
        int rowl = (lane & 7) + ((lane >> 4) * 8);
        uint32_t kcb = ((lane >> 3) & 1) * 16;
        #pragma unroll
        for (int p = 0; p < 2; p++)
            bLd[p] = smaddr(smw + 4608) + (n_base + p * 16 + rowl) * 144 + kcb;
    }

    float acc[4][4][4];
    #pragma unroll
    for (int mi = 0; mi < 4; mi++)
        #pragma unroll
        for (int ni = 0; ni < 4; ni++)
            #pragma unroll
            for (int r = 0; r < 4; r++) acc[mi][ni][r] = 0.f;

    #pragma unroll
    for (int kk = 0; kk < 4; kk++) {
        uint32_t afr[4][4], bfr[2][4];
        #pragma unroll
        for (int mi = 0; mi < 4; mi++) ldsm4(afr[mi], aLd[mi] + kk * 32);
        #pragma unroll
        for (int p = 0; p < 2; p++)    ldsm4(bfr[p], bLd[p] + kk * 32);
        #pragma unroll
        for (int mi = 0; mi < 4; mi++)
            #pragma unroll
            for (int ni = 0; ni < 4; ni++) {
                uint32_t bq[2] = { bfr[ni >> 1][(ni & 1) * 2],
                                   bfr[ni >> 1][(ni & 1) * 2 + 1] };
                mma_f16(acc[mi][ni], afr[mi], bq);
            }
    }

    #pragma unroll
    for (int mi = 0; mi < 4; mi++) {
        int row0 = bm + m_base + mi * 16 + g;
        float2 ml0 = stats[z * Tn + row0];
        float2 ml1 = stats[z * Tn + row0 + 8];
        float i0 = 1.f / ml0.y, i1 = 1.f / ml1.y;
        #pragma unroll
        for (int ni = 0; ni < 4; ni++) {
            int col = bn + n_base + ni * 8 + tg * 2;
            float v0 = expf(acc[mi][ni][0] * 0.125f - ml0.x) * i0;
            float v1 = expf(acc[mi][ni][1] * 0.125f - ml0.x) * i0;
            float v2 = expf(acc[mi][ni][2] * 0.125f - ml1.x) * i1;
            float v3 = expf(acc[mi][ni][3] * 0.125f - ml1.x) * i1;
            float* Cz = C + (long)z * Tn * Sn;
            *(float2*)&Cz[(long)row0 * Sn + col]       = make_float2(v0, v1);
            *(float2*)&Cz[(long)(row0 + 8) * Sn + col] = make_float2(v2, v3);
        }
    }
}

// ======================= out = LayerNorm(x+res)*g+b ; optional half copy
__global__ __launch_bounds__(256) void add_ln_kernel(
    const float* __restrict__ x, const float* __restrict__ res,
    const float* __restrict__ g, const float* __restrict__ b,
    float* __restrict__ out, __half* __restrict__ out_r)
{
    const long row = (long)blockIdx.x * En;
    const int tid = threadIdx.x;
    float v[4]; float s = 0.f, s2 = 0.f;
    #pragma unroll
    for (int j = 0; j < 4; j++) {
        int i = tid + j * 256;
        float val = x[row + i] + res[row + i];
        v[j] = val; s += val; s2 += val * val;
    }
    __shared__ float sh1[8], sh2[8];
    #pragma unroll
    for (int o = 16; o; o >>= 1) {
        s  += __shfl_xor_sync(0xffffffffu, s, o);
        s2 += __shfl_xor_sync(0xffffffffu, s2, o);
    }
    if ((tid & 31) == 0) { sh1[tid >> 5] = s; sh2[tid >> 5] = s2; }
    __syncthreads();
    float ts = 0.f, ts2 = 0.f;
    #pragma unroll
    for (int w = 0; w < 8; w++) { ts += sh1[w]; ts2 += sh2[w]; }
    const float mu  = ts * (1.f / En);
    const float var = ts2 * (1.f / En) - mu * mu;
    const float inv = rsqrtf(var + 1e-5f);
    #pragma unroll
    for (int j = 0; j < 4; j++) {
        int i = tid + j * 256;
        float o = (v[j] - mu) * inv * g[i] + b[i];
        out[row + i] = o;
        if (out_r) out_r[row + i] = __float2half_rn(o);
    }
}

// ======================= fused fp16 conversion pass =======================
#define NCVT 12
struct CvtJobs {
    const float4* src[NCVT];
    uint2* dst[NCVT];
    int cum[NCVT + 1];
};
__global__ __launch_bounds__(256) void cvt_multi(CvtJobs cj, int total4)
{
    for (int i = blockIdx.x * 256 + threadIdx.x; i < total4; i += gridDim.x * 256) {
        int job = 0;
        #pragma unroll
        for (int t = 0; t < NCVT - 1; t++) if (i >= cj.cum[t + 1]) job = t + 1;
        int off = i - cj.cum[job];
        float4 v = cj.src[job][off];
        __half2 h0 = __floats2half2_rn(v.x, v.y);
        __half2 h1 = __floats2half2_rn(v.z, v.w);
        uint2 u;
        u.x = *(uint32_t*)&h0;
        u.y = *(uint32_t*)&h1;
        cj.dst[job][off] = u;
    }
}

// ======================= host-side =======================
static cudaStream_t s2;
static cudaEvent_t ev_cvt, ev_kv, ev_fe, ev_wg;

static inline void gh_s(JobsH jobs, int M, int N, int K, int njobs, int postop,
                        cudaStream_t st)
{
    dim3 grid(N / 128, M / 128, njobs);
    hgemm2<<<grid, 256, H2_SMEM, st>>>(jobs, K, N, postop);
}

extern "C" void kernel_launch(void* const* d_in, const int* in_sizes, int n_in,
                              void* d_out, int out_size)
{
    static bool attr_done = false;
    if (!attr_done) {
        cudaFuncSetAttribute((const void*)hgemm2,
                             cudaFuncAttributeMaxDynamicSharedMemorySize, H2_SMEM);
        cudaFuncSetAttribute((const void*)flash_h<true>,
                             cudaFuncAttributeMaxDynamicSharedMemorySize, FLH_SMEM);
        cudaFuncSetAttribute((const void*)flash_h<false>,
                             cudaFuncAttributeMaxDynamicSharedMemorySize, FLH_SMEM);
        cudaFuncSetAttribute((const void*)wgemm,
                             cudaFuncAttributeMaxDynamicSharedMemorySize, WG_SMEM);
        cudaStreamCreateWithFlags(&s2, cudaStreamNonBlocking);
        cudaEventCreateWithFlags(&ev_cvt, cudaEventDisableTiming);
        cudaEventCreateWithFlags(&ev_kv,  cudaEventDisableTiming);
        cudaEventCreateWithFlags(&ev_fe,  cudaEventDisableTiming);
        cudaEventCreateWithFlags(&ev_wg,  cudaEventDisableTiming);
        attr_done = true;
    }

    const float* state = (const float*)d_in[0];
    const float* enc   = (const float*)d_in[1];
    const float* sa_wq = (const float*)d_in[3];  const float* sa_bq = (const float*)d_in[4];
    const float* sa_wk = (const float*)d_in[5];  const float* sa_bk = (const float*)d_in[6];
    const float* sa_wv = (const float*)d_in[7];  const float* sa_bv = (const float*)d_in[8];
    const float* sa_wo = (const float*)d_in[9];  const float* sa_bo = (const float*)d_in[10];
    const float* ea_wq = (const float*)d_in[11]; const float* ea_bq = (const float*)d_in[12];
    const float* ea_wk = (const float*)d_in[13]; const float* ea_bk = (const float*)d_in[14];
    const float* ea_wv = (const float*)d_in[15]; const float* ea_bv = (const float*)d_in[16];
    const float* ea_wo = (const float*)d_in[17]; const float* ea_bo = (const float*)d_in[18];
    const float* fc1_w = (const float*)d_in[19]; const float* fc1_b = (const float*)d_in[20];
    const float* fc2_w = (const float*)d_in[21]; const float* fc2_b = (const float*)d_in[22];
    const float* ln1_g = (const float*)d_in[23]; const float* ln1_b = (const float*)d_in[24];
    const float* ln2_g = (const float*)d_in[25]; const float* ln2_b = (const float*)d_in[26];
    const float* ln3_g = (const float*)d_in[27]; const float* ln3_b = (const float*)d_in[28];

    float *xq_f, *xk_f, *xv_f, *tmp, *st1, *st2, *rw;
    float *attn_f, *st1r_f, *st2r_f, *ffn_f;
    float2* stats;
    cudaGetSymbolAddress((void**)&xq_f,   g_xq);
    cudaGetSymbolAddress((void**)&xk_f,   g_xk);
    cudaGetSymbolAddress((void**)&xv_f,   g_xv);
    cudaGetSymbolAddress((void**)&attn_f, g_attn);
    cudaGetSymbolAddress((void**)&tmp,    g_tmp);
    cudaGetSymbolAddress((void**)&st1,    g_state1);
    cudaGetSymbolAddress((void**)&st2,    g_state2);
    cudaGetSymbolAddress((void**)&st1r_f, g_st1r);
    cudaGetSymbolAddress((void**)&st2r_f, g_st2r);
    cudaGetSymbolAddress((void**)&ffn_f,  g_ffn);
    cudaGetSymbolAddress((void**)&stats,  g_stats);
    cudaGetSymbolAddress((void**)&rw,     g_rw);

    __half* xq_h   = (__half*)xq_f;
    __half* xk_h   = (__half*)xk_f;
    __half* xv_h   = (__half*)xv_f;
    __half* attn_h = (__half*)attn_f;
    __half* st1r_h = (__half*)st1r_f;
    __half* st2r_h = (__half*)st2r_f;
    __half* ffn_h  = (__half*)ffn_f;
    __half* hp = (__half*)rw;
    __half* h_state = hp + 0L  * MEG;
    __half* h_enc   = hp + 4L  * MEG;
    __half* h_saq   = hp + 8L  * MEG;
    __half* h_sak   = hp + 9L  * MEG;
    __half* h_sav   = hp + 10L * MEG;
    __half* h_sao   = hp + 11L * MEG;
    __half* h_eaq   = hp + 12L * MEG;
    __half* h_eak   = hp + 13L * MEG;
    __half* h_eav   = hp + 14L * MEG;
    __half* h_eao   = hp + 15L * MEG;
    __half* h_fc1   = hp + 16L * MEG;
    __half* h_fc2   = hp + 20L * MEG;
    __half* eak_x   = hp + 24L * MEG;   // EA K projection [24M,32M)
    __half* eav_x   = hp + 32L * MEG;   // EA V projection [32M,40M)

    float* out_state = (float*)d_out;
    float* out_attn  = (float*)d_out + (long)Tn * Bn * En;

    // -------- fused fp16 conversion pass --------
    {
        CvtJobs cj;
        const float* srcs[NCVT] = {state, enc, sa_wq, sa_wk, sa_wv, sa_wo,
                                   ea_wq, ea_wk, ea_wv, ea_wo, fc1_w, fc2_w};
        __half* dsts[NCVT] = {h_state, h_enc, h_saq, h_sak, h_sav, h_sao,
                              h_eaq, h_eak, h_eav, h_eao, h_fc1, h_fc2};
        const int n4s[NCVT] = {MEG, MEG, MEG/4, MEG/4, MEG/4, MEG/4,
                               MEG/4, MEG/4, MEG/4, MEG/4, MEG, MEG};
        int c = 0;
        for (int i = 0; i < NCVT; i++) {
            cj.src[i] = (const float4*)srcs[i];
            cj.dst[i] = (uint2*)dsts[i];
            cj.cum[i] = c;
            c += n4s[i];
        }
        cj.cum[NCVT] = c;
        cvt_multi<<<1024, 256>>>(cj, c);
    }
    cudaEventRecord(ev_cvt, 0);

    // -------- side stream: EA K/V projections overlap the SA block --------
    cudaStreamWaitEvent(s2, ev_cvt, 0);
    {
        JobsH j = {{{h_enc, h_eak, ea_bk, eak_x},
                    {h_enc, h_eav, ea_bv, eav_x}, {}}};
        gh_s(j, ROWS, En, En, 2, 2, s2);
    }
    cudaEventRecord(ev_kv, s2);

    // ---------------- self-attention (fused flash, causal) ----------------
    {
        JobsH j = {{{h_state, h_saq, sa_bq, xq_h},
                    {h_state, h_sak, sa_bk, xk_h},
                    {h_state, h_sav, sa_bv, xv_h}}};
        gh_s(j, ROWS, En, En, 3, 2, 0);
    }
    flash_h<true><<<dim3(Tn / 128, BH), 256, FLH_SMEM>>>(xq_h, xk_h, xv_h, attn_h, nullptr);
    {
        JobsH j = {{{attn_h, h_sao, sa_bo, tmp}, {}, {}}};
        gh_s(j, ROWS, En, En, 1, 0, 0);
    }
    add_ln_kernel<<<ROWS, 256>>>(tmp, state, ln1_g, ln1_b, st1, st1r_h);

    // ---------------- encoder-decoder attention ----------------
    {
        JobsH j = {{{st1r_h, h_eaq, ea_bq, xq_h}, {}, {}}};
        gh_s(j, ROWS, En, En, 1, 2, 0);
    }
    cudaStreamWaitEvent(0, ev_kv, 0);
    flash_h<false><<<dim3(Tn / 128, BH), 256, FLH_SMEM>>>(xq_h, eak_x, eav_x, attn_h, stats);
    cudaEventRecord(ev_fe, 0);

    // side stream: normalized attention weights into d_out, overlapping FFN
    cudaStreamWaitEvent(s2, ev_fe, 0);
    wgemm<<<dim3(Sn / 128, Tn / 128, BH), 256, WG_SMEM, s2>>>(xq_h, eak_x, stats, out_attn);
    cudaEventRecord(ev_wg, s2);

    {
        JobsH j = {{{attn_h, h_eao, ea_bo, tmp}, {}, {}}};
        gh_s(j, ROWS, En, En, 1, 0, 0);
    }
    add_ln_kernel<<<ROWS, 256>>>(tmp, st1, ln2_g, ln2_b, st2, st2r_h);

    // ---------------- FFN ----------------
    {
        JobsH j = {{{st2r_h, h_fc1, fc1_b, ffn_h}, {}, {}}};
        gh_s(j, ROWS, FFn, En, 1, 1, 0);
    }
    {
        JobsH j = {{{ffn_h, h_fc2, fc2_b, tmp}, {}, {}}};
        gh_s(j, ROWS, En, FFn, 1, 0, 0);
    }
    add_ln_kernel<<<ROWS, 256>>>(tmp, st2, ln3_g, ln3_b, out_state, nullptr);

    // join: graph end depends on wgemm
    cudaStreamWaitEvent(0, ev_wg, 0);
}

// round 13
// speedup vs baseline: 7.3861x; 1.0190x over previous
#include <cuda_runtime.h>
#include <cuda_fp16.h>
#include <math.h>
#include <stdint.h>

// Problem dims
#define Tn 1024
#define Sn 1024
#define Bn 4
#define En 1024
#define Hn 16
#define DHn 64
#define FFn 4096
#define ROWS (Tn*Bn)
#define BH (Bn*Hn)
#define MEG (1024*1024)

// -------- scratch (device globals; no allocation) --------
__device__ float g_xq[ROWS*En];        // used as __half
__device__ float g_xk[ROWS*En];        // used as __half
__device__ float g_xv[ROWS*En];        // used as __half
__device__ float g_attn[ROWS*En];      // used as __half
__device__ float g_tmp[ROWS*En];
__device__ float g_state1[ROWS*En];
__device__ float g_state2[ROWS*En];
__device__ float g_st1r[ROWS*En];      // used as __half
__device__ float g_st2r[ROWS*En];      // used as __half
__device__ float g_ffn[ROWS*FFn];      // used as __half
__device__ float2 g_stats[BH*Tn];
__device__ float g_rw[24*MEG];         // used as __half pool (48M halfs)

// ======================= helpers =======================
__device__ __forceinline__ void mma_f16(float* c, const uint32_t* a, const uint32_t* b) {
    asm volatile(
        "mma.sync.aligned.m16n8k16.row.col.f32.f16.f16.f32 "
        "{%0,%1,%2,%3}, {%4,%5,%6,%7}, {%8,%9}, {%0,%1,%2,%3};"
        : "+f"(c[0]), "+f"(c[1]), "+f"(c[2]), "+f"(c[3])
        : "r"(a[0]), "r"(a[1]), "r"(a[2]), "r"(a[3]), "r"(b[0]), "r"(b[1]));
}
__device__ __forceinline__ void ldsm4(uint32_t* r, uint32_t addr) {
    asm volatile("ldmatrix.sync.aligned.m8n8.x4.shared.b16 {%0,%1,%2,%3}, [%4];"
        : "=r"(r[0]), "=r"(r[1]), "=r"(r[2]), "=r"(r[3]) : "r"(addr));
}
__device__ __forceinline__ void ldsm4t(uint32_t* r, uint32_t addr) {
    asm volatile("ldmatrix.sync.aligned.m8n8.x4.trans.shared.b16 {%0,%1,%2,%3}, [%4];"
        : "=r"(r[0]), "=r"(r[1]), "=r"(r[2]), "=r"(r[3]) : "r"(addr));
}
__device__ __forceinline__ void cp16(uint32_t dst, const void* src) {
    asm volatile("cp.async.cg.shared.global [%0], [%1], 16;" :: "r"(dst), "l"(src));
}
__device__ __forceinline__ void cp_commit() {
    asm volatile("cp.async.commit_group;" ::: "memory");
}
__device__ __forceinline__ void cp_wait0() {
    asm volatile("cp.async.wait_group 0;" ::: "memory");
}
__device__ __forceinline__ void cp_wait1() {
    asm volatile("cp.async.wait_group 1;" ::: "memory");
}
__device__ __forceinline__ uint32_t smaddr(const void* p) {
    return (uint32_t)__cvta_generic_to_shared(p);
}

// ======================= hgemm2: fp16 MMA + ldmatrix, 3-stage, 8 warps ============
// postop (per job): 0 = fp32 out; 1 = relu -> half out; 2 = half out;
//                   3 = (v * 0.125) -> half out   (exact pow2 scale for Q proj)
struct JobH { const __half* A; const __half* B; const float* bias; void* C; int postop; };
struct JobsH { JobH j[3]; };

#define H2_WS 36
#define H2_TILEW (128*H2_WS)
#define H2_SMEM (6*H2_TILEW*4)

__global__ __launch_bounds__(256, 2) void hgemm2(
    JobsH jobs, int K, int N)
{
    extern __shared__ uint32_t smw[];
    const int tid  = threadIdx.x;
    const int lane = tid & 31;
    const int wid  = tid >> 5;
    const int wm = wid & 1, wn = wid >> 1;
    const int m_base = wm * 64, n_base = wn * 32;
    const int g  = lane >> 2;
    const int tg = lane & 3;

    const JobH job = jobs.j[blockIdx.z];
    const int postop = job.postop;
    const int bm = blockIdx.y * 128;
    const int bn = blockIdx.x * 128;
    const __half* A = job.A + (long)bm * K;
    const __half* B = job.B + (long)bn * K;

    const int r0 = tid >> 3, c8 = tid & 7;
    const __half* aPtr = A + (long)r0 * K + c8 * 8;
    const __half* bPtr = B + (long)r0 * K + c8 * 8;
    const uint32_t aSm = smaddr(smw + r0 * H2_WS + c8 * 4);
    const uint32_t bSm = smaddr(smw + H2_TILEW + r0 * H2_WS + c8 * 4);
    const long rowAdv = 32L * K;

    auto load_slab = [&](int s, int st) {
        const uint32_t so = st * (2 * H2_TILEW * 4);
        const __half* ap = aPtr + s * 64;
        const __half* bp = bPtr + s * 64;
        #pragma unroll
        for (int it = 0; it < 4; it++) {
            cp16(aSm + so + it * (32 * H2_WS * 4), ap + it * rowAdv);
            cp16(bSm + so + it * (32 * H2_WS * 4), bp + it * rowAdv);
        }
        cp_commit();
    };

    uint32_t aLd[4];
    {
        int rowl = lane & 15;
        uint32_t kcb = (lane >> 4) * 16;
        #pragma unroll
        for (int mi = 0; mi < 4; mi++)
            aLd[mi] = smaddr(smw + (m_base + mi * 16 + rowl) * H2_WS) + kcb;
    }
    uint32_t bLd[2];
    {
        int rowl = (lane & 7) + ((lane >> 4) * 8);
        uint32_t kcb = ((lane >> 3) & 1) * 16;
        #pragma unroll
        for (int p = 0; p < 2; p++)
            bLd[p] = smaddr(smw + H2_TILEW + (n_base + p * 16 + rowl) * H2_WS) + kcb;
    }

    float acc[4][4][4];
    #pragma unroll
    for (int mi = 0; mi < 4; mi++)
        #pragma unroll
        for (int ni = 0; ni < 4; ni++)
            #pragma unroll
            for (int r = 0; r < 4; r++) acc[mi][ni][r] = 0.f;

    const int nslab = K >> 6;
    load_slab(0, 0);
    if (nslab > 1) load_slab(1, 1); else cp_commit();

    int st = 0;
    for (int s = 0; s < nslab; s++) {
        cp_wait1();
        __syncthreads();
        if (s + 2 < nslab) load_slab(s + 2, (st + 2) % 3);
        else cp_commit();

        const uint32_t so = st * (2 * H2_TILEW * 4);

        #pragma unroll
        for (int kw = 0; kw < 32; kw += 8) {
            uint32_t afr[4][4], bfr[2][4];
            #pragma unroll
            for (int mi = 0; mi < 4; mi++) ldsm4(afr[mi], aLd[mi] + so + kw * 4);
            #pragma unroll
            for (int p = 0; p < 2; p++)    ldsm4(bfr[p], bLd[p] + so + kw * 4);
            #pragma unroll
            for (int mi = 0; mi < 4; mi++)
                #pragma unroll
                for (int ni = 0; ni < 4; ni++) {
                    uint32_t bq[2] = { bfr[ni >> 1][(ni & 1) * 2],
                                       bfr[ni >> 1][(ni & 1) * 2 + 1] };
                    mma_f16(acc[mi][ni], afr[mi], bq);
                }
        }
        st = (st + 1) % 3;
    }

    const float* bias = job.bias;
    #pragma unroll
    for (int mi = 0; mi < 4; mi++) {
        int row0 = bm + m_base + mi * 16 + g;
        #pragma unroll
        for (int ni = 0; ni < 4; ni++) {
            int col = bn + n_base + ni * 8 + tg * 2;
            float b0 = bias[col], b1 = bias[col + 1];
            float v0 = acc[mi][ni][0] + b0;
            float v1 = acc[mi][ni][1] + b1;
            float v2 = acc[mi][ni][2] + b0;
            float v3 = acc[mi][ni][3] + b1;
            if (postop == 0) {
                float* C = (float*)job.C;
                *(float2*)&C[(long)row0 * N + col]       = make_float2(v0, v1);
                *(float2*)&C[(long)(row0 + 8) * N + col] = make_float2(v2, v3);
            } else {
                if (postop == 1) {
                    v0 = fmaxf(v0, 0.f); v1 = fmaxf(v1, 0.f);
                    v2 = fmaxf(v2, 0.f); v3 = fmaxf(v3, 0.f);
                } else if (postop == 3) {
                    v0 *= 0.125f; v1 *= 0.125f; v2 *= 0.125f; v3 *= 0.125f;
                }
                __half* C = (__half*)job.C;
                *(__half2*)&C[(long)row0 * N + col]       = __floats2half2_rn(v0, v1);
                *(__half2*)&C[(long)(row0 + 8) * N + col] = __floats2half2_rn(v2, v3);
            }
        }
    }
}

// ======================= fp16 fused flash attention =======================
// NOTE: Q is pre-scaled by 1/8 (exact), so S needs no scaling here.
#define FLH_SMEM (18432*4)

template<bool CAUSAL>
__global__ __launch_bounds__(256, 2) void flash_h(
    const __half* __restrict__ Qp, const __half* __restrict__ Kp,
    const __half* __restrict__ Vp, __half* __restrict__ Op,
    float2* __restrict__ stats)
{
    extern __shared__ uint32_t smw[];
    const int tid = threadIdx.x;
    const int lane = tid & 31, w = tid >> 5;
    const int g = lane >> 2, tg = lane & 3;
    const int bh = blockIdx.y;
    const int it = CAUSAL ? ((int)gridDim.x - 1 - (int)blockIdx.x) : (int)blockIdx.x;
    const int t0 = it * 128;
    const int nIter = CAUSAL ? 2 * it + 2 : 16;

    const __half* Qg = Qp + (long)t0 * 4096 + bh * 64;
    const __half* Kg = Kp + bh * 64;
    const __half* Vg = Vp + bh * 64;

    auto loadKV = [&](int j, int buf) {
        const long s0 = (long)j * 64;
        const uint32_t kb = smaddr(smw + 4608 + buf * 2304);
        const uint32_t vb = smaddr(smw + 9216 + buf * 2304);
        #pragma unroll
        for (int i = 0; i < 2; i++) {
            int idx = tid + i * 256;
            int row = idx >> 3, c = idx & 7;
            cp16(kb + row * 144 + c * 16, Kg + (s0 + row) * 4096 + c * 8);
            cp16(vb + row * 144 + c * 16, Vg + (s0 + row) * 4096 + c * 8);
        }
    };

    #pragma unroll
    for (int i = 0; i < 4; i++) {
        int idx = tid + i * 256;
        int row = idx >> 3, c = idx & 7;
        cp16(smaddr(smw) + row * 144 + c * 16, Qg + (long)row * 4096 + c * 8);
    }
    loadKV(0, 0);
    cp_commit();
    cp_wait0();
    __syncthreads();

    uint32_t qf[4][4];
    {
        uint32_t qbase = smaddr(smw) + (16 * w + (lane & 15)) * 144 + (lane >> 4) * 16;
        #pragma unroll
        for (int kk = 0; kk < 4; kk++) ldsm4(qf[kk], qbase + kk * 32);
    }
    uint32_t kbl[4];
    {
        int rowl = (lane & 7) + ((lane >> 4) * 8);
        uint32_t kcb = ((lane >> 3) & 1) * 16;
        #pragma unroll
        for (int p = 0; p < 4; p++)
            kbl[p] = smaddr(smw + 4608) + (p * 16 + rowl) * 144 + kcb;
    }
    uint32_t vbl[4];
    {
        int rowv = (lane & 7) + (((lane >> 3) & 1) * 8);
        uint32_t kcv = (lane >> 4) * 16;
        #pragma unroll
        for (int p = 0; p < 4; p++)
            vbl[p] = smaddr(smw + 9216) + rowv * 144 + kcv + p * 32;
    }
    uint32_t pbase = smaddr(smw + 13824) + (16 * w + (lane & 15)) * 144 + (lane >> 4) * 16;
    __half* Pw = (__half*)(smw + 13824) + (16 * w + g) * 72;

    float acc_o[8][4];
    #pragma unroll
    for (int ni = 0; ni < 8; ni++)
        #pragma unroll
        for (int r = 0; r < 4; r++) acc_o[ni][r] = 0.f;
    float m0 = -1e30f, m1 = -1e30f, l0 = 0.f, l1 = 0.f;

    for (int j = 0; j < nIter; j++) {
        const int buf = j & 1;
        const uint32_t bofs = buf * 9216;
        if (j + 1 < nIter) { loadKV(j + 1, buf ^ 1); cp_commit(); }

        float s_acc[8][4];
        #pragma unroll
        for (int ni = 0; ni < 8; ni++)
            #pragma unroll
            for (int r = 0; r < 4; r++) s_acc[ni][r] = 0.f;
        #pragma unroll
        for (int kk = 0; kk < 4; kk++) {
            uint32_t kfr[4][4];
            #pragma unroll
            for (int p = 0; p < 4; p++) ldsm4(kfr[p], kbl[p] + bofs + kk * 32);
            #pragma unroll
            for (int ni = 0; ni < 8; ni++) {
                uint32_t bq[2] = { kfr[ni >> 1][(ni & 1) * 2],
                                   kfr[ni >> 1][(ni & 1) * 2 + 1] };
                mma_f16(s_acc[ni], qf[kk], bq);
            }
        }

        const int s0 = j * 64;
        const bool need = CAUSAL && (s0 + 63 > t0 + 16 * w);
        const int tr0 = t0 + 16 * w + g, tr1 = tr0 + 8;
        float mx0 = -1e30f, mx1 = -1e30f;
        #pragma unroll
        for (int ni = 0; ni < 8; ni++) {
            float v0 = s_acc[ni][0];
            float v1 = s_acc[ni][1];
            float v2 = s_acc[ni][2];
            float v3 = s_acc[ni][3];
            if (need) {
                int c0 = s0 + ni * 8 + 2 * tg, c1 = c0 + 1;
                if (c0 > tr0) v0 -= 1e9f;
                if (c1 > tr0) v1 -= 1e9f;
                if (c0 > tr1) v2 -= 1e9f;
                if (c1 > tr1) v3 -= 1e9f;
                s_acc[ni][0] = v0; s_acc[ni][1] = v1;
                s_acc[ni][2] = v2; s_acc[ni][3] = v3;
            }
            mx0 = fmaxf(mx0, fmaxf(v0, v1));
            mx1 = fmaxf(mx1, fmaxf(v2, v3));
        }
        mx0 = fmaxf(mx0, __shfl_xor_sync(0xffffffffu, mx0, 1));
        mx0 = fmaxf(mx0, __shfl_xor_sync(0xffffffffu, mx0, 2));
        mx1 = fmaxf(mx1, __shfl_xor_sync(0xffffffffu, mx1, 1));
        mx1 = fmaxf(mx1, __shfl_xor_sync(0xffffffffu, mx1, 2));
        const float mn0 = fmaxf(m0, mx0), mn1 = fmaxf(m1, mx1);
        const float sc0 = __expf(m0 - mn0), sc1 = __expf(m1 - mn1);
        m0 = mn0; m1 = mn1;

        float sum0 = 0.f, sum1 = 0.f;
        #pragma unroll
        for (int ni = 0; ni < 8; ni++) {
            float p0 = __expf(s_acc[ni][0] - m0);
            float p1 = __expf(s_acc[ni][1] - m0);
            float p2 = __expf(s_acc[ni][2] - m1);
            float p3 = __expf(s_acc[ni][3] - m1);
            sum0 += p0 + p1; sum1 += p2 + p3;
            *(__half2*)&Pw[ni * 8 + 2 * tg]          = __floats2half2_rn(p0, p1);
            *(__half2*)&Pw[8 * 72 + ni * 8 + 2 * tg] = __floats2half2_rn(p2, p3);
        }
        sum0 += __shfl_xor_sync(0xffffffffu, sum0, 1);
        sum0 += __shfl_xor_sync(0xffffffffu, sum0, 2);
        sum1 += __shfl_xor_sync(0xffffffffu, sum1, 1);
        sum1 += __shfl_xor_sync(0xffffffffu, sum1, 2);
        l0 = l0 * sc0 + sum0;
        l1 = l1 * sc1 + sum1;
        #pragma unroll
        for (int ni = 0; ni < 8; ni++) {
            acc_o[ni][0] *= sc0; acc_o[ni][1] *= sc0;
            acc_o[ni][2] *= sc1; acc_o[ni][3] *= sc1;
        }
        __syncwarp();

        #pragma unroll
        for (int kk = 0; kk < 4; kk++) {
            uint32_t pf[4];
            ldsm4(pf, pbase + kk * 32);
            uint32_t vfr[4][4];
            #pragma unroll
            for (int p = 0; p < 4; p++) ldsm4t(vfr[p], vbl[p] + bofs + kk * 2304);
            #pragma unroll
            for (int ni = 0; ni < 8; ni++) {
                uint32_t bq[2] = { vfr[ni >> 1][(ni & 1) * 2],
                                   vfr[ni >> 1][(ni & 1) * 2 + 1] };
                mma_f16(acc_o[ni], pf, bq);
            }
        }
        if (j + 1 < nIter) cp_wait0();
        __syncthreads();
    }

    const float inv0 = 1.f / l0, inv1 = 1.f / l1;
    const int r0 = t0 + 16 * w + g;
    __half* o0 = Op + (long)r0 * 4096 + bh * 64;
    __half* o1 = o0 + 8L * 4096;
    #pragma unroll
    for (int ni = 0; ni < 8; ni++) {
        *(__half2*)&o0[ni * 8 + 2 * tg] =
            __floats2half2_rn(acc_o[ni][0] * inv0, acc_o[ni][1] * inv0);
        *(__half2*)&o1[ni * 8 + 2 * tg] =
            __floats2half2_rn(acc_o[ni][2] * inv1, acc_o[ni][3] * inv1);
    }
    if (!CAUSAL && tg == 0) {
        stats[bh * Tn + r0]     = make_float2(m0, l0);
        stats[bh * Tn + r0 + 8] = make_float2(m1, l1);
    }
}

// ======================= wgemm: EA normalized attention weights ============
// Q pre-scaled by 1/8; C = __expf(acc - m)/l.
#define WG_SMEM (9216*4)

__global__ __launch_bounds__(256, 2) void wgemm(
    const __half* __restrict__ Qh, const __half* __restrict__ Kh,
    const float2* __restrict__ stats, float* __restrict__ C)
{
    extern __shared__ uint32_t smw[];
    const int tid  = threadIdx.x;
    const int lane = tid & 31;
    const int wid  = tid >> 5;
    const int wm = wid & 1, wn = wid >> 1;
    const int m_base = wm * 64, n_base = wn * 32;
    const int g  = lane >> 2;
    const int tg = lane & 3;
    const int z  = blockIdx.z;
    const int bm = blockIdx.y * 128;
    const int bn = blockIdx.x * 128;

    const __half* A = Qh + (long)z * 64 + (long)bm * 4096;
    const __half* B = Kh + (long)z * 64 + (long)bn * 4096;

    #pragma unroll
    for (int i = 0; i < 4; i++) {
        int idx = tid + i * 256;
        int row = idx >> 3, c = idx & 7;
        cp16(smaddr(smw) + row * 144 + c * 16, A + (long)row * 4096 + c * 8);
        cp16(smaddr(smw + 4608) + row * 144 + c * 16, B + (long)row * 4096 + c * 8);
    }
    cp_commit();
    cp_wait0();
    __syncthreads();

    uint32_t aLd[4], bLd[2];
    {
        int rowl = lane & 15;
        uint32_t kcb = (lane >> 4) * 16;
        #pragma unroll
        for (int mi = 0; mi < 4; mi++)
            aLd[mi] = smaddr(smw) + (m_base + mi * 16 + rowl) * 144 + kcb;
    }
    {
        int rowl = (lane & 7) + ((lane >> 4) * 8);
        uint32_t kcb = ((lane >> 3) & 1) * 16;
        #pragma unroll
        for (int p = 0; p < 2; p++)
            bLd[p] = smaddr(smw + 4608) + (n_base + p * 16 + rowl) * 144 + kcb;
    }

    float acc[4][4][4];
    #pragma unroll
    for (int mi = 0; mi < 4; mi++)
        #pragma unroll
        for (int ni = 0; ni < 4; ni++)
            #pragma unroll
            for (int r = 0; r < 4; r++) acc[mi][ni][r] = 0.f;

    #pragma unroll
    for (int kk = 0; kk < 4; kk++) {
        uint32_t afr[4][4], bfr[2][4];
        #pragma unroll
        for (int mi = 0; mi < 4; mi++) ldsm4(afr[mi], aLd[mi] + kk * 32);
        #pragma unroll
        for (int p = 0; p < 2; p++)    ldsm4(bfr[p], bLd[p] + kk * 32);
        #pragma unroll
        for (int mi = 0; mi < 4; mi++)
            #pragma unroll
            for (int ni = 0; ni < 4; ni++) {
                uint32_t bq[2] = { bfr[ni >> 1][(ni & 1) * 2],
                                   bfr[ni >> 1][(ni & 1) * 2 + 1] };
                mma_f16(acc[mi][ni], afr[mi], bq);
            }
    }

    #pragma unroll
    for (int mi = 0; mi < 4; mi++) {
        int row0 = bm + m_base + mi * 16 + g;
        float2 ml0 = stats[z * Tn + row0];
        float2 ml1 = stats[z * Tn + row0 + 8];
        float i0 = 1.f / ml0.y, i1 = 1.f / ml1.y;
        #pragma unroll
        for (int ni = 0; ni < 4; ni++) {
            int col = bn + n_base + ni * 8 + tg * 2;
            float v0 = __expf(acc[mi][ni][0] - ml0.x) * i0;
            float v1 = __expf(acc[mi][ni][1] - ml0.x) * i0;
            float v2 = __expf(acc[mi][ni][2] - ml1.x) * i1;
            float v3 = __expf(acc[mi][ni][3] - ml1.x) * i1;
            float* Cz = C + (long)z * Tn * Sn;
            *(float2*)&Cz[(long)row0 * Sn + col]       = make_float2(v0, v1);
            *(float2*)&Cz[(long)(row0 + 8) * Sn + col] = make_float2(v2, v3);
        }
    }
}

// ======================= out = LayerNorm(x+res)*g+b ; optional half copy
__global__ __launch_bounds__(256) void add_ln_kernel(
    const float* __restrict__ x, const float* __restrict__ res,
    const float* __restrict__ g, const float* __restrict__ b,
    float* __restrict__ out, __half* __restrict__ out_r)
{
    const long row = (long)blockIdx.x * En;
    const int tid = threadIdx.x;
    float v[4]; float s = 0.f, s2 = 0.f;
    #pragma unroll
    for (int j = 0; j < 4; j++) {
        int i = tid + j * 256;
        float val = x[row + i] + res[row + i];
        v[j] = val; s += val; s2 += val * val;
    }
    __shared__ float sh1[8], sh2[8];
    #pragma unroll
    for (int o = 16; o; o >>= 1) {
        s  += __shfl_xor_sync(0xffffffffu, s, o);
        s2 += __shfl_xor_sync(0xffffffffu, s2, o);
    }
    if ((tid & 31) == 0) { sh1[tid >> 5] = s; sh2[tid >> 5] = s2; }
    __syncthreads();
    float ts = 0.f, ts2 = 0.f;
    #pragma unroll
    for (int w = 0; w < 8; w++) { ts += sh1[w]; ts2 += sh2[w]; }
    const float mu  = ts * (1.f / En);
    const float var = ts2 * (1.f / En) - mu * mu;
    const float inv = rsqrtf(var + 1e-5f);
    #pragma unroll
    for (int j = 0; j < 4; j++) {
        int i = tid + j * 256;
        float o = (v[j] - mu) * inv * g[i] + b[i];
        out[row + i] = o;
        if (out_r) out_r[row + i] = __float2half_rn(o);
    }
}

// ======================= fused fp16 conversion pass =======================
#define NCVT 12
struct CvtJobs {
    const float4* src[NCVT];
    uint2* dst[NCVT];
    int cum[NCVT + 1];
};
__global__ __launch_bounds__(256) void cvt_multi(CvtJobs cj, int total4)
{
    for (int i = blockIdx.x * 256 + threadIdx.x; i < total4; i += gridDim.x * 256) {
        int job = 0;
        #pragma unroll
        for (int t = 0; t < NCVT - 1; t++) if (i >= cj.cum[t + 1]) job = t + 1;
        int off = i - cj.cum[job];
        float4 v = cj.src[job][off];
        __half2 h0 = __floats2half2_rn(v.x, v.y);
        __half2 h1 = __floats2half2_rn(v.z, v.w);
        uint2 u;
        u.x = *(uint32_t*)&h0;
        u.y = *(uint32_t*)&h1;
        cj.dst[job][off] = u;
    }
}

// ======================= host-side =======================
static cudaStream_t s2;
static cudaEvent_t ev_cvt, ev_kv, ev_fe, ev_wg;

static inline void gh_s(JobsH jobs, int M, int N, int K, int njobs, cudaStream_t st)
{
    dim3 grid(N / 128, M / 128, njobs);
    hgemm2<<<grid, 256, H2_SMEM, st>>>(jobs, K, N);
}

extern "C" void kernel_launch(void* const* d_in, const int* in_sizes, int n_in,
                              void* d_out, int out_size)
{
    static bool attr_done = false;
    if (!attr_done) {
        cudaFuncSetAttribute((const void*)hgemm2,
                             cudaFuncAttributeMaxDynamicSharedMemorySize, H2_SMEM);
        cudaFuncSetAttribute((const void*)flash_h<true>,
                             cudaFuncAttributeMaxDynamicSharedMemorySize, FLH_SMEM);
        cudaFuncSetAttribute((const void*)flash_h<false>,
                             cudaFuncAttributeMaxDynamicSharedMemorySize, FLH_SMEM);
        cudaFuncSetAttribute((const void*)wgemm,
                             cudaFuncAttributeMaxDynamicSharedMemorySize, WG_SMEM);
        cudaStreamCreateWithFlags(&s2, cudaStreamNonBlocking);
        cudaEventCreateWithFlags(&ev_cvt, cudaEventDisableTiming);
        cudaEventCreateWithFlags(&ev_kv,  cudaEventDisableTiming);
        cudaEventCreateWithFlags(&ev_fe,  cudaEventDisableTiming);
        cudaEventCreateWithFlags(&ev_wg,  cudaEventDisableTiming);
        attr_done = true;
    }

    const float* state = (const float*)d_in[0];
    const float* enc   = (const float*)d_in[1];
    const float* sa_wq = (const float*)d_in[3];  const float* sa_bq = (const float*)d_in[4];
    const float* sa_wk = (const float*)d_in[5];  const float* sa_bk = (const float*)d_in[6];
    const float* sa_wv = (const float*)d_in[7];  const float* sa_bv = (const float*)d_in[8];
    const float* sa_wo = (const float*)d_in[9];  const float* sa_bo = (const float*)d_in[10];
    const float* ea_wq = (const float*)d_in[11]; const float* ea_bq = (const float*)d_in[12];
    const float* ea_wk = (const float*)d_in[13]; const float* ea_bk = (const float*)d_in[14];
    const float* ea_wv = (const float*)d_in[15]; const float* ea_bv = (const float*)d_in[16];
    const float* ea_wo = (const float*)d_in[17]; const float* ea_bo = (const float*)d_in[18];
    const float* fc1_w = (const float*)d_in[19]; const float* fc1_b = (const float*)d_in[20];
    const float* fc2_w = (const float*)d_in[21]; const float* fc2_b = (const float*)d_in[22];
    const float* ln1_g = (const float*)d_in[23]; const float* ln1_b = (const float*)d_in[24];
    const float* ln2_g = (const float*)d_in[25]; const float* ln2_b = (const float*)d_in[26];
    const float* ln3_g = (const float*)d_in[27]; const float* ln3_b = (const float*)d_in[28];

    float *xq_f, *xk_f, *xv_f, *tmp, *st1, *st2, *rw;
    float *attn_f, *st1r_f, *st2r_f, *ffn_f;
    float2* stats;
    cudaGetSymbolAddress((void**)&xq_f,   g_xq);
    cudaGetSymbolAddress((void**)&xk_f,   g_xk);
    cudaGetSymbolAddress((void**)&xv_f,   g_xv);
    cudaGetSymbolAddress((void**)&attn_f, g_attn);
    cudaGetSymbolAddress((void**)&tmp,    g_tmp);
    cudaGetSymbolAddress((void**)&st1,    g_state1);
    cudaGetSymbolAddress((void**)&st2,    g_state2);
    cudaGetSymbolAddress((void**)&st1r_f, g_st1r);
    cudaGetSymbolAddress((void**)&st2r_f, g_st2r);
    cudaGetSymbolAddress((void**)&ffn_f,  g_ffn);
    cudaGetSymbolAddress((void**)&stats,  g_stats);
    cudaGetSymbolAddress((void**)&rw,     g_rw);

    __half* xq_h   = (__half*)xq_f;
    __half* xk_h   = (__half*)xk_f;
    __half* xv_h   = (__half*)xv_f;
    __half* attn_h = (__half*)attn_f;
    __half* st1r_h = (__half*)st1r_f;
    __half* st2r_h = (__half*)st2r_f;
    __half* ffn_h  = (__half*)ffn_f;
    __half* hp = (__half*)rw;
    __half* h_state = hp + 0L  * MEG;
    __half* h_enc   = hp + 4L  * MEG;
    __half* h_saq   = hp + 8L  * MEG;
    __half* h_sak   = hp + 9L  * MEG;
    __half* h_sav   = hp + 10L * MEG;
    __half* h_sao   = hp + 11L * MEG;
    __half* h_eaq   = hp + 12L * MEG;
    __half* h_eak   = hp + 13L * MEG;
    __half* h_eav   = hp + 14L * MEG;
    __half* h_eao   = hp + 15L * MEG;
    __half* h_fc1   = hp + 16L * MEG;
    __half* h_fc2   = hp + 20L * MEG;
    __half* eak_x   = hp + 24L * MEG;
    __half* eav_x   = hp + 32L * MEG;

    float* out_state = (float*)d_out;
    float* out_attn  = (float*)d_out + (long)Tn * Bn * En;

    // -------- fused fp16 conversion pass --------
    {
        CvtJobs cj;
        const float* srcs[NCVT] = {state, enc, sa_wq, sa_wk, sa_wv, sa_wo,
                                   ea_wq, ea_wk, ea_wv, ea_wo, fc1_w, fc2_w};
        __half* dsts[NCVT] = {h_state, h_enc, h_saq, h_sak, h_sav, h_sao,
                              h_eaq, h_eak, h_eav, h_eao, h_fc1, h_fc2};
        const int n4s[NCVT] = {MEG, MEG, MEG/4, MEG/4, MEG/4, MEG/4,
                               MEG/4, MEG/4, MEG/4, MEG/4, MEG, MEG};
        int c = 0;
        for (int i = 0; i < NCVT; i++) {
            cj.src[i] = (const float4*)srcs[i];
            cj.dst[i] = (uint2*)dsts[i];
            cj.cum[i] = c;
            c += n4s[i];
        }
        cj.cum[NCVT] = c;
        cvt_multi<<<1024, 256>>>(cj, c);
    }
    cudaEventRecord(ev_cvt, 0);

    // -------- side stream: EA K/V projections overlap the SA block --------
    cudaStreamWaitEvent(s2, ev_cvt, 0);
    {
        JobsH j = {{{h_enc, h_eak, ea_bk, eak_x, 2},
                    {h_enc, h_eav, ea_bv, eav_x, 2}, {}}};
        gh_s(j, ROWS, En, En, 2, s2);
    }
    cudaEventRecord(ev_kv, s2);

    // ---------------- self-attention (fused flash, causal) ----------------
    {
        JobsH j = {{{h_state, h_saq, sa_bq, xq_h, 3},     // Q pre-scaled by 1/8
                    {h_state, h_sak, sa_bk, xk_h, 2},
                    {h_state, h_sav, sa_bv, xv_h, 2}}};
        gh_s(j, ROWS, En, En, 3, 0);
    }
    flash_h<true><<<dim3(Tn / 128, BH), 256, FLH_SMEM>>>(xq_h, xk_h, xv_h, attn_h, nullptr);
    {
        JobsH j = {{{attn_h, h_sao, sa_bo, tmp, 0}, {}, {}}};
        gh_s(j, ROWS, En, En, 1, 0);
    }
    add_ln_kernel<<<ROWS, 256>>>(tmp, state, ln1_g, ln1_b, st1, st1r_h);

    // ---------------- encoder-decoder attention ----------------
    {
        JobsH j = {{{st1r_h, h_eaq, ea_bq, xq_h, 3}, {}, {}}};   // pre-scaled
        gh_s(j, ROWS, En, En, 1, 0);
    }
    cudaStreamWaitEvent(0, ev_kv, 0);
    flash_h<false><<<dim3(Tn / 128, BH), 256, FLH_SMEM>>>(xq_h, eak_x, eav_x, attn_h, stats);
    cudaEventRecord(ev_fe, 0);

    // side stream: normalized attention weights into d_out, overlapping FFN
    cudaStreamWaitEvent(s2, ev_fe, 0);
    wgemm<<<dim3(Sn / 128, Tn / 128, BH), 256, WG_SMEM, s2>>>(xq_h, eak_x, stats, out_attn);
    cudaEventRecord(ev_wg, s2);

    {
        JobsH j = {{{attn_h, h_eao, ea_bo, tmp, 0}, {}, {}}};
        gh_s(j, ROWS, En, En, 1, 0);
    }
    add_ln_kernel<<<ROWS, 256>>>(tmp, st1, ln2_g, ln2_b, st2, st2r_h);

    // ---------------- FFN ----------------
    {
        JobsH j = {{{st2r_h, h_fc1, fc1_b, ffn_h, 1}, {}, {}}};
        gh_s(j, ROWS, FFn, En, 1, 0);
    }
    {
        JobsH j = {{{ffn_h, h_fc2, fc2_b, tmp, 0}, {}, {}}};
        gh_s(j, ROWS, En, FFn, 1, 0);
    }
    add_ln_kernel<<<ROWS, 256>>>(tmp, st2, ln3_g, ln3_b, out_state, nullptr);

    // join: graph end depends on wgemm
    cudaStreamWaitEvent(0, ev_wg, 0);
}

// round 15
// speedup vs baseline: 7.5567x; 1.0231x over previous
#include <cuda_runtime.h>
#include <cuda_fp16.h>
#include <math.h>
#include <stdint.h>

// Problem dims
#define Tn 1024
#define Sn 1024
#define Bn 4
#define En 1024
#define Hn 16
#define DHn 64
#define FFn 4096
#define ROWS (Tn*Bn)
#define BH (Bn*Hn)
#define MEG (1024*1024)

// -------- scratch (device globals; no allocation) --------
__device__ float g_xq[ROWS*En];        // used as __half
__device__ float g_xk[ROWS*En];        // used as __half
__device__ float g_xv[ROWS*En];        // used as __half
__device__ float g_attn[ROWS*En];      // used as __half
__device__ float g_tmp[ROWS*En];
__device__ float g_state1[ROWS*En];
__device__ float g_state2[ROWS*En];
__device__ float g_st1r[ROWS*En];      // used as __half
__device__ float g_st2r[ROWS*En];      // used as __half
__device__ float g_ffn[ROWS*FFn];      // used as __half
__device__ float2 g_stats[BH*Tn];
__device__ float g_rw[24*MEG];         // used as __half pool (48M halfs)

// ======================= helpers =======================
__device__ __forceinline__ void mma_f16(float* c, const uint32_t* a, const uint32_t* b) {
    asm volatile(
        "mma.sync.aligned.m16n8k16.row.col.f32.f16.f16.f32 "
        "{%0,%1,%2,%3}, {%4,%5,%6,%7}, {%8,%9}, {%0,%1,%2,%3};"
        : "+f"(c[0]), "+f"(c[1]), "+f"(c[2]), "+f"(c[3])
        : "r"(a[0]), "r"(a[1]), "r"(a[2]), "r"(a[3]), "r"(b[0]), "r"(b[1]));
}
__device__ __forceinline__ void ldsm4(uint32_t* r, uint32_t addr) {
    asm volatile("ldmatrix.sync.aligned.m8n8.x4.shared.b16 {%0,%1,%2,%3}, [%4];"
        : "=r"(r[0]), "=r"(r[1]), "=r"(r[2]), "=r"(r[3]) : "r"(addr));
}
__device__ __forceinline__ void ldsm4t(uint32_t* r, uint32_t addr) {
    asm volatile("ldmatrix.sync.aligned.m8n8.x4.trans.shared.b16 {%0,%1,%2,%3}, [%4];"
        : "=r"(r[0]), "=r"(r[1]), "=r"(r[2]), "=r"(r[3]) : "r"(addr));
}
__device__ __forceinline__ void cp16(uint32_t dst, const void* src) {
    asm volatile("cp.async.cg.shared.global [%0], [%1], 16;" :: "r"(dst), "l"(src));
}
__device__ __forceinline__ void cp_commit() {
    asm volatile("cp.async.commit_group;" ::: "memory");
}
__device__ __forceinline__ void cp_wait0() {
    asm volatile("cp.async.wait_group 0;" ::: "memory");
}
__device__ __forceinline__ void cp_wait1() {
    asm volatile("cp.async.wait_group 1;" ::: "memory");
}
__device__ __forceinline__ uint32_t smaddr(const void* p) {
    return (uint32_t)__cvta_generic_to_shared(p);
}
__device__ __forceinline__ uint32_t hex2(uint32_t x) {   // ex2 on packed half2
    uint32_t r;
    asm("ex2.approx.f16x2 %0, %1;" : "=r"(r) : "r"(x));
    return r;
}
__device__ __forceinline__ uint32_t packh2(float a, float b) {
    __half2 h = __floats2half2_rn(a, b);
    return *(uint32_t*)&h;
}

// ======================= hgemm2: fp16 MMA + ldmatrix, 3-stage, 8 warps ============
// postop (per job): 0 = fp32 out; 1 = relu -> half out; 2 = half out;
//                   3 = (v * 0.125) -> half out
struct JobH { const __half* A; const __half* B; const float* bias; void* C; int postop; };
struct JobsH { JobH j[3]; };

#define H2_WS 36
#define H2_TILEW (128*H2_WS)
#define H2_SMEM (6*H2_TILEW*4)

__global__ __launch_bounds__(256, 2) void hgemm2(
    JobsH jobs, int K, int N)
{
    extern __shared__ uint32_t smw[];
    const int tid  = threadIdx.x;
    const int lane = tid & 31;
    const int wid  = tid >> 5;
    const int wm = wid & 1, wn = wid >> 1;
    const int m_base = wm * 64, n_base = wn * 32;
    const int g  = lane >> 2;
    const int tg = lane & 3;

    const JobH job = jobs.j[blockIdx.z];
    const int postop = job.postop;
    const int bm = blockIdx.y * 128;
    const int bn = blockIdx.x * 128;
    const __half* A = job.A + (long)bm * K;
    const __half* B = job.B + (long)bn * K;

    const int r0 = tid >> 3, c8 = tid & 7;
    const __half* aPtr = A + (long)r0 * K + c8 * 8;
    const __half* bPtr = B + (long)r0 * K + c8 * 8;
    const uint32_t aSm = smaddr(smw + r0 * H2_WS + c8 * 4);
    const uint32_t bSm = smaddr(smw + H2_TILEW + r0 * H2_WS + c8 * 4);
    const long rowAdv = 32L * K;

    auto load_slab = [&](int s, int st) {
        const uint32_t so = st * (2 * H2_TILEW * 4);
        const __half* ap = aPtr + s * 64;
        const __half* bp = bPtr + s * 64;
        #pragma unroll
        for (int it = 0; it < 4; it++) {
            cp16(aSm + so + it * (32 * H2_WS * 4), ap + it * rowAdv);
            cp16(bSm + so + it * (32 * H2_WS * 4), bp + it * rowAdv);
        }
        cp_commit();
    };

    uint32_t aLd[4];
    {
        int rowl = lane & 15;
        uint32_t kcb = (lane >> 4) * 16;
        #pragma unroll
        for (int mi = 0; mi < 4; mi++)
            aLd[mi] = smaddr(smw + (m_base + mi * 16 + rowl) * H2_WS) + kcb;
    }
    uint32_t bLd[2];
    {
        int rowl = (lane & 7) + ((lane >> 4) * 8);
        uint32_t kcb = ((lane >> 3) & 1) * 16;
        #pragma unroll
        for (int p = 0; p < 2; p++)
            bLd[p] = smaddr(smw + H2_TILEW + (n_base + p * 16 + rowl) * H2_WS) + kcb;
    }

    float acc[4][4][4];
    #pragma unroll
    for (int mi = 0; mi < 4; mi++)
        #pragma unroll
        for (int ni = 0; ni < 4; ni++)
            #pragma unroll
            for (int r = 0; r < 4; r++) acc[mi][ni][r] = 0.f;

    const int nslab = K >> 6;
    load_slab(0, 0);
    if (nslab > 1) load_slab(1, 1); else cp_commit();

    int st = 0;
    for (int s = 0; s < nslab; s++) {
        cp_wait1();
        __syncthreads();
        if (s + 2 < nslab) load_slab(s + 2, (st + 2) % 3);
        else cp_commit();

        const uint32_t so = st * (2 * H2_TILEW * 4);

        #pragma unroll
        for (int kw = 0; kw < 32; kw += 8) {
            uint32_t afr[4][4], bfr[2][4];
            #pragma unroll
            for (int mi = 0; mi < 4; mi++) ldsm4(afr[mi], aLd[mi] + so + kw * 4);
            #pragma unroll
            for (int p = 0; p < 2; p++)    ldsm4(bfr[p], bLd[p] + so + kw * 4);
            #pragma unroll
            for (int mi = 0; mi < 4; mi++)
                #pragma unroll
                for (int ni = 0; ni < 4; ni++) {
                    uint32_t bq[2] = { bfr[ni >> 1][(ni & 1) * 2],
                                       bfr[ni >> 1][(ni & 1) * 2 + 1] };
                    mma_f16(acc[mi][ni], afr[mi], bq);
                }
        }
        st = (st + 1) % 3;
    }

    const float* bias = job.bias;
    #pragma unroll
    for (int mi = 0; mi < 4; mi++) {
        int row0 = bm + m_base + mi * 16 + g;
        #pragma unroll
        for (int ni = 0; ni < 4; ni++) {
            int col = bn + n_base + ni * 8 + tg * 2;
            float b0 = bias[col], b1 = bias[col + 1];
            float v0 = acc[mi][ni][0] + b0;
            float v1 = acc[mi][ni][1] + b1;
            float v2 = acc[mi][ni][2] + b0;
            float v3 = acc[mi][ni][3] + b1;
            if (postop == 0) {
                float* C = (float*)job.C;
                *(float2*)&C[(long)row0 * N + col]       = make_float2(v0, v1);
                *(float2*)&C[(long)(row0 + 8) * N + col] = make_float2(v2, v3);
            } else {
                if (postop == 1) {
                    v0 = fmaxf(v0, 0.f); v1 = fmaxf(v1, 0.f);
                    v2 = fmaxf(v2, 0.f); v3 = fmaxf(v3, 0.f);
                } else if (postop == 3) {
                    v0 *= 0.125f; v1 *= 0.125f; v2 *= 0.125f; v3 *= 0.125f;
                }
                __half* C = (__half*)job.C;
                *(__half2*)&C[(long)row0 * N + col]       = __floats2half2_rn(v0, v1);
                *(__half2*)&C[(long)(row0 + 8) * N + col] = __floats2half2_rn(v2, v3);
            }
        }
    }
}

// ======================= fp16 fused flash attention =======================
// Q pre-scaled by 1/8. exp via ex2.approx.f16x2; row sums via ones-column MMA.
#define FLH_SMEM (18432*4)
#define LOG2E 1.4426950408889634f

template<bool CAUSAL>
__global__ __launch_bounds__(256, 2) void flash_h(
    const __half* __restrict__ Qp, const __half* __restrict__ Kp,
    const __half* __restrict__ Vp, __half* __restrict__ Op,
    float2* __restrict__ stats)
{
    extern __shared__ uint32_t smw[];
    const int tid = threadIdx.x;
    const int lane = tid & 31, w = tid >> 5;
    const int g = lane >> 2, tg = lane & 3;
    const int bh = blockIdx.y;
    const int it = CAUSAL ? ((int)gridDim.x - 1 - (int)blockIdx.x) : (int)blockIdx.x;
    const int t0 = it * 128;
    const int nIter = CAUSAL ? 2 * it + 2 : 16;

    const __half* Qg = Qp + (long)t0 * 4096 + bh * 64;
    const __half* Kg = Kp + bh * 64;
    const __half* Vg = Vp + bh * 64;

    auto loadKV = [&](int j, int buf) {
        const long s0 = (long)j * 64;
        const uint32_t kb = smaddr(smw + 4608 + buf * 2304);
        const uint32_t vb = smaddr(smw + 9216 + buf * 2304);
        #pragma unroll
        for (int i = 0; i < 2; i++) {
            int idx = tid + i * 256;
            int row = idx >> 3, c = idx & 7;
            cp16(kb + row * 144 + c * 16, Kg + (s0 + row) * 4096 + c * 8);
            cp16(vb + row * 144 + c * 16, Vg + (s0 + row) * 4096 + c * 8);
        }
    };

    #pragma unroll
    for (int i = 0; i < 4; i++) {
        int idx = tid + i * 256;
        int row = idx >> 3, c = idx & 7;
        cp16(smaddr(smw) + row * 144 + c * 16, Qg + (long)row * 4096 + c * 8);
    }
    loadKV(0, 0);
    cp_commit();
    cp_wait0();
    __syncthreads();

    uint32_t qf[4][4];
    {
        uint32_t qbase = smaddr(smw) + (16 * w + (lane & 15)) * 144 + (lane >> 4) * 16;
        #pragma unroll
        for (int kk = 0; kk < 4; kk++) ldsm4(qf[kk], qbase + kk * 32);
    }
    uint32_t kbl[4];
    {
        int rowl = (lane & 7) + ((lane >> 4) * 8);
        uint32_t kcb = ((lane >> 3) & 1) * 16;
        #pragma unroll
        for (int p = 0; p < 4; p++)
            kbl[p] = smaddr(smw + 4608) + (p * 16 + rowl) * 144 + kcb;
    }
    uint32_t vbl[4];
    {
        int rowv = (lane & 7) + (((lane >> 3) & 1) * 8);
        uint32_t kcv = (lane >> 4) * 16;
        #pragma unroll
        for (int p = 0; p < 4; p++)
            vbl[p] = smaddr(smw + 9216) + rowv * 144 + kcv + p * 32;
    }
    uint32_t pbase = smaddr(smw + 13824) + (16 * w + (lane & 15)) * 144 + (lane >> 4) * 16;
    __half* Pw = (__half*)(smw + 13824) + (16 * w + g) * 72;

    float acc_o[8][4];
    #pragma unroll
    for (int ni = 0; ni < 8; ni++)
        #pragma unroll
        for (int r = 0; r < 4; r++) acc_o[ni][r] = 0.f;
    float acc_l[4] = {0.f, 0.f, 0.f, 0.f};
    float m0 = -1e30f, m1 = -1e30f;

    const uint32_t ONE2 = 0x3C003C00u;
    uint32_t ones_bq[2] = {ONE2, ONE2};

    for (int j = 0; j < nIter; j++) {
        const int buf = j & 1;
        const uint32_t bofs = buf * 9216;
        if (j + 1 < nIter) { loadKV(j + 1, buf ^ 1); cp_commit(); }

        float s_acc[8][4];
        #pragma unroll
        for (int ni = 0; ni < 8; ni++)
            #pragma unroll
            for (int r = 0; r < 4; r++) s_acc[ni][r] = 0.f;
        #pragma unroll
        for (int kk = 0; kk < 4; kk++) {
            uint32_t kfr[4][4];
            #pragma unroll
            for (int p = 0; p < 4; p++) ldsm4(kfr[p], kbl[p] + bofs + kk * 32);
            #pragma unroll
            for (int ni = 0; ni < 8; ni++) {
                uint32_t bq[2] = { kfr[ni >> 1][(ni & 1) * 2],
                                   kfr[ni >> 1][(ni & 1) * 2 + 1] };
                mma_f16(s_acc[ni], qf[kk], bq);
            }
        }

        const int s0 = j * 64;
        const bool need = CAUSAL && (s0 + 63 > t0 + 16 * w);
        const int tr0 = t0 + 16 * w + g, tr1 = tr0 + 8;
        float mx0 = -1e30f, mx1 = -1e30f;
        #pragma unroll
        for (int ni = 0; ni < 8; ni++) {
            float v0 = s_acc[ni][0];
            float v1 = s_acc[ni][1];
            float v2 = s_acc[ni][2];
            float v3 = s_acc[ni][3];
            if (need) {
                int c0 = s0 + ni * 8 + 2 * tg, c1 = c0 + 1;
                if (c0 > tr0) v0 -= 1e9f;
                if (c1 > tr0) v1 -= 1e9f;
                if (c0 > tr1) v2 -= 1e9f;
                if (c1 > tr1) v3 -= 1e9f;
                s_acc[ni][0] = v0; s_acc[ni][1] = v1;
                s_acc[ni][2] = v2; s_acc[ni][3] = v3;
            }
            mx0 = fmaxf(mx0, fmaxf(v0, v1));
            mx1 = fmaxf(mx1, fmaxf(v2, v3));
        }
        mx0 = fmaxf(mx0, __shfl_xor_sync(0xffffffffu, mx0, 1));
        mx0 = fmaxf(mx0, __shfl_xor_sync(0xffffffffu, mx0, 2));
        mx1 = fmaxf(mx1, __shfl_xor_sync(0xffffffffu, mx1, 1));
        mx1 = fmaxf(mx1, __shfl_xor_sync(0xffffffffu, mx1, 2));
        const float mn0 = fmaxf(m0, mx0), mn1 = fmaxf(m1, mx1);
        const float sc0 = __expf(m0 - mn0), sc1 = __expf(m1 - mn1);
        m0 = mn0; m1 = mn1;
        const float nm0 = m0 * LOG2E, nm1 = m1 * LOG2E;

        #pragma unroll
        for (int ni = 0; ni < 8; ni++) {
            float t0v = fmaf(s_acc[ni][0], LOG2E, -nm0);
            float t1v = fmaf(s_acc[ni][1], LOG2E, -nm0);
            float t2v = fmaf(s_acc[ni][2], LOG2E, -nm1);
            float t3v = fmaf(s_acc[ni][3], LOG2E, -nm1);
            *(uint32_t*)&Pw[ni * 8 + 2 * tg]          = hex2(packh2(t0v, t1v));
            *(uint32_t*)&Pw[8 * 72 + ni * 8 + 2 * tg] = hex2(packh2(t2v, t3v));
        }
        #pragma unroll
        for (int ni = 0; ni < 8; ni++) {
            acc_o[ni][0] *= sc0; acc_o[ni][1] *= sc0;
            acc_o[ni][2] *= sc1; acc_o[ni][3] *= sc1;
        }
        acc_l[0] *= sc0; acc_l[1] *= sc0;
        acc_l[2] *= sc1; acc_l[3] *= sc1;
        __syncwarp();

        #pragma unroll
        for (int kk = 0; kk < 4; kk++) {
            uint32_t pf[4];
            ldsm4(pf, pbase + kk * 32);
            mma_f16(acc_l, pf, ones_bq);
            uint32_t vfr[4][4];
            #pragma unroll
            for (int p = 0; p < 4; p++) ldsm4t(vfr[p], vbl[p] + bofs + kk * 2304);
            #pragma unroll
            for (int ni = 0; ni < 8; ni++) {
                uint32_t bq[2] = { vfr[ni >> 1][(ni & 1) * 2],
                                   vfr[ni >> 1][(ni & 1) * 2 + 1] };
                mma_f16(acc_o[ni], pf, bq);
            }
        }
        if (j + 1 < nIter) cp_wait0();
        __syncthreads();
    }

    const float l0 = acc_l[0], l1 = acc_l[2];
    const float inv0 = 1.f / l0, inv1 = 1.f / l1;
    const int r0 = t0 + 16 * w + g;
    __half* o0 = Op + (long)r0 * 4096 + bh * 64;
    __half* o1 = o0 + 8L * 4096;
    #pragma unroll
    for (int ni = 0; ni < 8; ni++) {
        *(__half2*)&o0[ni * 8 + 2 * tg] =
            __floats2half2_rn(acc_o[ni][0] * inv0, acc_o[ni][1] * inv0);
        *(__half2*)&o1[ni * 8 + 2 * tg] =
            __floats2half2_rn(acc_o[ni][2] * inv1, acc_o[ni][3] * inv1);
    }
    if (!CAUSAL && tg == 0) {
        stats[bh * Tn + r0]     = make_float2(m0, l0);
        stats[bh * Tn + r0 + 8] = make_float2(m1, l1);
    }
}

// ======================= wgemm: EA normalized attention weights ============
#define WG_SMEM (9216*4)

__global__ __launch_bounds__(256, 2) void wgemm(
    const __half* __restrict__ Qh, const __half* __restrict__ Kh,
    const float2* __restrict__ stats, float* __restrict__ C)
{
    extern __shared__ uint32_t smw[];
    const int tid  = threadIdx.x;
    const int lane = tid & 31;
    const int wid  = tid >> 5;
    const int wm = wid & 1, wn = wid >> 1;
    const int m_base = wm * 64, n_base = wn * 32;
    const int g  = lane >> 2;
    const int tg = lane & 3;
    const int z  = blockIdx.z;
    const int bm = blockIdx.y * 128;
    const int bn = blockIdx.x * 128;

    const __half* A = Qh + (long)z * 64 + (long)bm * 4096;
    const __half* B = Kh + (long)z * 64 + (long)bn * 4096;

    #pragma unroll
    for (int i = 0; i < 4; i++) {
        int idx = tid + i * 256;
        int row = idx >> 3, c = idx & 7;
        cp16(smaddr(smw) + row * 144 + c * 16, A + (long)row * 4096 + c * 8);
        cp16(smaddr(smw + 4608) + row * 144 + c * 16, B + (long)row * 4096 + c * 8);
    }
    cp_commit();
    cp_wait0();
    __syncthreads();

    uint32_t aLd[4], bLd[2];
    {
        int rowl = lane & 15;
        uint32_t kcb = (lane >> 4) * 16;
        #pragma unroll
        for (int mi = 0; mi < 4; mi++)
            aLd[mi] = smaddr(smw) + (m_base + mi * 16 + rowl) * 144 + kcb;
    }
    {
        int rowl = (lane & 7) + ((lane >> 4) * 8);
        uint32_t kcb = ((lane >> 3) & 1) * 16;
        #pragma unroll
        for (int p = 0; p < 2; p++)
            bLd[p] = smaddr(smw + 4608) + (n_base + p * 16 + rowl) * 144 + kcb;
    }

    float acc[4][4][4];
    #pragma unroll
    for (int mi = 0; mi < 4; mi++)
        #pragma unroll
        for (int ni = 0; ni < 4; ni++)
            #pragma unroll
            for (int r = 0; r < 4; r++) acc[mi][ni][r] = 0.f;

    #pragma unroll
    for (int kk = 0; kk < 4; kk++) {
        uint32_t afr[4][4], bfr[2][4];
        #pragma unroll
        for (int mi = 0; mi < 4; mi++) ldsm4(afr[mi], aLd[mi] + kk * 32);
        #pragma unroll
        for (int p = 0; p < 2; p++)    ldsm4(bfr[p], bLd[p] + kk * 32);
        #pragma unroll
        for (int mi = 0; mi < 4; mi++)
            #pragma unroll
            for (int ni = 0; ni < 4; ni++) {
                uint32_t bq[2] = { bfr[ni >> 1][(ni & 1) * 2],
                                   bfr[ni >> 1][(ni & 1) * 2 + 1] };
                mma_f16(acc[mi][ni], afr[mi], bq);
            }
    }

    #pragma unroll
    for (int mi = 0; mi < 4; mi++) {
        int row0 = bm + m_base + mi * 16 + g;
        float2 ml0 = stats[z * Tn + row0];
        float2 ml1 = stats[z * Tn + row0 + 8];
        float i0 = 1.f / ml0.y, i1 = 1.f / ml1.y;
        #pragma unroll
        for (int ni = 0; ni < 4; ni++) {
            int col = bn + n_base + ni * 8 + tg * 2;
            float v0 = __expf(acc[mi][ni][0] - ml0.x) * i0;
            float v1 = __expf(acc[mi][ni][1] - ml0.x) * i0;
            float v2 = __expf(acc[mi][ni][2] - ml1.x) * i1;
            float v3 = __expf(acc[mi][ni][3] - ml1.x) * i1;
            float* Cz = C + (long)z * Tn * Sn;
            *(float2*)&Cz[(long)row0 * Sn + col]       = make_float2(v0, v1);
            *(float2*)&Cz[(long)(row0 + 8) * Sn + col] = make_float2(v2, v3);
        }
    }
}

// ======================= out = LayerNorm(x+res)*g+b ; optional half copy
__global__ __launch_bounds__(256) void add_ln_kernel(
    const float* __restrict__ x, const float* __restrict__ res,
    const float* __restrict__ g, const float* __restrict__ b,
    float* __restrict__ out, __half* __restrict__ out_r)
{
    const long row = (long)blockIdx.x * En;
    const int tid = threadIdx.x;
    float v[4]; float s = 0.f, s2 = 0.f;
    #pragma unroll
    for (int j = 0; j < 4; j++) {
        int i = tid + j * 256;
        float val = x[row + i] + res[row + i];
        v[j] = val; s += val; s2 += val * val;
    }
    __shared__ float sh1[8], sh2[8];
    #pragma unroll
    for (int o = 16; o; o >>= 1) {
        s  += __shfl_xor_sync(0xffffffffu, s, o);
        s2 += __shfl_xor_sync(0xffffffffu, s2, o);
    }
    if ((tid & 31) == 0) { sh1[tid >> 5] = s; sh2[tid >> 5] = s2; }
    __syncthreads();
    float ts = 0.f, ts2 = 0.f;
    #pragma unroll
    for (int w = 0; w < 8; w++) { ts += sh1[w]; ts2 += sh2[w]; }
    const float mu  = ts * (1.f / En);
    const float var = ts2 * (1.f / En) - mu * mu;
    const float inv = rsqrtf(var + 1e-5f);
    #pragma unroll
    for (int j = 0; j < 4; j++) {
        int i = tid + j * 256;
        float o = (v[j] - mu) * inv * g[i] + b[i];
        out[row + i] = o;
        if (out_r) out_r[row + i] = __float2half_rn(o);
    }
}

// ======================= fused fp16 conversion pass =======================
#define NCVT 12
struct CvtJobs {
    const float4* src[NCVT];
    uint2* dst[NCVT];
    int cum[NCVT + 1];
};
__global__ __launch_bounds__(256) void cvt_multi(CvtJobs cj, int total4)
{
    for (int i = blockIdx.x * 256 + threadIdx.x; i < total4; i += gridDim.x * 256) {
        int job = 0;
        #pragma unroll
        for (int t = 0; t < NCVT - 1; t++) if (i >= cj.cum[t + 1]) job = t + 1;
        int off = i - cj.cum[job];
        float4 v = cj.src[job][off];
        __half2 h0 = __floats2half2_rn(v.x, v.y);
        __half2 h1 = __floats2half2_rn(v.z, v.w);
        uint2 u;
        u.x = *(uint32_t*)&h0;
        u.y = *(uint32_t*)&h1;
        cj.dst[job][off] = u;
    }
}

// ======================= host-side =======================
static cudaStream_t s2;
static cudaEvent_t ev0, ev_kv, ev_fe, ev_wg;

static inline void gh_s(JobsH jobs, int M, int N, int K, int njobs, cudaStream_t st)
{
    dim3 grid(N / 128, M / 128, njobs);
    hgemm2<<<grid, 256, H2_SMEM, st>>>(jobs, K, N);
}
static void run_cvt(const float** srcs, __half** dsts, const int* n4s, int njobs,
                    int grid, cudaStream_t st)
{
    CvtJobs cj;
    int c = 0;
    for (int i = 0; i < njobs; i++) {
        cj.src[i] = (const float4*)srcs[i];
        cj.dst[i] = (uint2*)dsts[i];
        cj.cum[i] = c;
        c += n4s[i];
    }
    for (int i = njobs; i <= NCVT; i++) cj.cum[i] = c;
    for (int i = njobs; i < NCVT; i++) { cj.src[i] = nullptr; cj.dst[i] = nullptr; }
    cvt_multi<<<grid, 256, 0, st>>>(cj, c);
}

extern "C" void kernel_launch(void* const* d_in, const int* in_sizes, int n_in,
                              void* d_out, int out_size)
{
    static bool attr_done = false;
    if (!attr_done) {
        cudaFuncSetAttribute((const void*)hgemm2,
                             cudaFuncAttributeMaxDynamicSharedMemorySize, H2_SMEM);
        cudaFuncSetAttribute((const void*)flash_h<true>,
                             cudaFuncAttributeMaxDynamicSharedMemorySize, FLH_SMEM);
        cudaFuncSetAttribute((const void*)flash_h<false>,
                             cudaFuncAttributeMaxDynamicSharedMemorySize, FLH_SMEM);
        cudaFuncSetAttribute((const void*)wgemm,
                             cudaFuncAttributeMaxDynamicSharedMemorySize, WG_SMEM);
        cudaStreamCreateWithFlags(&s2, cudaStreamNonBlocking);
        cudaEventCreateWithFlags(&ev0,   cudaEventDisableTiming);
        cudaEventCreateWithFlags(&ev_kv, cudaEventDisableTiming);
        cudaEventCreateWithFlags(&ev_fe, cudaEventDisableTiming);
        cudaEventCreateWithFlags(&ev_wg, cudaEventDisableTiming);
        attr_done = true;
    }

    const float* state = (const float*)d_in[0];
    const float* enc   = (const float*)d_in[1];
    const float* sa_wq = (const float*)d_in[3];  const float* sa_bq = (const float*)d_in[4];
    const float* sa_wk = (const float*)d_in[5];  const float* sa_bk = (const float*)d_in[6];
    const float* sa_wv = (const float*)d_in[7];  const float* sa_bv = (const float*)d_in[8];
    const float* sa_wo = (const float*)d_in[9];  const float* sa_bo = (const float*)d_in[10];
    const float* ea_wq = (const float*)d_in[11]; const float* ea_bq = (const float*)d_in[12];
    const float* ea_wk = (const float*)d_in[13]; const float* ea_bk = (const float*)d_in[14];
    const float* ea_wv = (const float*)d_in[15]; const float* ea_bv = (const float*)d_in[16];
    const float* ea_wo = (const float*)d_in[17]; const float* ea_bo = (const float*)d_in[18];
    const float* fc1_w = (const float*)d_in[19]; const float* fc1_b = (const float*)d_in[20];
    const float* fc2_w = (const float*)d_in[21]; const float* fc2_b = (const float*)d_in[22];
    const float* ln1_g = (const float*)d_in[23]; const float* ln1_b = (const float*)d_in[24];
    const float* ln2_g = (const float*)d_in[25]; const float* ln2_b = (const float*)d_in[26];
    const float* ln3_g = (const float*)d_in[27]; const float* ln3_b = (const float*)d_in[28];

    float *xq_f, *xk_f, *xv_f, *tmp, *st1, *st2, *rw;
    float *attn_f, *st1r_f, *st2r_f, *ffn_f;
    float2* stats;
    cudaGetSymbolAddress((void**)&xq_f,   g_xq);
    cudaGetSymbolAddress((void**)&xk_f,   g_xk);
    cudaGetSymbolAddress((void**)&xv_f,   g_xv);
    cudaGetSymbolAddress((void**)&attn_f, g_attn);
    cudaGetSymbolAddress((void**)&tmp,    g_tmp);
    cudaGetSymbolAddress((void**)&st1,    g_state1);
    cudaGetSymbolAddress((void**)&st2,    g_state2);
    cudaGetSymbolAddress((void**)&st1r_f, g_st1r);
    cudaGetSymbolAddress((void**)&st2r_f, g_st2r);
    cudaGetSymbolAddress((void**)&ffn_f,  g_ffn);
    cudaGetSymbolAddress((void**)&stats,  g_stats);
    cudaGetSymbolAddress((void**)&rw,     g_rw);

    __half* xq_h   = (__half*)xq_f;
    __half* xk_h   = (__half*)xk_f;
    __half* xv_h   = (__half*)xv_f;
    __half* attn_h = (__half*)attn_f;
    __half* st1r_h = (__half*)st1r_f;
    __half* st2r_h = (__half*)st2r_f;
    __half* ffn_h  = (__half*)ffn_f;
    __half* hp = (__half*)rw;
    __half* h_state = hp + 0L  * MEG;
    __half* h_enc   = hp + 4L  * MEG;
    __half* h_saq   = hp + 8L  * MEG;
    __half* h_sak   = hp + 9L  * MEG;
    __half* h_sav   = hp + 10L * MEG;
    __half* h_sao   = hp + 11L * MEG;
    __half* h_eaq   = hp + 12L * MEG;
    __half* h_eak   = hp + 13L * MEG;
    __half* h_eav   = hp + 14L * MEG;
    __half* h_eao   = hp + 15L * MEG;
    __half* h_fc1   = hp + 16L * MEG;
    __half* h_fc2   = hp + 20L * MEG;
    __half* eak_x   = hp + 24L * MEG;
    __half* eav_x   = hp + 32L * MEG;

    float* out_state = (float*)d_out;
    float* out_attn  = (float*)d_out + (long)Tn * Bn * En;

    // -------- fork point: record on capturing stream, then branch --------
    cudaEventRecord(ev0, 0);
    cudaStreamWaitEvent(s2, ev0, 0);

    // side stream: enc/EA-KV cvt + EA K/V projections (parallel with SA block)
    {
        const float* srcs[3] = {enc, ea_wk, ea_wv};
        __half* dsts[3] = {h_enc, h_eak, h_eav};
        const int n4s[3] = {MEG, MEG/4, MEG/4};
        run_cvt(srcs, dsts, n4s, 3, 512, s2);
    }
    {
        JobsH j = {{{h_enc, h_eak, ea_bk, eak_x, 2},
                    {h_enc, h_eav, ea_bv, eav_x, 2}, {}}};
        gh_s(j, ROWS, En, En, 2, s2);
    }
    cudaEventRecord(ev_kv, s2);

    // main cvt (everything the main chain needs)
    {
        const float* srcs[9] = {state, sa_wq, sa_wk, sa_wv, sa_wo,
                                ea_wq, ea_wo, fc1_w, fc2_w};
        __half* dsts[9] = {h_state, h_saq, h_sak, h_sav, h_sao,
                           h_eaq, h_eao, h_fc1, h_fc2};
        const int n4s[9] = {MEG, MEG/4, MEG/4, MEG/4, MEG/4,
                            MEG/4, MEG/4, MEG, MEG};
        run_cvt(srcs, dsts, n4s, 9, 1024, 0);
    }

    // ---------------- self-attention (fused flash, causal) ----------------
    {
        JobsH j = {{{h_state, h_saq, sa_bq, xq_h, 3},     // Q pre-scaled by 1/8
                    {h_state, h_sak, sa_bk, xk_h, 2},
                    {h_state, h_sav, sa_bv, xv_h, 2}}};
        gh_s(j, ROWS, En, En, 3, 0);
    }
    flash_h<true><<<dim3(Tn / 128, BH), 256, FLH_SMEM>>>(xq_h, xk_h, xv_h, attn_h, nullptr);
    {
        JobsH j = {{{attn_h, h_sao, sa_bo, tmp, 0}, {}, {}}};
        gh_s(j, ROWS, En, En, 1, 0);
    }
    add_ln_kernel<<<ROWS, 256>>>(tmp, state, ln1_g, ln1_b, st1, st1r_h);

    // ---------------- encoder-decoder attention ----------------
    {
        JobsH j = {{{st1r_h, h_eaq, ea_bq, xq_h, 3}, {}, {}}};
        gh_s(j, ROWS, En, En, 1, 0);
    }
    cudaStreamWaitEvent(0, ev_kv, 0);
    flash_h<false><<<dim3(Tn / 128, BH), 256, FLH_SMEM>>>(xq_h, eak_x, eav_x, attn_h, stats);
    cudaEventRecord(ev_fe, 0);

    // side stream: normalized attention weights into d_out, overlapping FFN
    cudaStreamWaitEvent(s2, ev_fe, 0);
    wgemm<<<dim3(Sn / 128, Tn / 128, BH), 256, WG_SMEM, s2>>>(xq_h, eak_x, stats, out_attn);
    cudaEventRecord(ev_wg, s2);

    {
        JobsH j = {{{attn_h, h_eao, ea_bo, tmp, 0}, {}, {}}};
        gh_s(j, ROWS, En, En, 1, 0);
    }
    add_ln_kernel<<<ROWS, 256>>>(tmp, st1, ln2_g, ln2_b, st2, st2r_h);

    // ---------------- FFN ----------------
    {
        JobsH j = {{{st2r_h, h_fc1, fc1_b, ffn_h, 1}, {}, {}}};
        gh_s(j, ROWS, FFn, En, 1, 0);
    }
    {
        JobsH j = {{{ffn_h, h_fc2, fc2_b, tmp, 0}, {}, {}}};
        gh_s(j, ROWS, En, FFn, 1, 0);
    }
    add_ln_kernel<<<ROWS, 256>>>(tmp, st2, ln3_g, ln3_b, out_state, nullptr);

    // join: graph end depends on wgemm
    cudaStreamWaitEvent(0, ev_wg, 0);
}